// round 7
// baseline (speedup 1.0000x reference)
#include <cuda_runtime.h>
#include <cuda_bf16.h>
#include <math.h>
#include <stdint.h>

// Problem constants
#define Bz     2
#define SEQ    2048
#define EMB    1024
#define NHEAD  16
#define HDIM   64
#define HIDDEN 4096
#define TOK    (Bz * SEQ)          // 4096 rows
#define BH     (Bz * NHEAD)        // 32 batched heads

typedef __nv_bfloat16 bf16;

// ===================== MMA primitives (non-'a' PTX, sm_80+) ============
__device__ __forceinline__ void ldm_x4(uint32_t* r, uint32_t addr) {
    asm volatile("ldmatrix.sync.aligned.m8n8.x4.shared.b16 {%0,%1,%2,%3}, [%4];"
        : "=r"(r[0]), "=r"(r[1]), "=r"(r[2]), "=r"(r[3]) : "r"(addr));
}
__device__ __forceinline__ void mma_bf16(float* c, const uint32_t* a,
                                         uint32_t b0, uint32_t b1) {
    asm volatile(
        "mma.sync.aligned.m16n8k16.row.col.f32.bf16.bf16.f32 "
        "{%0,%1,%2,%3}, {%4,%5,%6,%7}, {%8,%9}, {%0,%1,%2,%3};"
        : "+f"(c[0]), "+f"(c[1]), "+f"(c[2]), "+f"(c[3])
        : "r"(a[0]), "r"(a[1]), "r"(a[2]), "r"(a[3]), "r"(b0), "r"(b1));
}
__device__ __forceinline__ uint32_t smem_to_u32(const void* p) {
    uint32_t a;
    asm("{ .reg .u64 t; cvta.to.shared.u64 t, %1; cvt.u32.u64 %0, t; }" : "=r"(a) : "l"(p));
    return a;
}
#define SW128(off) ((off) ^ (((off) >> 3) & 0x70))

__device__ __forceinline__ uint32_t pack_bf16(float a, float b) {
    __nv_bfloat162 h;
    h.x = __float2bfloat16(a);
    h.y = __float2bfloat16(b);
    return *(uint32_t*)&h;
}

// ===================== scratch =========================================
__device__ bf16  g_wqkvT_h[3 * EMB * EMB],  g_wqkvT_l[3 * EMB * EMB];
__device__ bf16  g_wprojT_h[EMB * EMB],     g_wprojT_l[EMB * EMB];
__device__ bf16  g_wfc1T_h[HIDDEN * EMB],   g_wfc1T_l[HIDDEN * EMB];
__device__ bf16  g_wfc2T_h[EMB * HIDDEN],   g_wfc2T_l[EMB * HIDDEN];
__device__ bf16  g_ln1_h[TOK * EMB],        g_ln1_l[TOK * EMB];
__device__ float g_qkv[TOK * 3 * EMB];
__device__ bf16  g_q_h[BH * SEQ * HDIM],    g_q_l[BH * SEQ * HDIM];
__device__ bf16  g_k_h[BH * SEQ * HDIM],    g_k_l[BH * SEQ * HDIM];
__device__ bf16  g_vt_h[BH * HDIM * SEQ],   g_vt_l[BH * HDIM * SEQ];
__device__ bf16  g_am_h[TOK * EMB],         g_am_l[TOK * EMB];
__device__ float g_x1[TOK * EMB];
__device__ bf16  g_ln2_h[TOK * EMB],        g_ln2_l[TOK * EMB];
__device__ bf16  g_h_h[TOK * HIDDEN],       g_h_l[TOK * HIDDEN];

__device__ __forceinline__ void bf16split(float v, bf16& hi, bf16& lo) {
    hi = __float2bfloat16(v);
    lo = __float2bfloat16(v - __bfloat162float(hi));
}
__device__ __forceinline__ float gelu_exact(float x) {
    return 0.5f * x * (1.0f + erff(x * 0.70710678118654752440f));
}

// ===================== mma.sync split-bf16 GEMM ========================
// D[M,N] = alpha * (A @ B^T)  A[M,K], B[N,K] as hi/lo bf16 (3-term product).
#define EPI_ALPHA      0
#define EPI_BIAS       1
#define EPI_BIAS_RES   2
#define EPI_SPLIT      3
#define EPI_GELU_SPLIT 4

template<int BN, int WM, int WN, int EPI>
__global__ __launch_bounds__(256, 1)
void gemm_mma(const bf16* __restrict__ Ahi, const bf16* __restrict__ Alo,
              const bf16* __restrict__ Bhi, const bf16* __restrict__ Blo,
              const float* __restrict__ bias, const float* __restrict__ resid,
              float* __restrict__ C, bf16* __restrict__ Chi, bf16* __restrict__ Clo,
              int M, int N, int K, int ldc,
              long long sA, long long sB,
              int hdiv, long long sCb, long long sCh,
              float alpha)
{
    constexpr int BK = 64;                       // bf16 per row = 128 bytes
    constexpr int OFF_AL = 128 * 128;
    constexpr int OFF_BH = 2 * 128 * 128;
    constexpr int OFF_BL = OFF_BH + BN * 128;
    constexpr int WGC = BN / WN;                 // warp grid cols
    constexpr int MT  = WM / 16;                 // m16 tiles per warp
    constexpr int NT  = WN / 8;                  // n8 tiles per warp
    constexpr int NG  = WN / 16;                 // n16 ldmatrix groups

    extern __shared__ char sm[];
    const uint32_t smb = smem_to_u32(sm);
    const int tid = threadIdx.x, wid = tid >> 5, lane = tid & 31;
    const int bm = blockIdx.y * 128, bn = blockIdx.x * BN, z = blockIdx.z;
    const int wm0 = (wid / WGC) * WM, wn0 = (wid % WGC) * WN;

    Ahi += (long long)z * sA;  Alo += (long long)z * sA;
    Bhi += (long long)z * sB;  Blo += (long long)z * sB;
    const long long coff = (long long)(z / hdiv) * sCb + (long long)(z % hdiv) * sCh;

    float acc[MT][NT][4];
#pragma unroll
    for (int i = 0; i < MT; i++)
#pragma unroll
        for (int j = 0; j < NT; j++)
#pragma unroll
            for (int t = 0; t < 4; t++) acc[i][j][t] = 0.0f;

    const int swz   = lane & 7;
    const int aHalf = lane >> 4;
    const int bHalf = (lane >> 3) & 1;
    int aRowOff[MT], bRowOff[NG];
#pragma unroll
    for (int mt = 0; mt < MT; mt++)
        aRowOff[mt] = (wm0 + mt * 16 + (lane & 15)) * 128;
#pragma unroll
    for (int ng = 0; ng < NG; ng++)
        bRowOff[ng] = (wn0 + ng * 16 + (lane & 7) + ((lane >> 4) << 3)) * 128;

    const int nch = K / BK;
    for (int c = 0; c < nch; c++) {
        const long long k0 = (long long)c * BK;
        {
            const bf16* a0 = Ahi + (long long)bm * K + k0;
            const bf16* a1 = Alo + (long long)bm * K + k0;
#pragma unroll
            for (int i = tid; i < 128 * 8; i += 256) {
                int r = i >> 3, u = i & 7;
                int sw = SW128(r * 128 + u * 16);
                *(int4*)(sm + sw)          = *(const int4*)(a0 + (long long)r * K + u * 8);
                *(int4*)(sm + OFF_AL + sw) = *(const int4*)(a1 + (long long)r * K + u * 8);
            }
            const bf16* b0 = Bhi + (long long)bn * K + k0;
            const bf16* b1 = Blo + (long long)bn * K + k0;
#pragma unroll
            for (int i = tid; i < BN * 8; i += 256) {
                int r = i >> 3, u = i & 7;
                int sw = SW128(r * 128 + u * 16);
                *(int4*)(sm + OFF_BH + sw) = *(const int4*)(b0 + (long long)r * K + u * 8);
                *(int4*)(sm + OFF_BL + sw) = *(const int4*)(b1 + (long long)r * K + u * 8);
            }
        }
        __syncthreads();

#pragma unroll
        for (int ks = 0; ks < BK / 16; ks++) {
            const uint32_t ca = (uint32_t)(((2 * ks + aHalf) ^ swz) * 16);
            const uint32_t cb = (uint32_t)(((2 * ks + bHalf) ^ swz) * 16);
            uint32_t ah[MT][4], al[MT][4], bhr[NG][4], blr[NG][4];
#pragma unroll
            for (int mt = 0; mt < MT; mt++) {
                ldm_x4(ah[mt], smb + aRowOff[mt] + ca);
                ldm_x4(al[mt], smb + OFF_AL + aRowOff[mt] + ca);
            }
#pragma unroll
            for (int ng = 0; ng < NG; ng++) {
                ldm_x4(bhr[ng], smb + OFF_BH + bRowOff[ng] + cb);
                ldm_x4(blr[ng], smb + OFF_BL + bRowOff[ng] + cb);
            }
#pragma unroll
            for (int mt = 0; mt < MT; mt++)
#pragma unroll
                for (int nt = 0; nt < NT; nt++)
                    mma_bf16(acc[mt][nt], ah[mt],
                             bhr[nt >> 1][(nt & 1) * 2], bhr[nt >> 1][(nt & 1) * 2 + 1]);
#pragma unroll
            for (int mt = 0; mt < MT; mt++)
#pragma unroll
                for (int nt = 0; nt < NT; nt++)
                    mma_bf16(acc[mt][nt], ah[mt],
                             blr[nt >> 1][(nt & 1) * 2], blr[nt >> 1][(nt & 1) * 2 + 1]);
#pragma unroll
            for (int mt = 0; mt < MT; mt++)
#pragma unroll
                for (int nt = 0; nt < NT; nt++)
                    mma_bf16(acc[mt][nt], al[mt],
                             bhr[nt >> 1][(nt & 1) * 2], bhr[nt >> 1][(nt & 1) * 2 + 1]);
        }
        __syncthreads();
    }

#pragma unroll
    for (int mt = 0; mt < MT; mt++) {
#pragma unroll
        for (int half = 0; half < 2; half++) {
            const long long row = bm + wm0 + mt * 16 + (lane >> 2) + half * 8;
#pragma unroll
            for (int nt = 0; nt < NT; nt++) {
                const int col = bn + wn0 + nt * 8 + (lane & 3) * 2;
                float v0 = acc[mt][nt][half * 2 + 0] * alpha;
                float v1 = acc[mt][nt][half * 2 + 1] * alpha;
                if (EPI == EPI_BIAS || EPI == EPI_BIAS_RES || EPI == EPI_GELU_SPLIT) {
                    v0 += bias[col]; v1 += bias[col + 1];
                }
                if (EPI == EPI_BIAS_RES) {
                    const float* rp = resid + coff + row * (long long)ldc + col;
                    v0 += rp[0]; v1 += rp[1];
                }
                if (EPI == EPI_GELU_SPLIT) {
                    v0 = gelu_exact(v0); v1 = gelu_exact(v1);
                }
                const long long o = coff + row * (long long)ldc + col;
                if (EPI == EPI_ALPHA || EPI == EPI_BIAS || EPI == EPI_BIAS_RES) {
                    float2 w; w.x = v0; w.y = v1;
                    *(float2*)(C + o) = w;
                } else {
                    bf16 h0, l0, h1, l1;
                    bf16split(v0, h0, l0); bf16split(v1, h1, l1);
                    __nv_bfloat162 hh; hh.x = h0; hh.y = h1;
                    __nv_bfloat162 ll; ll.x = l0; ll.y = l1;
                    *(__nv_bfloat162*)(Chi + o) = hh;
                    *(__nv_bfloat162*)(Clo + o) = ll;
                }
            }
        }
    }
}

// ===================== Flash attention (fused QK^T/softmax/PV) =========
// Grid: (SEQ/128, BH). Block: 256 threads (8 warps), warp w owns 16 Q rows.
// Q,K: [BH, SEQ, 64] hi/lo (Q pre-scaled by 0.125). Vt: [BH, 64, SEQ] hi/lo.
// Out: merged heads, bf16 hi/lo at [tok, EMB], cols h*64..h*64+63.
__global__ __launch_bounds__(256, 1)
void flash_kernel(const bf16* __restrict__ Qh, const bf16* __restrict__ Ql,
                  const bf16* __restrict__ Kh, const bf16* __restrict__ Kl,
                  const bf16* __restrict__ Vh, const bf16* __restrict__ Vl,
                  bf16* __restrict__ Oh, bf16* __restrict__ Ol)
{
    // smem: QH 0, QL 16K, KH 32K, KL 48K, VH 64K (2 halves x 8K), VL 80K
    constexpr int OFF_QL = 16384, OFF_KH = 32768, OFF_KL = 49152;
    constexpr int OFF_VH = 65536, OFF_VL = 81920;
    extern __shared__ char sm[];
    const uint32_t smb = smem_to_u32(sm);
    const int tid = threadIdx.x, wid = tid >> 5, lane = tid & 31;
    const int bh = blockIdx.y;
    const int q0 = blockIdx.x * 128;
    const long long qkbase = (long long)bh * SEQ * HDIM;
    const long long vbase  = (long long)bh * HDIM * SEQ;
    const int swz = lane & 7;

    // ---- stage Q tile (128 x 64 hi/lo) ----
#pragma unroll
    for (int i = tid; i < 128 * 8; i += 256) {
        int r = i >> 3, u = i & 7;
        int sw = SW128(r * 128 + u * 16);
        *(int4*)(sm + sw)          = *(const int4*)(Qh + qkbase + (long long)(q0 + r) * HDIM + u * 8);
        *(int4*)(sm + OFF_QL + sw) = *(const int4*)(Ql + qkbase + (long long)(q0 + r) * HDIM + u * 8);
    }
    __syncthreads();

    // ---- persistent Q fragments (4 k-steps over HDIM=64) ----
    uint32_t qfh[4][4], qfl[4][4];
    {
        const int aRowOff = (wid * 16 + (lane & 15)) * 128;
        const int aHalf = lane >> 4;
#pragma unroll
        for (int ks = 0; ks < 4; ks++) {
            const uint32_t ca = (uint32_t)(((2 * ks + aHalf) ^ swz) * 16);
            ldm_x4(qfh[ks], smb + aRowOff + ca);
            ldm_x4(qfl[ks], smb + OFF_QL + aRowOff + ca);
        }
    }

    float Oacc[8][4];
#pragma unroll
    for (int i = 0; i < 8; i++)
#pragma unroll
        for (int t = 0; t < 4; t++) Oacc[i][t] = 0.0f;
    float mrow[2] = {-1e30f, -1e30f};
    float lrow[2] = {0.0f, 0.0f};

    const int kRowOff = (lane & 7) + ((lane >> 4) << 3);
    const int bHalf = (lane >> 3) & 1;

    for (int t = 0; t < SEQ / 128; t++) {
        const int kv0 = t * 128;
        __syncthreads();   // previous iteration's frag reads done
        // stage K tile (128 x 64 hi/lo)
#pragma unroll
        for (int i = tid; i < 128 * 8; i += 256) {
            int r = i >> 3, u = i & 7;
            int sw = SW128(r * 128 + u * 16);
            *(int4*)(sm + OFF_KH + sw) = *(const int4*)(Kh + qkbase + (long long)(kv0 + r) * HDIM + u * 8);
            *(int4*)(sm + OFF_KL + sw) = *(const int4*)(Kl + qkbase + (long long)(kv0 + r) * HDIM + u * 8);
        }
        // stage V^T tile (64 x 128 hi/lo), two 64-col halves, 128B rows
#pragma unroll
        for (int i = tid; i < 64 * 16; i += 256) {
            int r = i >> 4, u = i & 15;
            int half = u >> 3, uw = u & 7;
            int sw = half * 8192 + SW128(r * 128 + uw * 16);
            *(int4*)(sm + OFF_VH + sw) = *(const int4*)(Vh + vbase + (long long)r * SEQ + kv0 + u * 8);
            *(int4*)(sm + OFF_VL + sw) = *(const int4*)(Vl + vbase + (long long)r * SEQ + kv0 + u * 8);
        }
        __syncthreads();

        // ---- S = Q K^T (3-pass split), fp32 acc ----
        float S[16][4];
#pragma unroll
        for (int j = 0; j < 16; j++)
#pragma unroll
            for (int c = 0; c < 4; c++) S[j][c] = 0.0f;
#pragma unroll
        for (int g = 0; g < 8; g++) {
            const int bRow = (g * 16 + kRowOff) * 128;
#pragma unroll
            for (int ks = 0; ks < 4; ks++) {
                const uint32_t cb = (uint32_t)(((2 * ks + bHalf) ^ swz) * 16);
                uint32_t kh4[4], kl4[4];
                ldm_x4(kh4, smb + OFF_KH + bRow + cb);
                ldm_x4(kl4, smb + OFF_KL + bRow + cb);
                mma_bf16(S[2 * g],     qfh[ks], kh4[0], kh4[1]);
                mma_bf16(S[2 * g + 1], qfh[ks], kh4[2], kh4[3]);
                mma_bf16(S[2 * g],     qfh[ks], kl4[0], kl4[1]);
                mma_bf16(S[2 * g + 1], qfh[ks], kl4[2], kl4[3]);
                mma_bf16(S[2 * g],     qfl[ks], kh4[0], kh4[1]);
                mma_bf16(S[2 * g + 1], qfl[ks], kh4[2], kh4[3]);
            }
        }

        // ---- online softmax update ----
        float mt0 = -1e30f, mt1 = -1e30f;
#pragma unroll
        for (int j = 0; j < 16; j++) {
            mt0 = fmaxf(mt0, fmaxf(S[j][0], S[j][1]));
            mt1 = fmaxf(mt1, fmaxf(S[j][2], S[j][3]));
        }
        mt0 = fmaxf(mt0, __shfl_xor_sync(0xffffffffu, mt0, 1));
        mt0 = fmaxf(mt0, __shfl_xor_sync(0xffffffffu, mt0, 2));
        mt1 = fmaxf(mt1, __shfl_xor_sync(0xffffffffu, mt1, 1));
        mt1 = fmaxf(mt1, __shfl_xor_sync(0xffffffffu, mt1, 2));
        const float mn0 = fmaxf(mrow[0], mt0), mn1 = fmaxf(mrow[1], mt1);
        const float sc0 = __expf(mrow[0] - mn0), sc1 = __expf(mrow[1] - mn1);
        float rs0 = 0.0f, rs1 = 0.0f;
#pragma unroll
        for (int j = 0; j < 16; j++) {
            S[j][0] = __expf(S[j][0] - mn0);
            S[j][1] = __expf(S[j][1] - mn0);
            S[j][2] = __expf(S[j][2] - mn1);
            S[j][3] = __expf(S[j][3] - mn1);
            rs0 += S[j][0] + S[j][1];
            rs1 += S[j][2] + S[j][3];
        }
        rs0 += __shfl_xor_sync(0xffffffffu, rs0, 1);
        rs0 += __shfl_xor_sync(0xffffffffu, rs0, 2);
        rs1 += __shfl_xor_sync(0xffffffffu, rs1, 1);
        rs1 += __shfl_xor_sync(0xffffffffu, rs1, 2);
        lrow[0] = lrow[0] * sc0 + rs0;
        lrow[1] = lrow[1] * sc1 + rs1;
        mrow[0] = mn0; mrow[1] = mn1;
#pragma unroll
        for (int i = 0; i < 8; i++) {
            Oacc[i][0] *= sc0; Oacc[i][1] *= sc0;
            Oacc[i][2] *= sc1; Oacc[i][3] *= sc1;
        }

        // ---- O += P V (3-pass split) ----
#pragma unroll
        for (int j = 0; j < 8; j++) {
            // A-fragments straight from S regs (C->A identity, no shuffles)
            float p00 = S[2*j][0],   p01 = S[2*j][1],   p02 = S[2*j][2],   p03 = S[2*j][3];
            float p10 = S[2*j+1][0], p11 = S[2*j+1][1], p12 = S[2*j+1][2], p13 = S[2*j+1][3];
            bf16 h; bf16 lo;
            float r00h, r01h, r02h, r03h, r10h, r11h, r12h, r13h;
            bf16split(p00, h, lo); r00h = __bfloat162float(h); float r00l = __bfloat162float(lo);
            bf16split(p01, h, lo); r01h = __bfloat162float(h); float r01l = __bfloat162float(lo);
            bf16split(p02, h, lo); r02h = __bfloat162float(h); float r02l = __bfloat162float(lo);
            bf16split(p03, h, lo); r03h = __bfloat162float(h); float r03l = __bfloat162float(lo);
            bf16split(p10, h, lo); r10h = __bfloat162float(h); float r10l = __bfloat162float(lo);
            bf16split(p11, h, lo); r11h = __bfloat162float(h); float r11l = __bfloat162float(lo);
            bf16split(p12, h, lo); r12h = __bfloat162float(h); float r12l = __bfloat162float(lo);
            bf16split(p13, h, lo); r13h = __bfloat162float(h); float r13l = __bfloat162float(lo);
            uint32_t ah[4], al[4];
            ah[0] = pack_bf16(r00h, r01h); ah[1] = pack_bf16(r02h, r03h);
            ah[2] = pack_bf16(r10h, r11h); ah[3] = pack_bf16(r12h, r13h);
            al[0] = pack_bf16(r00l, r01l); al[1] = pack_bf16(r02l, r03l);
            al[2] = pack_bf16(r10l, r11l); al[3] = pack_bf16(r12l, r13l);

            const int half = j >> 2;
            const uint32_t cv = (uint32_t)(((2 * (j & 3) + bHalf) ^ swz) * 16);
#pragma unroll
            for (int vg = 0; vg < 4; vg++) {
                const int vRow = half * 8192 + (vg * 16 + kRowOff) * 128;
                uint32_t vh4[4], vl4[4];
                ldm_x4(vh4, smb + OFF_VH + vRow + cv);
                ldm_x4(vl4, smb + OFF_VL + vRow + cv);
                mma_bf16(Oacc[2 * vg],     ah, vh4[0], vh4[1]);
                mma_bf16(Oacc[2 * vg + 1], ah, vh4[2], vh4[3]);
                mma_bf16(Oacc[2 * vg],     ah, vl4[0], vl4[1]);
                mma_bf16(Oacc[2 * vg + 1], ah, vl4[2], vl4[3]);
                mma_bf16(Oacc[2 * vg],     al, vh4[0], vh4[1]);
                mma_bf16(Oacc[2 * vg + 1], al, vh4[2], vh4[3]);
            }
        }
    }

    // ---- epilogue: O /= l, write merged-head bf16 hi/lo ----
    const float inv0 = 1.0f / lrow[0], inv1 = 1.0f / lrow[1];
    const int b = bh / NHEAD, h = bh % NHEAD;
    const long long tok0 = (long long)b * SEQ + q0 + wid * 16 + (lane >> 2);
    const int col0 = h * HDIM + (lane & 3) * 2;
#pragma unroll
    for (int vt = 0; vt < 8; vt++) {
        float v0 = Oacc[vt][0] * inv0, v1 = Oacc[vt][1] * inv0;
        float v2 = Oacc[vt][2] * inv1, v3 = Oacc[vt][3] * inv1;
        bf16 h0, l0, h1, l1;
        long long o = tok0 * EMB + col0 + vt * 8;
        bf16split(v0, h0, l0); bf16split(v1, h1, l1);
        { __nv_bfloat162 hh; hh.x = h0; hh.y = h1; *(__nv_bfloat162*)(Oh + o) = hh; }
        { __nv_bfloat162 ll; ll.x = l0; ll.y = l1; *(__nv_bfloat162*)(Ol + o) = ll; }
        long long o2 = (tok0 + 8) * EMB + col0 + vt * 8;
        bf16split(v2, h0, l0); bf16split(v3, h1, l1);
        { __nv_bfloat162 hh; hh.x = h0; hh.y = h1; *(__nv_bfloat162*)(Oh + o2) = hh; }
        { __nv_bfloat162 ll; ll.x = l0; ll.y = l1; *(__nv_bfloat162*)(Ol + o2) = ll; }
    }
}

// ===================== LayerNorm -> bf16 hi/lo =========================
__global__ __launch_bounds__(256)
void layernorm_split_kernel(const float* __restrict__ x, const float* __restrict__ gamma,
                            const float* __restrict__ beta,
                            bf16* __restrict__ oh, bf16* __restrict__ ol)
{
    long long row = blockIdx.x;
    const float4* xr = (const float4*)(x + row * EMB);
    float4 v = xr[threadIdx.x];
    float s  = v.x + v.y + v.z + v.w;
    float ss = v.x * v.x + v.y * v.y + v.z * v.z + v.w * v.w;
#pragma unroll
    for (int o = 16; o; o >>= 1) {
        s  += __shfl_xor_sync(0xffffffffu, s,  o);
        ss += __shfl_xor_sync(0xffffffffu, ss, o);
    }
    __shared__ float sh_s[8], sh_ss[8];
    int w = threadIdx.x >> 5, l = threadIdx.x & 31;
    if (l == 0) { sh_s[w] = s; sh_ss[w] = ss; }
    __syncthreads();
    s = 0.f; ss = 0.f;
#pragma unroll
    for (int i = 0; i < 8; i++) { s += sh_s[i]; ss += sh_ss[i]; }
    float mu   = s * (1.0f / EMB);
    float var  = ss * (1.0f / EMB) - mu * mu;
    float rstd = rsqrtf(var + 1e-6f);
    float4 gv = ((const float4*)gamma)[threadIdx.x];
    float4 bv = ((const float4*)beta)[threadIdx.x];
    float o0 = (v.x - mu) * rstd * gv.x + bv.x;
    float o1 = (v.y - mu) * rstd * gv.y + bv.y;
    float o2 = (v.z - mu) * rstd * gv.z + bv.z;
    float o3 = (v.w - mu) * rstd * gv.w + bv.w;
    bf16 h0,l0,h1,l1,h2,l2,h3,l3;
    bf16split(o0,h0,l0); bf16split(o1,h1,l1); bf16split(o2,h2,l2); bf16split(o3,h3,l3);
    long long base = row * EMB + threadIdx.x * 4;
    __nv_bfloat162 a; a.x=h0; a.y=h1; __nv_bfloat162 b; b.x=h2; b.y=h3;
    __nv_bfloat162 c; c.x=l0; c.y=l1; __nv_bfloat162 d; d.x=l2; d.y=l3;
    *(__nv_bfloat162*)(oh + base)     = a;
    *(__nv_bfloat162*)(oh + base + 2) = b;
    *(__nv_bfloat162*)(ol + base)     = c;
    *(__nv_bfloat162*)(ol + base + 2) = d;
}

// ============ transpose-convert: src fp32 [R,C] -> dst [C,R] hi/lo =====
__global__ __launch_bounds__(256)
void wt_prep_kernel(const float* __restrict__ src, int R, int C,
                    bf16* __restrict__ dh, bf16* __restrict__ dl)
{
    __shared__ float t[32][33];
    int c0 = blockIdx.x * 32, r0 = blockIdx.y * 32;
    int tx = threadIdx.x & 31, ty = threadIdx.x >> 5;
#pragma unroll
    for (int i = ty; i < 32; i += 8)
        t[i][tx] = src[(long long)(r0 + i) * C + c0 + tx];
    __syncthreads();
#pragma unroll
    for (int i = ty; i < 32; i += 8) {
        float v = t[tx][i];
        bf16 h, l; bf16split(v, h, l);
        long long o = (long long)(c0 + i) * R + r0 + tx;
        dh[o] = h; dl[o] = l;
    }
}

// ============ V^T prep: qkv -> vt hi/lo [BH, 64, 2048] =================
__global__ __launch_bounds__(256)
void vt_prep_kernel(const float* __restrict__ qkv, bf16* __restrict__ dh, bf16* __restrict__ dl)
{
    __shared__ float t[32][33];
    int bh = blockIdx.z, b = bh / NHEAD, h = bh % NHEAD;
    int n0 = blockIdx.x * 32, d0 = blockIdx.y * 32;
    int tx = threadIdx.x & 31, ty = threadIdx.x >> 5;
#pragma unroll
    for (int i = ty; i < 32; i += 8)
        t[i][tx] = qkv[((long long)(b * SEQ + n0 + i)) * (3 * EMB) + 2 * EMB + h * HDIM + d0 + tx];
    __syncthreads();
#pragma unroll
    for (int i = ty; i < 32; i += 8) {
        float v = t[tx][i];
        bf16 hh, ll; bf16split(v, hh, ll);
        long long o = ((long long)bh * HDIM + d0 + i) * SEQ + n0 + tx;
        dh[o] = hh; dl[o] = ll;
    }
}

// ============ Q/K prep: qkv -> q (x0.125), k hi/lo [BH, 2048, 64] ======
__global__ __launch_bounds__(256)
void qk_prep_kernel(const float* __restrict__ qkv,
                    bf16* __restrict__ qh, bf16* __restrict__ ql,
                    bf16* __restrict__ kh, bf16* __restrict__ kl)
{
    long long idx4 = (long long)blockIdx.x * 256 + threadIdx.x;
    long long e  = idx4 * 4;
    long long bn = e / EMB;
    int c  = (int)(e % EMB);
    long long b  = bn / SEQ, n = bn % SEQ;
    int h = c / HDIM, d = c % HDIM;
    long long src = bn * (3 * EMB) + (long long)h * HDIM + d;
    long long dst = ((b * NHEAD + h) * SEQ + n) * HDIM + d;
    float4 q4 = *(const float4*)(qkv + src);
    float4 k4 = *(const float4*)(qkv + src + EMB);
    q4.x *= 0.125f; q4.y *= 0.125f; q4.z *= 0.125f; q4.w *= 0.125f;
    bf16 h0,l0,h1,l1,h2,l2,h3,l3;
    bf16split(q4.x,h0,l0); bf16split(q4.y,h1,l1); bf16split(q4.z,h2,l2); bf16split(q4.w,h3,l3);
    { __nv_bfloat162 a; a.x=h0; a.y=h1; __nv_bfloat162 bb; bb.x=h2; bb.y=h3;
      __nv_bfloat162 cc; cc.x=l0; cc.y=l1; __nv_bfloat162 dd; dd.x=l2; dd.y=l3;
      *(__nv_bfloat162*)(qh+dst)=a; *(__nv_bfloat162*)(qh+dst+2)=bb;
      *(__nv_bfloat162*)(ql+dst)=cc; *(__nv_bfloat162*)(ql+dst+2)=dd; }
    bf16split(k4.x,h0,l0); bf16split(k4.y,h1,l1); bf16split(k4.z,h2,l2); bf16split(k4.w,h3,l3);
    { __nv_bfloat162 a; a.x=h0; a.y=h1; __nv_bfloat162 bb; bb.x=h2; bb.y=h3;
      __nv_bfloat162 cc; cc.x=l0; cc.y=l1; __nv_bfloat162 dd; dd.x=l2; dd.y=l3;
      *(__nv_bfloat162*)(kh+dst)=a; *(__nv_bfloat162*)(kh+dst+2)=bb;
      *(__nv_bfloat162*)(kl+dst)=cc; *(__nv_bfloat162*)(kl+dst+2)=dd; }
}

// ===================== host side =======================================
template<int BN, int WM, int WN, int EPI>
static void launch_gemm(const bf16* Ahi, const bf16* Alo, const bf16* Bhi, const bf16* Blo,
                        const float* bias, const float* resid,
                        float* C, bf16* Chi, bf16* Clo,
                        int M, int N, int K, int ldc,
                        long long sA, long long sB,
                        int batch, int hdiv, long long sCb, long long sCh,
                        float alpha)
{
    constexpr int SMEM_BYTES = 2 * 128 * 128 + 2 * BN * 128;
    cudaFuncSetAttribute(gemm_mma<BN, WM, WN, EPI>,
                         cudaFuncAttributeMaxDynamicSharedMemorySize, SMEM_BYTES);
    dim3 grid(N / BN, M / 128, batch);
    gemm_mma<BN, WM, WN, EPI><<<grid, 256, SMEM_BYTES>>>(
        Ahi, Alo, Bhi, Blo, bias, resid, C, Chi, Clo,
        M, N, K, ldc, sA, sB, hdiv, sCb, sCh, alpha);
}

extern "C" void kernel_launch(void* const* d_in, const int* in_sizes, int n_in,
                              void* d_out, int out_size)
{
    const float* x      = (const float*)d_in[0];
    const float* ln1_g  = (const float*)d_in[1];
    const float* ln1_b  = (const float*)d_in[2];
    const float* w_qkv  = (const float*)d_in[3];
    const float* b_qkv  = (const float*)d_in[4];
    const float* w_proj = (const float*)d_in[5];
    const float* b_proj = (const float*)d_in[6];
    const float* ln2_g  = (const float*)d_in[7];
    const float* ln2_b  = (const float*)d_in[8];
    const float* w_fc1  = (const float*)d_in[9];
    const float* b_fc1  = (const float*)d_in[10];
    const float* w_fc2  = (const float*)d_in[11];
    const float* b_fc2  = (const float*)d_in[12];
    float* out = (float*)d_out;

    bf16 *wqkvTh, *wqkvTl, *wprojTh, *wprojTl, *wfc1Th, *wfc1Tl, *wfc2Th, *wfc2Tl;
    bf16 *ln1h, *ln1l, *qh, *ql, *kh, *kl, *vth, *vtl, *amh, *aml, *ln2h, *ln2l, *hh, *hl;
    float *qkv, *x1;
    cudaGetSymbolAddress((void**)&wqkvTh, g_wqkvT_h);  cudaGetSymbolAddress((void**)&wqkvTl, g_wqkvT_l);
    cudaGetSymbolAddress((void**)&wprojTh, g_wprojT_h); cudaGetSymbolAddress((void**)&wprojTl, g_wprojT_l);
    cudaGetSymbolAddress((void**)&wfc1Th, g_wfc1T_h);  cudaGetSymbolAddress((void**)&wfc1Tl, g_wfc1T_l);
    cudaGetSymbolAddress((void**)&wfc2Th, g_wfc2T_h);  cudaGetSymbolAddress((void**)&wfc2Tl, g_wfc2T_l);
    cudaGetSymbolAddress((void**)&ln1h, g_ln1_h);      cudaGetSymbolAddress((void**)&ln1l, g_ln1_l);
    cudaGetSymbolAddress((void**)&qkv, g_qkv);
    cudaGetSymbolAddress((void**)&qh, g_q_h);          cudaGetSymbolAddress((void**)&ql, g_q_l);
    cudaGetSymbolAddress((void**)&kh, g_k_h);          cudaGetSymbolAddress((void**)&kl, g_k_l);
    cudaGetSymbolAddress((void**)&vth, g_vt_h);        cudaGetSymbolAddress((void**)&vtl, g_vt_l);
    cudaGetSymbolAddress((void**)&amh, g_am_h);        cudaGetSymbolAddress((void**)&aml, g_am_l);
    cudaGetSymbolAddress((void**)&x1, g_x1);
    cudaGetSymbolAddress((void**)&ln2h, g_ln2_h);      cudaGetSymbolAddress((void**)&ln2l, g_ln2_l);
    cudaGetSymbolAddress((void**)&hh, g_h_h);          cudaGetSymbolAddress((void**)&hl, g_h_l);

    // 0) weight transpose-converts  W[K,N] -> Wt[N,K] hi/lo
    wt_prep_kernel<<<dim3(3 * EMB / 32, EMB / 32), 256>>>(w_qkv, EMB, 3 * EMB, wqkvTh, wqkvTl);
    wt_prep_kernel<<<dim3(EMB / 32, EMB / 32), 256>>>(w_proj, EMB, EMB, wprojTh, wprojTl);
    wt_prep_kernel<<<dim3(HIDDEN / 32, EMB / 32), 256>>>(w_fc1, EMB, HIDDEN, wfc1Th, wfc1Tl);
    wt_prep_kernel<<<dim3(EMB / 32, HIDDEN / 32), 256>>>(w_fc2, HIDDEN, EMB, wfc2Th, wfc2Tl);

    // 1) LN1 -> hi/lo
    layernorm_split_kernel<<<TOK, 256>>>(x, ln1_g, ln1_b, ln1h, ln1l);

    // 2) QKV: [4096,3072] = ln1 @ w_qkv + b  (fp32 out)
    launch_gemm<128, 64, 32, EPI_BIAS>(ln1h, ln1l, wqkvTh, wqkvTl, b_qkv, nullptr,
                                       qkv, nullptr, nullptr,
                                       TOK, 3 * EMB, EMB, 3 * EMB, 0, 0, 1, 1, 0, 0, 1.0f);

    // 3) Q/K gather (+0.125 on Q) + V transpose, split to bf16
    qk_prep_kernel<<<(TOK * EMB / 4) / 256, 256>>>(qkv, qh, ql, kh, kl);
    vt_prep_kernel<<<dim3(SEQ / 32, HDIM / 32, BH), 256>>>(qkv, vth, vtl);

    // 4) fused flash attention -> merged heads bf16 hi/lo
    {
        constexpr int FSMEM = 96 * 1024;
        cudaFuncSetAttribute(flash_kernel,
                             cudaFuncAttributeMaxDynamicSharedMemorySize, FSMEM);
        dim3 grid(SEQ / 128, BH);
        flash_kernel<<<grid, 256, FSMEM>>>(qh, ql, kh, kl, vth, vtl, amh, aml);
    }

    // 5) proj + residual: x1 = attnm @ w_proj + b + x
    launch_gemm<128, 64, 32, EPI_BIAS_RES>(amh, aml, wprojTh, wprojTl, b_proj, x,
                                           x1, nullptr, nullptr,
                                           TOK, EMB, EMB, EMB, 0, 0, 1, 1, 0, 0, 1.0f);

    // 6) LN2 -> hi/lo
    layernorm_split_kernel<<<TOK, 256>>>(x1, ln2_g, ln2_b, ln2h, ln2l);

    // 7) FC1 + GELU -> h hi/lo
    launch_gemm<128, 64, 32, EPI_GELU_SPLIT>(ln2h, ln2l, wfc1Th, wfc1Tl, b_fc1, nullptr,
                                             nullptr, hh, hl,
                                             TOK, HIDDEN, EMB, HIDDEN, 0, 0, 1, 1, 0, 0, 1.0f);

    // 8) FC2 + bias + residual -> out
    launch_gemm<128, 64, 32, EPI_BIAS_RES>(hh, hl, wfc2Th, wfc2Tl, b_fc2, x1,
                                           out, nullptr, nullptr,
                                           TOK, EMB, HIDDEN, EMB, 0, 0, 1, 1, 0, 0, 1.0f);
}

// round 9
// speedup vs baseline: 1.5562x; 1.5562x over previous
#include <cuda_runtime.h>
#include <cuda_bf16.h>
#include <math.h>
#include <stdint.h>

// Problem constants
#define Bz     2
#define SEQ    2048
#define EMB    1024
#define NHEAD  16
#define HDIM   64
#define HIDDEN 4096
#define TOK    (Bz * SEQ)          // 4096 rows
#define BH     (Bz * NHEAD)        // 32 batched heads

typedef __nv_bfloat16 bf16;

// ===================== MMA / async primitives (non-'a' PTX) ============
__device__ __forceinline__ void ldm_x4(uint32_t* r, uint32_t addr) {
    asm volatile("ldmatrix.sync.aligned.m8n8.x4.shared.b16 {%0,%1,%2,%3}, [%4];"
        : "=r"(r[0]), "=r"(r[1]), "=r"(r[2]), "=r"(r[3]) : "r"(addr));
}
__device__ __forceinline__ void mma_bf16(float* c, const uint32_t* a,
                                         uint32_t b0, uint32_t b1) {
    asm volatile(
        "mma.sync.aligned.m16n8k16.row.col.f32.bf16.bf16.f32 "
        "{%0,%1,%2,%3}, {%4,%5,%6,%7}, {%8,%9}, {%0,%1,%2,%3};"
        : "+f"(c[0]), "+f"(c[1]), "+f"(c[2]), "+f"(c[3])
        : "r"(a[0]), "r"(a[1]), "r"(a[2]), "r"(a[3]), "r"(b0), "r"(b1));
}
__device__ __forceinline__ uint32_t smem_to_u32(const void* p) {
    uint32_t a;
    asm("{ .reg .u64 t; cvta.to.shared.u64 t, %1; cvt.u32.u64 %0, t; }" : "=r"(a) : "l"(p));
    return a;
}
#define SW128(off) ((off) ^ (((off) >> 3) & 0x70))

#define CP_ASYNC16(saddr, gptr) \
    asm volatile("cp.async.cg.shared.global [%0], [%1], 16;" \
        :: "r"((uint32_t)(saddr)), "l"(gptr))
#define CP_COMMIT() asm volatile("cp.async.commit_group;" ::: "memory")
#define CP_WAIT1()  asm volatile("cp.async.wait_group 1;" ::: "memory")
#define CP_WAIT0()  asm volatile("cp.async.wait_group 0;" ::: "memory")

// ===================== scratch =========================================
__device__ bf16  g_wqkvT_h[3 * EMB * EMB],  g_wqkvT_l[3 * EMB * EMB];
__device__ bf16  g_wprojT_h[EMB * EMB],     g_wprojT_l[EMB * EMB];
__device__ bf16  g_wfc1T_h[HIDDEN * EMB],   g_wfc1T_l[HIDDEN * EMB];
__device__ bf16  g_wfc2T_h[EMB * HIDDEN],   g_wfc2T_l[EMB * HIDDEN];
__device__ bf16  g_ln1_h[TOK * EMB],        g_ln1_l[TOK * EMB];
__device__ float g_qkv[TOK * 3 * EMB];
__device__ bf16  g_q_h[BH * SEQ * HDIM],    g_q_l[BH * SEQ * HDIM];
__device__ bf16  g_k_h[BH * SEQ * HDIM],    g_k_l[BH * SEQ * HDIM];
__device__ bf16  g_vt_h[BH * HDIM * SEQ],   g_vt_l[BH * HDIM * SEQ];
__device__ float g_scores[(long long)BH * SEQ * SEQ];    // 512 MB
__device__ bf16  g_p_h[(long long)BH * SEQ * SEQ];       // 256 MB
__device__ bf16  g_p_l[(long long)BH * SEQ * SEQ];       // 256 MB
__device__ bf16  g_am_h[TOK * EMB],         g_am_l[TOK * EMB];
__device__ float g_x1[TOK * EMB];
__device__ bf16  g_ln2_h[TOK * EMB],        g_ln2_l[TOK * EMB];
__device__ bf16  g_h_h[TOK * HIDDEN],       g_h_l[TOK * HIDDEN];

__device__ __forceinline__ void bf16split(float v, bf16& hi, bf16& lo) {
    hi = __float2bfloat16(v);
    lo = __float2bfloat16(v - __bfloat162float(hi));
}
__device__ __forceinline__ float gelu_exact(float x) {
    return 0.5f * x * (1.0f + erff(x * 0.70710678118654752440f));
}

// ===================== mma.sync split-bf16 GEMM (cp.async pipelined) ===
// D[M,N] = alpha * (A @ B^T)  A[M,K], B[N,K] as hi/lo bf16 (3-term product).
#define EPI_ALPHA      0
#define EPI_BIAS       1
#define EPI_BIAS_RES   2
#define EPI_SPLIT      3
#define EPI_GELU_SPLIT 4

template<int BN, int WM, int WN, int EPI>
__global__ __launch_bounds__(256, 1)
void gemm_mma(const bf16* __restrict__ Ahi, const bf16* __restrict__ Alo,
              const bf16* __restrict__ Bhi, const bf16* __restrict__ Blo,
              const float* __restrict__ bias, const float* __restrict__ resid,
              float* __restrict__ C, bf16* __restrict__ Chi, bf16* __restrict__ Clo,
              int M, int N, int K, int ldc,
              long long sA, long long sB,
              int hdiv, long long sCb, long long sCh,
              float alpha)
{
    constexpr int BK = 64;                       // bf16 per row = 128 bytes
    constexpr int OFF_AL = 128 * 128;            // within a buffer
    constexpr int OFF_BH = 2 * 128 * 128;
    constexpr int OFF_BL = OFF_BH + BN * 128;
    constexpr int BUFB   = OFF_BL + BN * 128;    // bytes per buffer
    constexpr int WGC = BN / WN;
    constexpr int MT  = WM / 16;
    constexpr int NT  = WN / 8;
    constexpr int NG  = WN / 16;

    extern __shared__ char sm[];
    const uint32_t smb = smem_to_u32(sm);
    const int tid = threadIdx.x, wid = tid >> 5, lane = tid & 31;
    const int bm = blockIdx.y * 128, bn = blockIdx.x * BN, z = blockIdx.z;
    const int wm0 = (wid / WGC) * WM, wn0 = (wid % WGC) * WN;

    Ahi += (long long)z * sA;  Alo += (long long)z * sA;
    Bhi += (long long)z * sB;  Blo += (long long)z * sB;
    const long long coff = (long long)(z / hdiv) * sCb + (long long)(z % hdiv) * sCh;

    float acc[MT][NT][4];
#pragma unroll
    for (int i = 0; i < MT; i++)
#pragma unroll
        for (int j = 0; j < NT; j++)
#pragma unroll
            for (int t = 0; t < 4; t++) acc[i][j][t] = 0.0f;

    const int swz   = lane & 7;
    const int aHalf = lane >> 4;
    const int bHalf = (lane >> 3) & 1;
    int aRowOff[MT], bRowOff[NG];
#pragma unroll
    for (int mt = 0; mt < MT; mt++)
        aRowOff[mt] = (wm0 + mt * 16 + (lane & 15)) * 128;
#pragma unroll
    for (int ng = 0; ng < NG; ng++)
        bRowOff[ng] = (wn0 + ng * 16 + (lane & 7) + ((lane >> 4) << 3)) * 128;

    // async stage of one K-chunk into buffer `base`
    auto stage = [&](int c, uint32_t base) {
        const long long k0 = (long long)c * BK;
        const bf16* a0 = Ahi + (long long)bm * K + k0;
        const bf16* a1 = Alo + (long long)bm * K + k0;
#pragma unroll
        for (int i = tid; i < 128 * 8; i += 256) {
            int r = i >> 3, u = i & 7;
            int sw = SW128(r * 128 + u * 16);
            CP_ASYNC16(smb + base + sw,          a0 + (long long)r * K + u * 8);
            CP_ASYNC16(smb + base + OFF_AL + sw, a1 + (long long)r * K + u * 8);
        }
        const bf16* b0 = Bhi + (long long)bn * K + k0;
        const bf16* b1 = Blo + (long long)bn * K + k0;
#pragma unroll
        for (int i = tid; i < BN * 8; i += 256) {
            int r = i >> 3, u = i & 7;
            int sw = SW128(r * 128 + u * 16);
            CP_ASYNC16(smb + base + OFF_BH + sw, b0 + (long long)r * K + u * 8);
            CP_ASYNC16(smb + base + OFF_BL + sw, b1 + (long long)r * K + u * 8);
        }
        CP_COMMIT();
    };

    const int nch = K / BK;
    stage(0, 0);
    for (int c = 0; c < nch; c++) {
        const uint32_t cur = (c & 1) ? BUFB : 0;
        if (c + 1 < nch) {
            stage(c + 1, (c & 1) ? 0 : BUFB);
            CP_WAIT1();
        } else {
            CP_WAIT0();
        }
        __syncthreads();

#pragma unroll
        for (int ks = 0; ks < BK / 16; ks++) {
            const uint32_t ca = (uint32_t)(((2 * ks + aHalf) ^ swz) * 16);
            const uint32_t cb = (uint32_t)(((2 * ks + bHalf) ^ swz) * 16);
            uint32_t ah[MT][4], al[MT][4], bhr[NG][4], blr[NG][4];
#pragma unroll
            for (int mt = 0; mt < MT; mt++) {
                ldm_x4(ah[mt], smb + cur + aRowOff[mt] + ca);
                ldm_x4(al[mt], smb + cur + OFF_AL + aRowOff[mt] + ca);
            }
#pragma unroll
            for (int ng = 0; ng < NG; ng++) {
                ldm_x4(bhr[ng], smb + cur + OFF_BH + bRowOff[ng] + cb);
                ldm_x4(blr[ng], smb + cur + OFF_BL + bRowOff[ng] + cb);
            }
#pragma unroll
            for (int mt = 0; mt < MT; mt++)
#pragma unroll
                for (int nt = 0; nt < NT; nt++)
                    mma_bf16(acc[mt][nt], ah[mt],
                             bhr[nt >> 1][(nt & 1) * 2], bhr[nt >> 1][(nt & 1) * 2 + 1]);
#pragma unroll
            for (int mt = 0; mt < MT; mt++)
#pragma unroll
                for (int nt = 0; nt < NT; nt++)
                    mma_bf16(acc[mt][nt], ah[mt],
                             blr[nt >> 1][(nt & 1) * 2], blr[nt >> 1][(nt & 1) * 2 + 1]);
#pragma unroll
            for (int mt = 0; mt < MT; mt++)
#pragma unroll
                for (int nt = 0; nt < NT; nt++)
                    mma_bf16(acc[mt][nt], al[mt],
                             bhr[nt >> 1][(nt & 1) * 2], bhr[nt >> 1][(nt & 1) * 2 + 1]);
        }
        __syncthreads();
    }

#pragma unroll
    for (int mt = 0; mt < MT; mt++) {
#pragma unroll
        for (int half = 0; half < 2; half++) {
            const long long row = bm + wm0 + mt * 16 + (lane >> 2) + half * 8;
#pragma unroll
            for (int nt = 0; nt < NT; nt++) {
                const int col = bn + wn0 + nt * 8 + (lane & 3) * 2;
                float v0 = acc[mt][nt][half * 2 + 0] * alpha;
                float v1 = acc[mt][nt][half * 2 + 1] * alpha;
                if (EPI == EPI_BIAS || EPI == EPI_BIAS_RES || EPI == EPI_GELU_SPLIT) {
                    v0 += bias[col]; v1 += bias[col + 1];
                }
                if (EPI == EPI_BIAS_RES) {
                    const float* rp = resid + coff + row * (long long)ldc + col;
                    v0 += rp[0]; v1 += rp[1];
                }
                if (EPI == EPI_GELU_SPLIT) {
                    v0 = gelu_exact(v0); v1 = gelu_exact(v1);
                }
                const long long o = coff + row * (long long)ldc + col;
                if (EPI == EPI_ALPHA || EPI == EPI_BIAS || EPI == EPI_BIAS_RES) {
                    float2 w; w.x = v0; w.y = v1;
                    *(float2*)(C + o) = w;
                } else {
                    bf16 h0, l0, h1, l1;
                    bf16split(v0, h0, l0); bf16split(v1, h1, l1);
                    __nv_bfloat162 hh; hh.x = h0; hh.y = h1;
                    __nv_bfloat162 ll; ll.x = l0; ll.y = l1;
                    *(__nv_bfloat162*)(Chi + o) = hh;
                    *(__nv_bfloat162*)(Clo + o) = ll;
                }
            }
        }
    }
}

// ===================== LayerNorm -> bf16 hi/lo =========================
__global__ __launch_bounds__(256)
void layernorm_split_kernel(const float* __restrict__ x, const float* __restrict__ gamma,
                            const float* __restrict__ beta,
                            bf16* __restrict__ oh, bf16* __restrict__ ol)
{
    long long row = blockIdx.x;
    const float4* xr = (const float4*)(x + row * EMB);
    float4 v = xr[threadIdx.x];
    float s  = v.x + v.y + v.z + v.w;
    float ss = v.x * v.x + v.y * v.y + v.z * v.z + v.w * v.w;
#pragma unroll
    for (int o = 16; o; o >>= 1) {
        s  += __shfl_xor_sync(0xffffffffu, s,  o);
        ss += __shfl_xor_sync(0xffffffffu, ss, o);
    }
    __shared__ float sh_s[8], sh_ss[8];
    int w = threadIdx.x >> 5, l = threadIdx.x & 31;
    if (l == 0) { sh_s[w] = s; sh_ss[w] = ss; }
    __syncthreads();
    s = 0.f; ss = 0.f;
#pragma unroll
    for (int i = 0; i < 8; i++) { s += sh_s[i]; ss += sh_ss[i]; }
    float mu   = s * (1.0f / EMB);
    float var  = ss * (1.0f / EMB) - mu * mu;
    float rstd = rsqrtf(var + 1e-6f);
    float4 gv = ((const float4*)gamma)[threadIdx.x];
    float4 bv = ((const float4*)beta)[threadIdx.x];
    float o0 = (v.x - mu) * rstd * gv.x + bv.x;
    float o1 = (v.y - mu) * rstd * gv.y + bv.y;
    float o2 = (v.z - mu) * rstd * gv.z + bv.z;
    float o3 = (v.w - mu) * rstd * gv.w + bv.w;
    bf16 h0,l0,h1,l1,h2,l2,h3,l3;
    bf16split(o0,h0,l0); bf16split(o1,h1,l1); bf16split(o2,h2,l2); bf16split(o3,h3,l3);
    long long base = row * EMB + threadIdx.x * 4;
    __nv_bfloat162 a; a.x=h0; a.y=h1; __nv_bfloat162 b; b.x=h2; b.y=h3;
    __nv_bfloat162 c; c.x=l0; c.y=l1; __nv_bfloat162 d; d.x=l2; d.y=l3;
    *(__nv_bfloat162*)(oh + base)     = a;
    *(__nv_bfloat162*)(oh + base + 2) = b;
    *(__nv_bfloat162*)(ol + base)     = c;
    *(__nv_bfloat162*)(ol + base + 2) = d;
}

// ===================== Softmax -> bf16 hi/lo ===========================
__global__ __launch_bounds__(256)
void softmax_split_kernel(const float* __restrict__ S,
                          bf16* __restrict__ ph, bf16* __restrict__ pl)
{
    long long row = blockIdx.x;
    const float* p = S + row * SEQ;
    float4 v0 = ((const float4*)p)[threadIdx.x];
    float4 v1 = ((const float4*)p)[threadIdx.x + 256];

    float m = fmaxf(fmaxf(fmaxf(v0.x, v0.y), fmaxf(v0.z, v0.w)),
                    fmaxf(fmaxf(v1.x, v1.y), fmaxf(v1.z, v1.w)));
#pragma unroll
    for (int o = 16; o; o >>= 1) m = fmaxf(m, __shfl_xor_sync(0xffffffffu, m, o));
    __shared__ float sh[8];
    int w = threadIdx.x >> 5, l = threadIdx.x & 31;
    if (l == 0) sh[w] = m;
    __syncthreads();
    m = sh[0];
#pragma unroll
    for (int i = 1; i < 8; i++) m = fmaxf(m, sh[i]);
    __syncthreads();

    v0.x = expf(v0.x - m); v0.y = expf(v0.y - m); v0.z = expf(v0.z - m); v0.w = expf(v0.w - m);
    v1.x = expf(v1.x - m); v1.y = expf(v1.y - m); v1.z = expf(v1.z - m); v1.w = expf(v1.w - m);
    float s = v0.x + v0.y + v0.z + v0.w + v1.x + v1.y + v1.z + v1.w;
#pragma unroll
    for (int o = 16; o; o >>= 1) s += __shfl_xor_sync(0xffffffffu, s, o);
    if (l == 0) sh[w] = s;
    __syncthreads();
    s = 0.f;
#pragma unroll
    for (int i = 0; i < 8; i++) s += sh[i];
    float inv = 1.0f / s;

    float a[8] = {v0.x*inv, v0.y*inv, v0.z*inv, v0.w*inv,
                  v1.x*inv, v1.y*inv, v1.z*inv, v1.w*inv};
    long long b0 = row * SEQ + threadIdx.x * 4;
    long long b1 = row * SEQ + 1024 + threadIdx.x * 4;
#pragma unroll
    for (int g = 0; g < 2; g++) {
        long long base = g ? b1 : b0;
        bf16 h0,l0,h1,l1,h2,l2,h3,l3;
        bf16split(a[g*4+0],h0,l0); bf16split(a[g*4+1],h1,l1);
        bf16split(a[g*4+2],h2,l2); bf16split(a[g*4+3],h3,l3);
        __nv_bfloat162 x; x.x=h0; x.y=h1; __nv_bfloat162 y; y.x=h2; y.y=h3;
        __nv_bfloat162 u; u.x=l0; u.y=l1; __nv_bfloat162 t; t.x=l2; t.y=l3;
        *(__nv_bfloat162*)(ph + base)     = x;
        *(__nv_bfloat162*)(ph + base + 2) = y;
        *(__nv_bfloat162*)(pl + base)     = u;
        *(__nv_bfloat162*)(pl + base + 2) = t;
    }
}

// ============ transpose-convert: src fp32 [R,C] -> dst [C,R] hi/lo =====
__global__ __launch_bounds__(256)
void wt_prep_kernel(const float* __restrict__ src, int R, int C,
                    bf16* __restrict__ dh, bf16* __restrict__ dl)
{
    __shared__ float t[32][33];
    int c0 = blockIdx.x * 32, r0 = blockIdx.y * 32;
    int tx = threadIdx.x & 31, ty = threadIdx.x >> 5;
#pragma unroll
    for (int i = ty; i < 32; i += 8)
        t[i][tx] = src[(long long)(r0 + i) * C + c0 + tx];
    __syncthreads();
#pragma unroll
    for (int i = ty; i < 32; i += 8) {
        float v = t[tx][i];
        bf16 h, l; bf16split(v, h, l);
        long long o = (long long)(c0 + i) * R + r0 + tx;
        dh[o] = h; dl[o] = l;
    }
}

// ============ V^T prep: qkv -> vt hi/lo [BH, 64, 2048] =================
__global__ __launch_bounds__(256)
void vt_prep_kernel(const float* __restrict__ qkv, bf16* __restrict__ dh, bf16* __restrict__ dl)
{
    __shared__ float t[32][33];
    int bh = blockIdx.z, b = bh / NHEAD, h = bh % NHEAD;
    int n0 = blockIdx.x * 32, d0 = blockIdx.y * 32;
    int tx = threadIdx.x & 31, ty = threadIdx.x >> 5;
#pragma unroll
    for (int i = ty; i < 32; i += 8)
        t[i][tx] = qkv[((long long)(b * SEQ + n0 + i)) * (3 * EMB) + 2 * EMB + h * HDIM + d0 + tx];
    __syncthreads();
#pragma unroll
    for (int i = ty; i < 32; i += 8) {
        float v = t[tx][i];
        bf16 hh, ll; bf16split(v, hh, ll);
        long long o = ((long long)bh * HDIM + d0 + i) * SEQ + n0 + tx;
        dh[o] = hh; dl[o] = ll;
    }
}

// ============ Q/K prep: qkv -> q,k hi/lo [BH, 2048, 64] ================
__global__ __launch_bounds__(256)
void qk_prep_kernel(const float* __restrict__ qkv,
                    bf16* __restrict__ qh, bf16* __restrict__ ql,
                    bf16* __restrict__ kh, bf16* __restrict__ kl)
{
    long long idx4 = (long long)blockIdx.x * 256 + threadIdx.x;
    long long e  = idx4 * 4;
    long long bn = e / EMB;
    int c  = (int)(e % EMB);
    long long b  = bn / SEQ, n = bn % SEQ;
    int h = c / HDIM, d = c % HDIM;
    long long src = bn * (3 * EMB) + (long long)h * HDIM + d;
    long long dst = ((b * NHEAD + h) * SEQ + n) * HDIM + d;
    float4 q4 = *(const float4*)(qkv + src);
    float4 k4 = *(const float4*)(qkv + src + EMB);
    bf16 h0,l0,h1,l1,h2,l2,h3,l3;
    bf16split(q4.x,h0,l0); bf16split(q4.y,h1,l1); bf16split(q4.z,h2,l2); bf16split(q4.w,h3,l3);
    { __nv_bfloat162 a; a.x=h0; a.y=h1; __nv_bfloat162 bb; bb.x=h2; bb.y=h3;
      __nv_bfloat162 cc; cc.x=l0; cc.y=l1; __nv_bfloat162 dd; dd.x=l2; dd.y=l3;
      *(__nv_bfloat162*)(qh+dst)=a; *(__nv_bfloat162*)(qh+dst+2)=bb;
      *(__nv_bfloat162*)(ql+dst)=cc; *(__nv_bfloat162*)(ql+dst+2)=dd; }
    bf16split(k4.x,h0,l0); bf16split(k4.y,h1,l1); bf16split(k4.z,h2,l2); bf16split(k4.w,h3,l3);
    { __nv_bfloat162 a; a.x=h0; a.y=h1; __nv_bfloat162 bb; bb.x=h2; bb.y=h3;
      __nv_bfloat162 cc; cc.x=l0; cc.y=l1; __nv_bfloat162 dd; dd.x=l2; dd.y=l3;
      *(__nv_bfloat162*)(kh+dst)=a; *(__nv_bfloat162*)(kh+dst+2)=bb;
      *(__nv_bfloat162*)(kl+dst)=cc; *(__nv_bfloat162*)(kl+dst+2)=dd; }
}

// ===================== host side =======================================
template<int BN, int WM, int WN, int EPI>
static void launch_gemm(const bf16* Ahi, const bf16* Alo, const bf16* Bhi, const bf16* Blo,
                        const float* bias, const float* resid,
                        float* C, bf16* Chi, bf16* Clo,
                        int M, int N, int K, int ldc,
                        long long sA, long long sB,
                        int batch, int hdiv, long long sCb, long long sCh,
                        float alpha)
{
    constexpr int SMEM_BYTES = 2 * (2 * 128 * 128 + 2 * BN * 128);
    cudaFuncSetAttribute(gemm_mma<BN, WM, WN, EPI>,
                         cudaFuncAttributeMaxDynamicSharedMemorySize, SMEM_BYTES);
    dim3 grid(N / BN, M / 128, batch);
    gemm_mma<BN, WM, WN, EPI><<<grid, 256, SMEM_BYTES>>>(
        Ahi, Alo, Bhi, Blo, bias, resid, C, Chi, Clo,
        M, N, K, ldc, sA, sB, hdiv, sCb, sCh, alpha);
}

extern "C" void kernel_launch(void* const* d_in, const int* in_sizes, int n_in,
                              void* d_out, int out_size)
{
    const float* x      = (const float*)d_in[0];
    const float* ln1_g  = (const float*)d_in[1];
    const float* ln1_b  = (const float*)d_in[2];
    const float* w_qkv  = (const float*)d_in[3];
    const float* b_qkv  = (const float*)d_in[4];
    const float* w_proj = (const float*)d_in[5];
    const float* b_proj = (const float*)d_in[6];
    const float* ln2_g  = (const float*)d_in[7];
    const float* ln2_b  = (const float*)d_in[8];
    const float* w_fc1  = (const float*)d_in[9];
    const float* b_fc1  = (const float*)d_in[10];
    const float* w_fc2  = (const float*)d_in[11];
    const float* b_fc2  = (const float*)d_in[12];
    float* out = (float*)d_out;

    bf16 *wqkvTh, *wqkvTl, *wprojTh, *wprojTl, *wfc1Th, *wfc1Tl, *wfc2Th, *wfc2Tl;
    bf16 *ln1h, *ln1l, *qh, *ql, *kh, *kl, *vth, *vtl, *ph, *pl, *amh, *aml, *ln2h, *ln2l, *hh, *hl;
    float *qkv, *scores, *x1;
    cudaGetSymbolAddress((void**)&wqkvTh, g_wqkvT_h);  cudaGetSymbolAddress((void**)&wqkvTl, g_wqkvT_l);
    cudaGetSymbolAddress((void**)&wprojTh, g_wprojT_h); cudaGetSymbolAddress((void**)&wprojTl, g_wprojT_l);
    cudaGetSymbolAddress((void**)&wfc1Th, g_wfc1T_h);  cudaGetSymbolAddress((void**)&wfc1Tl, g_wfc1T_l);
    cudaGetSymbolAddress((void**)&wfc2Th, g_wfc2T_h);  cudaGetSymbolAddress((void**)&wfc2Tl, g_wfc2T_l);
    cudaGetSymbolAddress((void**)&ln1h, g_ln1_h);      cudaGetSymbolAddress((void**)&ln1l, g_ln1_l);
    cudaGetSymbolAddress((void**)&qkv, g_qkv);
    cudaGetSymbolAddress((void**)&qh, g_q_h);          cudaGetSymbolAddress((void**)&ql, g_q_l);
    cudaGetSymbolAddress((void**)&kh, g_k_h);          cudaGetSymbolAddress((void**)&kl, g_k_l);
    cudaGetSymbolAddress((void**)&vth, g_vt_h);        cudaGetSymbolAddress((void**)&vtl, g_vt_l);
    cudaGetSymbolAddress((void**)&scores, g_scores);
    cudaGetSymbolAddress((void**)&ph, g_p_h);          cudaGetSymbolAddress((void**)&pl, g_p_l);
    cudaGetSymbolAddress((void**)&amh, g_am_h);        cudaGetSymbolAddress((void**)&aml, g_am_l);
    cudaGetSymbolAddress((void**)&x1, g_x1);
    cudaGetSymbolAddress((void**)&ln2h, g_ln2_h);      cudaGetSymbolAddress((void**)&ln2l, g_ln2_l);
    cudaGetSymbolAddress((void**)&hh, g_h_h);          cudaGetSymbolAddress((void**)&hl, g_h_l);

    // 0) weight transpose-converts  W[K,N] -> Wt[N,K] hi/lo
    wt_prep_kernel<<<dim3(3 * EMB / 32, EMB / 32), 256>>>(w_qkv, EMB, 3 * EMB, wqkvTh, wqkvTl);
    wt_prep_kernel<<<dim3(EMB / 32, EMB / 32), 256>>>(w_proj, EMB, EMB, wprojTh, wprojTl);
    wt_prep_kernel<<<dim3(HIDDEN / 32, EMB / 32), 256>>>(w_fc1, EMB, HIDDEN, wfc1Th, wfc1Tl);
    wt_prep_kernel<<<dim3(EMB / 32, HIDDEN / 32), 256>>>(w_fc2, HIDDEN, EMB, wfc2Th, wfc2Tl);

    // 1) LN1 -> hi/lo
    layernorm_split_kernel<<<TOK, 256>>>(x, ln1_g, ln1_b, ln1h, ln1l);

    // 2) QKV: [4096,3072] = ln1 @ w_qkv + b  (fp32 out)
    launch_gemm<128, 64, 32, EPI_BIAS>(ln1h, ln1l, wqkvTh, wqkvTl, b_qkv, nullptr,
                                       qkv, nullptr, nullptr,
                                       TOK, 3 * EMB, EMB, 3 * EMB, 0, 0, 1, 1, 0, 0, 1.0f);

    // 3) Q/K gather + V transpose, split to bf16
    qk_prep_kernel<<<(TOK * EMB / 4) / 256, 256>>>(qkv, qh, ql, kh, kl);
    vt_prep_kernel<<<dim3(SEQ / 32, HDIM / 32, BH), 256>>>(qkv, vth, vtl);

    // 4) scores = 0.125 * Q K^T  (batched 32)
    launch_gemm<128, 64, 32, EPI_ALPHA>(qh, ql, kh, kl, nullptr, nullptr,
                                        scores, nullptr, nullptr,
                                        SEQ, SEQ, HDIM, SEQ,
                                        (long long)SEQ * HDIM, (long long)SEQ * HDIM,
                                        BH, 1, (long long)SEQ * SEQ, 0, 0.125f);

    // 5) softmax -> P hi/lo
    softmax_split_kernel<<<BH * SEQ, 256>>>(scores, ph, pl);

    // 6) attn = P @ V  -> merged heads, split bf16  (batched 32, N=64)
    launch_gemm<64, 32, 32, EPI_SPLIT>(ph, pl, vth, vtl, nullptr, nullptr,
                                       nullptr, amh, aml,
                                       SEQ, HDIM, SEQ, EMB,
                                       (long long)SEQ * SEQ, (long long)HDIM * SEQ,
                                       BH, NHEAD, (long long)SEQ * EMB, HDIM, 1.0f);

    // 7) proj + residual: x1 = attnm @ w_proj + b + x
    launch_gemm<128, 64, 32, EPI_BIAS_RES>(amh, aml, wprojTh, wprojTl, b_proj, x,
                                           x1, nullptr, nullptr,
                                           TOK, EMB, EMB, EMB, 0, 0, 1, 1, 0, 0, 1.0f);

    // 8) LN2 -> hi/lo
    layernorm_split_kernel<<<TOK, 256>>>(x1, ln2_g, ln2_b, ln2h, ln2l);

    // 9) FC1 + GELU -> h hi/lo
    launch_gemm<128, 64, 32, EPI_GELU_SPLIT>(ln2h, ln2l, wfc1Th, wfc1Tl, b_fc1, nullptr,
                                             nullptr, hh, hl,
                                             TOK, HIDDEN, EMB, HIDDEN, 0, 0, 1, 1, 0, 0, 1.0f);

    // 10) FC2 + bias + residual -> out
    launch_gemm<128, 64, 32, EPI_BIAS_RES>(hh, hl, wfc2Th, wfc2Tl, b_fc2, x1,
                                           out, nullptr, nullptr,
                                           TOK, EMB, HIDDEN, EMB, 0, 0, 1, 1, 0, 0, 1.0f);
}

// round 10
// speedup vs baseline: 1.8944x; 1.2174x over previous
#include <cuda_runtime.h>
#include <cuda_bf16.h>
#include <math.h>
#include <stdint.h>

// Problem constants
#define Bz     2
#define SEQ    2048
#define EMB    1024
#define NHEAD  16
#define HDIM   64
#define HIDDEN 4096
#define TOK    (Bz * SEQ)          // 4096 rows
#define BH     (Bz * NHEAD)        // 32 batched heads

typedef __nv_bfloat16 bf16;

// ===================== MMA / async primitives (non-'a' PTX) ============
__device__ __forceinline__ void ldm_x4(uint32_t* r, uint32_t addr) {
    asm volatile("ldmatrix.sync.aligned.m8n8.x4.shared.b16 {%0,%1,%2,%3}, [%4];"
        : "=r"(r[0]), "=r"(r[1]), "=r"(r[2]), "=r"(r[3]) : "r"(addr));
}
__device__ __forceinline__ void mma_bf16(float* c, const uint32_t* a,
                                         uint32_t b0, uint32_t b1) {
    asm volatile(
        "mma.sync.aligned.m16n8k16.row.col.f32.bf16.bf16.f32 "
        "{%0,%1,%2,%3}, {%4,%5,%6,%7}, {%8,%9}, {%0,%1,%2,%3};"
        : "+f"(c[0]), "+f"(c[1]), "+f"(c[2]), "+f"(c[3])
        : "r"(a[0]), "r"(a[1]), "r"(a[2]), "r"(a[3]), "r"(b0), "r"(b1));
}
__device__ __forceinline__ uint32_t smem_to_u32(const void* p) {
    uint32_t a;
    asm("{ .reg .u64 t; cvta.to.shared.u64 t, %1; cvt.u32.u64 %0, t; }" : "=r"(a) : "l"(p));
    return a;
}
#define SW128(off) ((off) ^ (((off) >> 3) & 0x70))

#define CP_ASYNC16(saddr, gptr) \
    asm volatile("cp.async.cg.shared.global [%0], [%1], 16;" \
        :: "r"((uint32_t)(saddr)), "l"(gptr))
#define CP_COMMIT() asm volatile("cp.async.commit_group;" ::: "memory")
#define CP_WAIT1()  asm volatile("cp.async.wait_group 1;" ::: "memory")
#define CP_WAIT0()  asm volatile("cp.async.wait_group 0;" ::: "memory")

__device__ __forceinline__ uint32_t pack_bf16(float a, float b) {
    __nv_bfloat162 h;
    h.x = __float2bfloat16(a);
    h.y = __float2bfloat16(b);
    return *(uint32_t*)&h;
}

// ===================== scratch =========================================
__device__ bf16  g_wqkvT_h[3 * EMB * EMB],  g_wqkvT_l[3 * EMB * EMB];
__device__ bf16  g_wprojT_h[EMB * EMB],     g_wprojT_l[EMB * EMB];
__device__ bf16  g_wfc1T_h[HIDDEN * EMB],   g_wfc1T_l[HIDDEN * EMB];
__device__ bf16  g_wfc2T_h[EMB * HIDDEN],   g_wfc2T_l[EMB * HIDDEN];
__device__ bf16  g_ln1_h[TOK * EMB],        g_ln1_l[TOK * EMB];
__device__ float g_qkv[TOK * 3 * EMB];
__device__ bf16  g_q_h[BH * SEQ * HDIM],    g_q_l[BH * SEQ * HDIM];
__device__ bf16  g_k_h[BH * SEQ * HDIM],    g_k_l[BH * SEQ * HDIM];
__device__ bf16  g_vt_h[BH * HDIM * SEQ],   g_vt_l[BH * HDIM * SEQ];
__device__ bf16  g_am_h[TOK * EMB],         g_am_l[TOK * EMB];
__device__ float g_x1[TOK * EMB];
__device__ bf16  g_ln2_h[TOK * EMB],        g_ln2_l[TOK * EMB];
__device__ bf16  g_h_h[TOK * HIDDEN],       g_h_l[TOK * HIDDEN];

__device__ __forceinline__ void bf16split(float v, bf16& hi, bf16& lo) {
    hi = __float2bfloat16(v);
    lo = __float2bfloat16(v - __bfloat162float(hi));
}
__device__ __forceinline__ float gelu_exact(float x) {
    return 0.5f * x * (1.0f + erff(x * 0.70710678118654752440f));
}

// ===================== mma.sync split-bf16 GEMM (cp.async pipelined) ===
#define EPI_ALPHA      0
#define EPI_BIAS       1
#define EPI_BIAS_RES   2
#define EPI_SPLIT      3
#define EPI_GELU_SPLIT 4

template<int BN, int WM, int WN, int EPI>
__global__ __launch_bounds__(256, 1)
void gemm_mma(const bf16* __restrict__ Ahi, const bf16* __restrict__ Alo,
              const bf16* __restrict__ Bhi, const bf16* __restrict__ Blo,
              const float* __restrict__ bias, const float* __restrict__ resid,
              float* __restrict__ C, bf16* __restrict__ Chi, bf16* __restrict__ Clo,
              int M, int N, int K, int ldc,
              long long sA, long long sB,
              int hdiv, long long sCb, long long sCh,
              float alpha)
{
    constexpr int BK = 64;
    constexpr int OFF_AL = 128 * 128;
    constexpr int OFF_BH = 2 * 128 * 128;
    constexpr int OFF_BL = OFF_BH + BN * 128;
    constexpr int BUFB   = OFF_BL + BN * 128;
    constexpr int WGC = BN / WN;
    constexpr int MT  = WM / 16;
    constexpr int NT  = WN / 8;
    constexpr int NG  = WN / 16;

    extern __shared__ char sm[];
    const uint32_t smb = smem_to_u32(sm);
    const int tid = threadIdx.x, wid = tid >> 5, lane = tid & 31;
    const int bm = blockIdx.y * 128, bn = blockIdx.x * BN, z = blockIdx.z;
    const int wm0 = (wid / WGC) * WM, wn0 = (wid % WGC) * WN;

    Ahi += (long long)z * sA;  Alo += (long long)z * sA;
    Bhi += (long long)z * sB;  Blo += (long long)z * sB;
    const long long coff = (long long)(z / hdiv) * sCb + (long long)(z % hdiv) * sCh;

    float acc[MT][NT][4];
#pragma unroll
    for (int i = 0; i < MT; i++)
#pragma unroll
        for (int j = 0; j < NT; j++)
#pragma unroll
            for (int t = 0; t < 4; t++) acc[i][j][t] = 0.0f;

    const int swz   = lane & 7;
    const int aHalf = lane >> 4;
    const int bHalf = (lane >> 3) & 1;
    int aRowOff[MT], bRowOff[NG];
#pragma unroll
    for (int mt = 0; mt < MT; mt++)
        aRowOff[mt] = (wm0 + mt * 16 + (lane & 15)) * 128;
#pragma unroll
    for (int ng = 0; ng < NG; ng++)
        bRowOff[ng] = (wn0 + ng * 16 + (lane & 7) + ((lane >> 4) << 3)) * 128;

    auto stage = [&](int c, uint32_t base) {
        const long long k0 = (long long)c * BK;
        const bf16* a0 = Ahi + (long long)bm * K + k0;
        const bf16* a1 = Alo + (long long)bm * K + k0;
#pragma unroll
        for (int i = tid; i < 128 * 8; i += 256) {
            int r = i >> 3, u = i & 7;
            int sw = SW128(r * 128 + u * 16);
            CP_ASYNC16(smb + base + sw,          a0 + (long long)r * K + u * 8);
            CP_ASYNC16(smb + base + OFF_AL + sw, a1 + (long long)r * K + u * 8);
        }
        const bf16* b0 = Bhi + (long long)bn * K + k0;
        const bf16* b1 = Blo + (long long)bn * K + k0;
#pragma unroll
        for (int i = tid; i < BN * 8; i += 256) {
            int r = i >> 3, u = i & 7;
            int sw = SW128(r * 128 + u * 16);
            CP_ASYNC16(smb + base + OFF_BH + sw, b0 + (long long)r * K + u * 8);
            CP_ASYNC16(smb + base + OFF_BL + sw, b1 + (long long)r * K + u * 8);
        }
        CP_COMMIT();
    };

    const int nch = K / BK;
    stage(0, 0);
    for (int c = 0; c < nch; c++) {
        const uint32_t cur = (c & 1) ? BUFB : 0;
        if (c + 1 < nch) {
            stage(c + 1, (c & 1) ? 0 : BUFB);
            CP_WAIT1();
        } else {
            CP_WAIT0();
        }
        __syncthreads();

#pragma unroll
        for (int ks = 0; ks < BK / 16; ks++) {
            const uint32_t ca = (uint32_t)(((2 * ks + aHalf) ^ swz) * 16);
            const uint32_t cb = (uint32_t)(((2 * ks + bHalf) ^ swz) * 16);
            uint32_t ah[MT][4], al[MT][4], bhr[NG][4], blr[NG][4];
#pragma unroll
            for (int mt = 0; mt < MT; mt++) {
                ldm_x4(ah[mt], smb + cur + aRowOff[mt] + ca);
                ldm_x4(al[mt], smb + cur + OFF_AL + aRowOff[mt] + ca);
            }
#pragma unroll
            for (int ng = 0; ng < NG; ng++) {
                ldm_x4(bhr[ng], smb + cur + OFF_BH + bRowOff[ng] + cb);
                ldm_x4(blr[ng], smb + cur + OFF_BL + bRowOff[ng] + cb);
            }
#pragma unroll
            for (int mt = 0; mt < MT; mt++)
#pragma unroll
                for (int nt = 0; nt < NT; nt++)
                    mma_bf16(acc[mt][nt], ah[mt],
                             bhr[nt >> 1][(nt & 1) * 2], bhr[nt >> 1][(nt & 1) * 2 + 1]);
#pragma unroll
            for (int mt = 0; mt < MT; mt++)
#pragma unroll
                for (int nt = 0; nt < NT; nt++)
                    mma_bf16(acc[mt][nt], ah[mt],
                             blr[nt >> 1][(nt & 1) * 2], blr[nt >> 1][(nt & 1) * 2 + 1]);
#pragma unroll
            for (int mt = 0; mt < MT; mt++)
#pragma unroll
                for (int nt = 0; nt < NT; nt++)
                    mma_bf16(acc[mt][nt], al[mt],
                             bhr[nt >> 1][(nt & 1) * 2], bhr[nt >> 1][(nt & 1) * 2 + 1]);
        }
        __syncthreads();
    }

#pragma unroll
    for (int mt = 0; mt < MT; mt++) {
#pragma unroll
        for (int half = 0; half < 2; half++) {
            const long long row = bm + wm0 + mt * 16 + (lane >> 2) + half * 8;
#pragma unroll
            for (int nt = 0; nt < NT; nt++) {
                const int col = bn + wn0 + nt * 8 + (lane & 3) * 2;
                float v0 = acc[mt][nt][half * 2 + 0] * alpha;
                float v1 = acc[mt][nt][half * 2 + 1] * alpha;
                if (EPI == EPI_BIAS || EPI == EPI_BIAS_RES || EPI == EPI_GELU_SPLIT) {
                    v0 += bias[col]; v1 += bias[col + 1];
                }
                if (EPI == EPI_BIAS_RES) {
                    const float* rp = resid + coff + row * (long long)ldc + col;
                    v0 += rp[0]; v1 += rp[1];
                }
                if (EPI == EPI_GELU_SPLIT) {
                    v0 = gelu_exact(v0); v1 = gelu_exact(v1);
                }
                const long long o = coff + row * (long long)ldc + col;
                if (EPI == EPI_ALPHA || EPI == EPI_BIAS || EPI == EPI_BIAS_RES) {
                    float2 w; w.x = v0; w.y = v1;
                    *(float2*)(C + o) = w;
                } else {
                    bf16 h0, l0, h1, l1;
                    bf16split(v0, h0, l0); bf16split(v1, h1, l1);
                    __nv_bfloat162 hh; hh.x = h0; hh.y = h1;
                    __nv_bfloat162 ll; ll.x = l0; ll.y = l1;
                    *(__nv_bfloat162*)(Chi + o) = hh;
                    *(__nv_bfloat162*)(Clo + o) = ll;
                }
            }
        }
    }
}

// ===================== Flash attention v2 ==============================
// Grid (SEQ/128, BH), 256 threads. Q tile 128 (16 rows/warp), KV tile 64,
// K/V double-buffered via cp.async. Q pre-scaled by 0.125 in qk_prep.
__global__ __launch_bounds__(256, 1)
void flash_kernel(const bf16* __restrict__ Qh, const bf16* __restrict__ Ql,
                  const bf16* __restrict__ Kh, const bf16* __restrict__ Kl,
                  const bf16* __restrict__ Vh, const bf16* __restrict__ Vl,
                  bf16* __restrict__ Oh, bf16* __restrict__ Ol)
{
    constexpr int OFF_QL = 16384;
    constexpr int OFF_K  = 32768;      // 2 bufs x (hi 8K + lo 8K)
    constexpr int OFF_V  = 65536;      // 2 bufs x (hi 8K + lo 8K)
    constexpr int KBUF   = 16384;
    extern __shared__ char sm[];
    const uint32_t smb = smem_to_u32(sm);
    const int tid = threadIdx.x, wid = tid >> 5, lane = tid & 31;
    const int bh = blockIdx.y, q0 = blockIdx.x * 128;
    const long long qkbase = (long long)bh * SEQ * HDIM;
    const long long vbase  = (long long)bh * HDIM * SEQ;
    const int swz = lane & 7;

    // stage Q (128 x 64 hi/lo)
#pragma unroll
    for (int i = tid; i < 128 * 8; i += 256) {
        int r = i >> 3, u = i & 7;
        int sw = SW128(r * 128 + u * 16);
        CP_ASYNC16(smb + sw,          Qh + qkbase + (long long)(q0 + r) * HDIM + u * 8);
        CP_ASYNC16(smb + OFF_QL + sw, Ql + qkbase + (long long)(q0 + r) * HDIM + u * 8);
    }
    CP_COMMIT();

    auto stage = [&](int t, int buf) {
        const int kv0 = t * 64;
        const uint32_t kb = OFF_K + buf * KBUF, vb = OFF_V + buf * KBUF;
#pragma unroll
        for (int i = tid; i < 64 * 8; i += 256) {
            int r = i >> 3, u = i & 7;
            int sw = SW128(r * 128 + u * 16);
            CP_ASYNC16(smb + kb + sw,        Kh + qkbase + (long long)(kv0 + r) * HDIM + u * 8);
            CP_ASYNC16(smb + kb + 8192 + sw, Kl + qkbase + (long long)(kv0 + r) * HDIM + u * 8);
            CP_ASYNC16(smb + vb + sw,        Vh + vbase + (long long)r * SEQ + kv0 + u * 8);
            CP_ASYNC16(smb + vb + 8192 + sw, Vl + vbase + (long long)r * SEQ + kv0 + u * 8);
        }
        CP_COMMIT();
    };
    stage(0, 0);
    CP_WAIT0();
    __syncthreads();

    // persistent Q fragments
    uint32_t qfh[4][4], qfl[4][4];
    {
        const int aRowOff = (wid * 16 + (lane & 15)) * 128;
        const int aHalf = lane >> 4;
#pragma unroll
        for (int ks = 0; ks < 4; ks++) {
            const uint32_t ca = (uint32_t)(((2 * ks + aHalf) ^ swz) * 16);
            ldm_x4(qfh[ks], smb + aRowOff + ca);
            ldm_x4(qfl[ks], smb + OFF_QL + aRowOff + ca);
        }
    }

    float Oacc[8][4];
#pragma unroll
    for (int i = 0; i < 8; i++)
#pragma unroll
        for (int t = 0; t < 4; t++) Oacc[i][t] = 0.0f;
    float mrow[2] = {-1e30f, -1e30f};
    float lrow[2] = {0.0f, 0.0f};

    const int kRowOff = (lane & 7) + ((lane >> 4) << 3);
    const int bHalf = (lane >> 3) & 1;

    for (int t = 0; t < SEQ / 64; t++) {
        const int buf = t & 1;
        if (t + 1 < SEQ / 64) { stage(t + 1, buf ^ 1); CP_WAIT1(); }
        else                  { CP_WAIT0(); }
        __syncthreads();
        const uint32_t kb = OFF_K + buf * KBUF, vb = OFF_V + buf * KBUF;

        // ---- S = Q K^T (3-pass split) over 64 KV cols ----
        float S[8][4];
#pragma unroll
        for (int j = 0; j < 8; j++)
#pragma unroll
            for (int c = 0; c < 4; c++) S[j][c] = 0.0f;
#pragma unroll
        for (int g = 0; g < 4; g++) {
            const int bRow = (g * 16 + kRowOff) * 128;
#pragma unroll
            for (int ks = 0; ks < 4; ks++) {
                const uint32_t cb = (uint32_t)(((2 * ks + bHalf) ^ swz) * 16);
                uint32_t kh4[4], kl4[4];
                ldm_x4(kh4, smb + kb + bRow + cb);
                ldm_x4(kl4, smb + kb + 8192 + bRow + cb);
                mma_bf16(S[2 * g],     qfh[ks], kh4[0], kh4[1]);
                mma_bf16(S[2 * g + 1], qfh[ks], kh4[2], kh4[3]);
                mma_bf16(S[2 * g],     qfh[ks], kl4[0], kl4[1]);
                mma_bf16(S[2 * g + 1], qfh[ks], kl4[2], kl4[3]);
                mma_bf16(S[2 * g],     qfl[ks], kh4[0], kh4[1]);
                mma_bf16(S[2 * g + 1], qfl[ks], kh4[2], kh4[3]);
            }
        }

        // ---- online softmax ----
        float mt0 = -1e30f, mt1 = -1e30f;
#pragma unroll
        for (int j = 0; j < 8; j++) {
            mt0 = fmaxf(mt0, fmaxf(S[j][0], S[j][1]));
            mt1 = fmaxf(mt1, fmaxf(S[j][2], S[j][3]));
        }
        mt0 = fmaxf(mt0, __shfl_xor_sync(0xffffffffu, mt0, 1));
        mt0 = fmaxf(mt0, __shfl_xor_sync(0xffffffffu, mt0, 2));
        mt1 = fmaxf(mt1, __shfl_xor_sync(0xffffffffu, mt1, 1));
        mt1 = fmaxf(mt1, __shfl_xor_sync(0xffffffffu, mt1, 2));
        const float mn0 = fmaxf(mrow[0], mt0), mn1 = fmaxf(mrow[1], mt1);
        const float sc0 = __expf(mrow[0] - mn0), sc1 = __expf(mrow[1] - mn1);
        float rs0 = 0.0f, rs1 = 0.0f;
#pragma unroll
        for (int j = 0; j < 8; j++) {
            S[j][0] = __expf(S[j][0] - mn0);
            S[j][1] = __expf(S[j][1] - mn0);
            S[j][2] = __expf(S[j][2] - mn1);
            S[j][3] = __expf(S[j][3] - mn1);
            rs0 += S[j][0] + S[j][1];
            rs1 += S[j][2] + S[j][3];
        }
        rs0 += __shfl_xor_sync(0xffffffffu, rs0, 1);
        rs0 += __shfl_xor_sync(0xffffffffu, rs0, 2);
        rs1 += __shfl_xor_sync(0xffffffffu, rs1, 1);
        rs1 += __shfl_xor_sync(0xffffffffu, rs1, 2);
        lrow[0] = lrow[0] * sc0 + rs0;
        lrow[1] = lrow[1] * sc1 + rs1;
        mrow[0] = mn0; mrow[1] = mn1;
#pragma unroll
        for (int i = 0; i < 8; i++) {
            Oacc[i][0] *= sc0; Oacc[i][1] *= sc0;
            Oacc[i][2] *= sc1; Oacc[i][3] *= sc1;
        }

        // ---- O += P V (3-pass split) ----
#pragma unroll
        for (int j = 0; j < 4; j++) {
            float p00 = S[2*j][0],   p01 = S[2*j][1],   p02 = S[2*j][2],   p03 = S[2*j][3];
            float p10 = S[2*j+1][0], p11 = S[2*j+1][1], p12 = S[2*j+1][2], p13 = S[2*j+1][3];
            bf16 h, lo;
            uint32_t ah[4], al[4];
            float t0, t1, u0, u1;
            bf16split(p00, h, lo); t0 = __bfloat162float(h); u0 = __bfloat162float(lo);
            bf16split(p01, h, lo); t1 = __bfloat162float(h); u1 = __bfloat162float(lo);
            ah[0] = pack_bf16(t0, t1); al[0] = pack_bf16(u0, u1);
            bf16split(p02, h, lo); t0 = __bfloat162float(h); u0 = __bfloat162float(lo);
            bf16split(p03, h, lo); t1 = __bfloat162float(h); u1 = __bfloat162float(lo);
            ah[1] = pack_bf16(t0, t1); al[1] = pack_bf16(u0, u1);
            bf16split(p10, h, lo); t0 = __bfloat162float(h); u0 = __bfloat162float(lo);
            bf16split(p11, h, lo); t1 = __bfloat162float(h); u1 = __bfloat162float(lo);
            ah[2] = pack_bf16(t0, t1); al[2] = pack_bf16(u0, u1);
            bf16split(p12, h, lo); t0 = __bfloat162float(h); u0 = __bfloat162float(lo);
            bf16split(p13, h, lo); t1 = __bfloat162float(h); u1 = __bfloat162float(lo);
            ah[3] = pack_bf16(t0, t1); al[3] = pack_bf16(u0, u1);

            const uint32_t cv = (uint32_t)(((2 * j + bHalf) ^ swz) * 16);
#pragma unroll
            for (int vg = 0; vg < 4; vg++) {
                const int vRow = (vg * 16 + kRowOff) * 128;
                uint32_t vh4[4], vl4[4];
                ldm_x4(vh4, smb + vb + vRow + cv);
                ldm_x4(vl4, smb + vb + 8192 + vRow + cv);
                mma_bf16(Oacc[2 * vg],     ah, vh4[0], vh4[1]);
                mma_bf16(Oacc[2 * vg + 1], ah, vh4[2], vh4[3]);
                mma_bf16(Oacc[2 * vg],     ah, vl4[0], vl4[1]);
                mma_bf16(Oacc[2 * vg + 1], ah, vl4[2], vl4[3]);
                mma_bf16(Oacc[2 * vg],     al, vh4[0], vh4[1]);
                mma_bf16(Oacc[2 * vg + 1], al, vh4[2], vh4[3]);
            }
        }
        __syncthreads();
    }

    // ---- epilogue ----
    const float inv0 = 1.0f / lrow[0], inv1 = 1.0f / lrow[1];
    const int b = bh / NHEAD, hh = bh % NHEAD;
    const long long tok0 = (long long)b * SEQ + q0 + wid * 16 + (lane >> 2);
    const int col0 = hh * HDIM + (lane & 3) * 2;
#pragma unroll
    for (int vt = 0; vt < 8; vt++) {
        float v0 = Oacc[vt][0] * inv0, v1 = Oacc[vt][1] * inv0;
        float v2 = Oacc[vt][2] * inv1, v3 = Oacc[vt][3] * inv1;
        bf16 h0, l0, h1, l1;
        long long o = tok0 * EMB + col0 + vt * 8;
        bf16split(v0, h0, l0); bf16split(v1, h1, l1);
        { __nv_bfloat162 x; x.x = h0; x.y = h1; *(__nv_bfloat162*)(Oh + o) = x; }
        { __nv_bfloat162 x; x.x = l0; x.y = l1; *(__nv_bfloat162*)(Ol + o) = x; }
        long long o2 = (tok0 + 8) * EMB + col0 + vt * 8;
        bf16split(v2, h0, l0); bf16split(v3, h1, l1);
        { __nv_bfloat162 x; x.x = h0; x.y = h1; *(__nv_bfloat162*)(Oh + o2) = x; }
        { __nv_bfloat162 x; x.x = l0; x.y = l1; *(__nv_bfloat162*)(Ol + o2) = x; }
    }
}

// ===================== LayerNorm -> bf16 hi/lo =========================
__global__ __launch_bounds__(256)
void layernorm_split_kernel(const float* __restrict__ x, const float* __restrict__ gamma,
                            const float* __restrict__ beta,
                            bf16* __restrict__ oh, bf16* __restrict__ ol)
{
    long long row = blockIdx.x;
    const float4* xr = (const float4*)(x + row * EMB);
    float4 v = xr[threadIdx.x];
    float s  = v.x + v.y + v.z + v.w;
    float ss = v.x * v.x + v.y * v.y + v.z * v.z + v.w * v.w;
#pragma unroll
    for (int o = 16; o; o >>= 1) {
        s  += __shfl_xor_sync(0xffffffffu, s,  o);
        ss += __shfl_xor_sync(0xffffffffu, ss, o);
    }
    __shared__ float sh_s[8], sh_ss[8];
    int w = threadIdx.x >> 5, l = threadIdx.x & 31;
    if (l == 0) { sh_s[w] = s; sh_ss[w] = ss; }
    __syncthreads();
    s = 0.f; ss = 0.f;
#pragma unroll
    for (int i = 0; i < 8; i++) { s += sh_s[i]; ss += sh_ss[i]; }
    float mu   = s * (1.0f / EMB);
    float var  = ss * (1.0f / EMB) - mu * mu;
    float rstd = rsqrtf(var + 1e-6f);
    float4 gv = ((const float4*)gamma)[threadIdx.x];
    float4 bv = ((const float4*)beta)[threadIdx.x];
    float o0 = (v.x - mu) * rstd * gv.x + bv.x;
    float o1 = (v.y - mu) * rstd * gv.y + bv.y;
    float o2 = (v.z - mu) * rstd * gv.z + bv.z;
    float o3 = (v.w - mu) * rstd * gv.w + bv.w;
    bf16 h0,l0,h1,l1,h2,l2,h3,l3;
    bf16split(o0,h0,l0); bf16split(o1,h1,l1); bf16split(o2,h2,l2); bf16split(o3,h3,l3);
    long long base = row * EMB + threadIdx.x * 4;
    __nv_bfloat162 a; a.x=h0; a.y=h1; __nv_bfloat162 b; b.x=h2; b.y=h3;
    __nv_bfloat162 c; c.x=l0; c.y=l1; __nv_bfloat162 d; d.x=l2; d.y=l3;
    *(__nv_bfloat162*)(oh + base)     = a;
    *(__nv_bfloat162*)(oh + base + 2) = b;
    *(__nv_bfloat162*)(ol + base)     = c;
    *(__nv_bfloat162*)(ol + base + 2) = d;
}

// ============ transpose-convert: src fp32 [R,C] -> dst [C,R] hi/lo =====
__global__ __launch_bounds__(256)
void wt_prep_kernel(const float* __restrict__ src, int R, int C,
                    bf16* __restrict__ dh, bf16* __restrict__ dl)
{
    __shared__ float t[32][33];
    int c0 = blockIdx.x * 32, r0 = blockIdx.y * 32;
    int tx = threadIdx.x & 31, ty = threadIdx.x >> 5;
#pragma unroll
    for (int i = ty; i < 32; i += 8)
        t[i][tx] = src[(long long)(r0 + i) * C + c0 + tx];
    __syncthreads();
#pragma unroll
    for (int i = ty; i < 32; i += 8) {
        float v = t[tx][i];
        bf16 h, l; bf16split(v, h, l);
        long long o = (long long)(c0 + i) * R + r0 + tx;
        dh[o] = h; dl[o] = l;
    }
}

// ============ V^T prep: qkv -> vt hi/lo [BH, 64, 2048] =================
__global__ __launch_bounds__(256)
void vt_prep_kernel(const float* __restrict__ qkv, bf16* __restrict__ dh, bf16* __restrict__ dl)
{
    __shared__ float t[32][33];
    int bh = blockIdx.z, b = bh / NHEAD, h = bh % NHEAD;
    int n0 = blockIdx.x * 32, d0 = blockIdx.y * 32;
    int tx = threadIdx.x & 31, ty = threadIdx.x >> 5;
#pragma unroll
    for (int i = ty; i < 32; i += 8)
        t[i][tx] = qkv[((long long)(b * SEQ + n0 + i)) * (3 * EMB) + 2 * EMB + h * HDIM + d0 + tx];
    __syncthreads();
#pragma unroll
    for (int i = ty; i < 32; i += 8) {
        float v = t[tx][i];
        bf16 hh, ll; bf16split(v, hh, ll);
        long long o = ((long long)bh * HDIM + d0 + i) * SEQ + n0 + tx;
        dh[o] = hh; dl[o] = ll;
    }
}

// ============ Q/K prep: qkv -> q (x0.125), k hi/lo [BH, 2048, 64] ======
__global__ __launch_bounds__(256)
void qk_prep_kernel(const float* __restrict__ qkv,
                    bf16* __restrict__ qh, bf16* __restrict__ ql,
                    bf16* __restrict__ kh, bf16* __restrict__ kl)
{
    long long idx4 = (long long)blockIdx.x * 256 + threadIdx.x;
    long long e  = idx4 * 4;
    long long bn = e / EMB;
    int c  = (int)(e % EMB);
    long long b  = bn / SEQ, n = bn % SEQ;
    int h = c / HDIM, d = c % HDIM;
    long long src = bn * (3 * EMB) + (long long)h * HDIM + d;
    long long dst = ((b * NHEAD + h) * SEQ + n) * HDIM + d;
    float4 q4 = *(const float4*)(qkv + src);
    float4 k4 = *(const float4*)(qkv + src + EMB);
    q4.x *= 0.125f; q4.y *= 0.125f; q4.z *= 0.125f; q4.w *= 0.125f;
    bf16 h0,l0,h1,l1,h2,l2,h3,l3;
    bf16split(q4.x,h0,l0); bf16split(q4.y,h1,l1); bf16split(q4.z,h2,l2); bf16split(q4.w,h3,l3);
    { __nv_bfloat162 a; a.x=h0; a.y=h1; __nv_bfloat162 bb; bb.x=h2; bb.y=h3;
      __nv_bfloat162 cc; cc.x=l0; cc.y=l1; __nv_bfloat162 dd; dd.x=l2; dd.y=l3;
      *(__nv_bfloat162*)(qh+dst)=a; *(__nv_bfloat162*)(qh+dst+2)=bb;
      *(__nv_bfloat162*)(ql+dst)=cc; *(__nv_bfloat162*)(ql+dst+2)=dd; }
    bf16split(k4.x,h0,l0); bf16split(k4.y,h1,l1); bf16split(k4.z,h2,l2); bf16split(k4.w,h3,l3);
    { __nv_bfloat162 a; a.x=h0; a.y=h1; __nv_bfloat162 bb; bb.x=h2; bb.y=h3;
      __nv_bfloat162 cc; cc.x=l0; cc.y=l1; __nv_bfloat162 dd; dd.x=l2; dd.y=l3;
      *(__nv_bfloat162*)(kh+dst)=a; *(__nv_bfloat162*)(kh+dst+2)=bb;
      *(__nv_bfloat162*)(kl+dst)=cc; *(__nv_bfloat162*)(kl+dst+2)=dd; }
}

// ===================== host side =======================================
template<int BN, int WM, int WN, int EPI>
static void launch_gemm(const bf16* Ahi, const bf16* Alo, const bf16* Bhi, const bf16* Blo,
                        const float* bias, const float* resid,
                        float* C, bf16* Chi, bf16* Clo,
                        int M, int N, int K, int ldc,
                        long long sA, long long sB,
                        int batch, int hdiv, long long sCb, long long sCh,
                        float alpha)
{
    constexpr int SMEM_BYTES = 2 * (2 * 128 * 128 + 2 * BN * 128);
    cudaFuncSetAttribute(gemm_mma<BN, WM, WN, EPI>,
                         cudaFuncAttributeMaxDynamicSharedMemorySize, SMEM_BYTES);
    dim3 grid(N / BN, M / 128, batch);
    gemm_mma<BN, WM, WN, EPI><<<grid, 256, SMEM_BYTES>>>(
        Ahi, Alo, Bhi, Blo, bias, resid, C, Chi, Clo,
        M, N, K, ldc, sA, sB, hdiv, sCb, sCh, alpha);
}

extern "C" void kernel_launch(void* const* d_in, const int* in_sizes, int n_in,
                              void* d_out, int out_size)
{
    const float* x      = (const float*)d_in[0];
    const float* ln1_g  = (const float*)d_in[1];
    const float* ln1_b  = (const float*)d_in[2];
    const float* w_qkv  = (const float*)d_in[3];
    const float* b_qkv  = (const float*)d_in[4];
    const float* w_proj = (const float*)d_in[5];
    const float* b_proj = (const float*)d_in[6];
    const float* ln2_g  = (const float*)d_in[7];
    const float* ln2_b  = (const float*)d_in[8];
    const float* w_fc1  = (const float*)d_in[9];
    const float* b_fc1  = (const float*)d_in[10];
    const float* w_fc2  = (const float*)d_in[11];
    const float* b_fc2  = (const float*)d_in[12];
    float* out = (float*)d_out;

    bf16 *wqkvTh, *wqkvTl, *wprojTh, *wprojTl, *wfc1Th, *wfc1Tl, *wfc2Th, *wfc2Tl;
    bf16 *ln1h, *ln1l, *qh, *ql, *kh, *kl, *vth, *vtl, *amh, *aml, *ln2h, *ln2l, *hh, *hl;
    float *qkv, *x1;
    cudaGetSymbolAddress((void**)&wqkvTh, g_wqkvT_h);  cudaGetSymbolAddress((void**)&wqkvTl, g_wqkvT_l);
    cudaGetSymbolAddress((void**)&wprojTh, g_wprojT_h); cudaGetSymbolAddress((void**)&wprojTl, g_wprojT_l);
    cudaGetSymbolAddress((void**)&wfc1Th, g_wfc1T_h);  cudaGetSymbolAddress((void**)&wfc1Tl, g_wfc1T_l);
    cudaGetSymbolAddress((void**)&wfc2Th, g_wfc2T_h);  cudaGetSymbolAddress((void**)&wfc2Tl, g_wfc2T_l);
    cudaGetSymbolAddress((void**)&ln1h, g_ln1_h);      cudaGetSymbolAddress((void**)&ln1l, g_ln1_l);
    cudaGetSymbolAddress((void**)&qkv, g_qkv);
    cudaGetSymbolAddress((void**)&qh, g_q_h);          cudaGetSymbolAddress((void**)&ql, g_q_l);
    cudaGetSymbolAddress((void**)&kh, g_k_h);          cudaGetSymbolAddress((void**)&kl, g_k_l);
    cudaGetSymbolAddress((void**)&vth, g_vt_h);        cudaGetSymbolAddress((void**)&vtl, g_vt_l);
    cudaGetSymbolAddress((void**)&amh, g_am_h);        cudaGetSymbolAddress((void**)&aml, g_am_l);
    cudaGetSymbolAddress((void**)&x1, g_x1);
    cudaGetSymbolAddress((void**)&ln2h, g_ln2_h);      cudaGetSymbolAddress((void**)&ln2l, g_ln2_l);
    cudaGetSymbolAddress((void**)&hh, g_h_h);          cudaGetSymbolAddress((void**)&hl, g_h_l);

    // 0) weight transpose-converts  W[K,N] -> Wt[N,K] hi/lo
    wt_prep_kernel<<<dim3(3 * EMB / 32, EMB / 32), 256>>>(w_qkv, EMB, 3 * EMB, wqkvTh, wqkvTl);
    wt_prep_kernel<<<dim3(EMB / 32, EMB / 32), 256>>>(w_proj, EMB, EMB, wprojTh, wprojTl);
    wt_prep_kernel<<<dim3(HIDDEN / 32, EMB / 32), 256>>>(w_fc1, EMB, HIDDEN, wfc1Th, wfc1Tl);
    wt_prep_kernel<<<dim3(EMB / 32, HIDDEN / 32), 256>>>(w_fc2, HIDDEN, EMB, wfc2Th, wfc2Tl);

    // 1) LN1 -> hi/lo
    layernorm_split_kernel<<<TOK, 256>>>(x, ln1_g, ln1_b, ln1h, ln1l);

    // 2) QKV: [4096,3072] = ln1 @ w_qkv + b  (fp32 out)
    launch_gemm<128, 64, 32, EPI_BIAS>(ln1h, ln1l, wqkvTh, wqkvTl, b_qkv, nullptr,
                                       qkv, nullptr, nullptr,
                                       TOK, 3 * EMB, EMB, 3 * EMB, 0, 0, 1, 1, 0, 0, 1.0f);

    // 3) Q/K gather (+0.125 on Q) + V transpose, split to bf16
    qk_prep_kernel<<<(TOK * EMB / 4) / 256, 256>>>(qkv, qh, ql, kh, kl);
    vt_prep_kernel<<<dim3(SEQ / 32, HDIM / 32, BH), 256>>>(qkv, vth, vtl);

    // 4) fused flash attention -> merged heads bf16 hi/lo
    {
        constexpr int FSMEM = 96 * 1024;
        cudaFuncSetAttribute(flash_kernel,
                             cudaFuncAttributeMaxDynamicSharedMemorySize, FSMEM);
        dim3 grid(SEQ / 128, BH);
        flash_kernel<<<grid, 256, FSMEM>>>(qh, ql, kh, kl, vth, vtl, amh, aml);
    }

    // 5) proj + residual: x1 = attnm @ w_proj + b + x
    launch_gemm<128, 64, 32, EPI_BIAS_RES>(amh, aml, wprojTh, wprojTl, b_proj, x,
                                           x1, nullptr, nullptr,
                                           TOK, EMB, EMB, EMB, 0, 0, 1, 1, 0, 0, 1.0f);

    // 6) LN2 -> hi/lo
    layernorm_split_kernel<<<TOK, 256>>>(x1, ln2_g, ln2_b, ln2h, ln2l);

    // 7) FC1 + GELU -> h hi/lo
    launch_gemm<128, 64, 32, EPI_GELU_SPLIT>(ln2h, ln2l, wfc1Th, wfc1Tl, b_fc1, nullptr,
                                             nullptr, hh, hl,
                                             TOK, HIDDEN, EMB, HIDDEN, 0, 0, 1, 1, 0, 0, 1.0f);

    // 8) FC2 + bias + residual -> out
    launch_gemm<128, 64, 32, EPI_BIAS_RES>(hh, hl, wfc2Th, wfc2Tl, b_fc2, x1,
                                           out, nullptr, nullptr,
                                           TOK, EMB, HIDDEN, EMB, 0, 0, 1, 1, 0, 0, 1.0f);
}

// round 11
// speedup vs baseline: 2.3667x; 1.2493x over previous
#include <cuda_runtime.h>
#include <cuda_bf16.h>
#include <cuda_fp16.h>
#include <math.h>
#include <stdint.h>

// Problem constants
#define Bz     2
#define SEQ    2048
#define EMB    1024
#define NHEAD  16
#define HDIM   64
#define HIDDEN 4096
#define TOK    (Bz * SEQ)          // 4096 rows
#define BH     (Bz * NHEAD)        // 32 batched heads

typedef __nv_bfloat16 bf16;
typedef __half fp16;

// ===================== MMA / async primitives (non-'a' PTX) ============
__device__ __forceinline__ void ldm_x4(uint32_t* r, uint32_t addr) {
    asm volatile("ldmatrix.sync.aligned.m8n8.x4.shared.b16 {%0,%1,%2,%3}, [%4];"
        : "=r"(r[0]), "=r"(r[1]), "=r"(r[2]), "=r"(r[3]) : "r"(addr));
}
__device__ __forceinline__ void mma_bf16(float* c, const uint32_t* a,
                                         uint32_t b0, uint32_t b1) {
    asm volatile(
        "mma.sync.aligned.m16n8k16.row.col.f32.bf16.bf16.f32 "
        "{%0,%1,%2,%3}, {%4,%5,%6,%7}, {%8,%9}, {%0,%1,%2,%3};"
        : "+f"(c[0]), "+f"(c[1]), "+f"(c[2]), "+f"(c[3])
        : "r"(a[0]), "r"(a[1]), "r"(a[2]), "r"(a[3]), "r"(b0), "r"(b1));
}
__device__ __forceinline__ void mma_fp16(float* c, const uint32_t* a,
                                         uint32_t b0, uint32_t b1) {
    asm volatile(
        "mma.sync.aligned.m16n8k16.row.col.f32.f16.f16.f32 "
        "{%0,%1,%2,%3}, {%4,%5,%6,%7}, {%8,%9}, {%0,%1,%2,%3};"
        : "+f"(c[0]), "+f"(c[1]), "+f"(c[2]), "+f"(c[3])
        : "r"(a[0]), "r"(a[1]), "r"(a[2]), "r"(a[3]), "r"(b0), "r"(b1));
}
__device__ __forceinline__ uint32_t smem_to_u32(const void* p) {
    uint32_t a;
    asm("{ .reg .u64 t; cvta.to.shared.u64 t, %1; cvt.u32.u64 %0, t; }" : "=r"(a) : "l"(p));
    return a;
}
#define SW128(off) ((off) ^ (((off) >> 3) & 0x70))

#define CP_ASYNC16(saddr, gptr) \
    asm volatile("cp.async.cg.shared.global [%0], [%1], 16;" \
        :: "r"((uint32_t)(saddr)), "l"(gptr))
#define CP_COMMIT() asm volatile("cp.async.commit_group;" ::: "memory")
#define CP_WAIT1()  asm volatile("cp.async.wait_group 1;" ::: "memory")
#define CP_WAIT0()  asm volatile("cp.async.wait_group 0;" ::: "memory")

__device__ __forceinline__ uint32_t pack_bf16(float a, float b) {
    __nv_bfloat162 h;
    h.x = __float2bfloat16(a);
    h.y = __float2bfloat16(b);
    return *(uint32_t*)&h;
}

// ===================== scratch =========================================
__device__ fp16  g_wqkvT_h[3 * EMB * EMB],  g_wqkvT_l[3 * EMB * EMB];
__device__ fp16  g_wprojT_h[EMB * EMB],     g_wprojT_l[EMB * EMB];
__device__ fp16  g_wfc1T_h[HIDDEN * EMB],   g_wfc1T_l[HIDDEN * EMB];
__device__ fp16  g_wfc2T_h[EMB * HIDDEN],   g_wfc2T_l[EMB * HIDDEN];
__device__ fp16  g_ln1[TOK * EMB];
__device__ float g_qkv[TOK * 3 * EMB];
__device__ bf16  g_q_h[BH * SEQ * HDIM],    g_q_l[BH * SEQ * HDIM];
__device__ bf16  g_k_h[BH * SEQ * HDIM],    g_k_l[BH * SEQ * HDIM];
__device__ bf16  g_vt_h[BH * HDIM * SEQ],   g_vt_l[BH * HDIM * SEQ];
__device__ fp16  g_am[TOK * EMB];
__device__ float g_x1[TOK * EMB];
__device__ fp16  g_ln2[TOK * EMB];
__device__ fp16  g_h[TOK * HIDDEN];

__device__ __forceinline__ void bf16split(float v, bf16& hi, bf16& lo) {
    hi = __float2bfloat16(v);
    lo = __float2bfloat16(v - __bfloat162float(hi));
}
__device__ __forceinline__ void fp16split(float v, fp16& hi, fp16& lo) {
    hi = __float2half(v);
    lo = __float2half(v - __half2float(hi));
}
__device__ __forceinline__ float gelu_exact(float x) {
    return 0.5f * x * (1.0f + erff(x * 0.70710678118654752440f));
}

// ===================== fp16 2-pass GEMM (cp.async pipelined) ===========
// D[M,N] = alpha*(A @ B^T). A[M,K] fp16 (single); B[N,K] fp16 hi/lo.
// C = A*Bh + A*Bl  (error ~ (A - fp32A)*B ~ 2^-12)
#define EPI_ALPHA    0
#define EPI_BIAS     1
#define EPI_BIAS_RES 2
#define EPI_H        3   // write single fp16
#define EPI_GELU_H   4   // gelu then single fp16

template<int BN, int WM, int WN, int EPI>
__global__ __launch_bounds__(256, 1)
void gemm_mma(const fp16* __restrict__ A,
              const fp16* __restrict__ Bhi, const fp16* __restrict__ Blo,
              const float* __restrict__ bias, const float* __restrict__ resid,
              float* __restrict__ C, fp16* __restrict__ Ch,
              int M, int N, int K, int ldc,
              long long sA, long long sB,
              int hdiv, long long sCb, long long sCh,
              float alpha)
{
    constexpr int BK = 64;                     // fp16 per row = 128 bytes
    constexpr int OFF_BH = 128 * 128;          // A tile = 16 KB
    constexpr int OFF_BL = OFF_BH + BN * 128;
    constexpr int BUFB   = OFF_BL + BN * 128;  // bytes per buffer
    constexpr int WGC = BN / WN;
    constexpr int MT  = WM / 16;
    constexpr int NT  = WN / 8;
    constexpr int NG  = WN / 16;

    extern __shared__ char sm[];
    const uint32_t smb = smem_to_u32(sm);
    const int tid = threadIdx.x, wid = tid >> 5, lane = tid & 31;
    const int bm = blockIdx.y * 128, bn = blockIdx.x * BN, z = blockIdx.z;
    const int wm0 = (wid / WGC) * WM, wn0 = (wid % WGC) * WN;

    A   += (long long)z * sA;
    Bhi += (long long)z * sB;  Blo += (long long)z * sB;
    const long long coff = (long long)(z / hdiv) * sCb + (long long)(z % hdiv) * sCh;

    float acc[MT][NT][4];
#pragma unroll
    for (int i = 0; i < MT; i++)
#pragma unroll
        for (int j = 0; j < NT; j++)
#pragma unroll
            for (int t = 0; t < 4; t++) acc[i][j][t] = 0.0f;

    const int swz   = lane & 7;
    const int aHalf = lane >> 4;
    const int bHalf = (lane >> 3) & 1;
    int aRowOff[MT], bRowOff[NG];
#pragma unroll
    for (int mt = 0; mt < MT; mt++)
        aRowOff[mt] = (wm0 + mt * 16 + (lane & 15)) * 128;
#pragma unroll
    for (int ng = 0; ng < NG; ng++)
        bRowOff[ng] = (wn0 + ng * 16 + (lane & 7) + ((lane >> 4) << 3)) * 128;

    auto stage = [&](int c, uint32_t base) {
        const long long k0 = (long long)c * BK;
        const fp16* a0 = A + (long long)bm * K + k0;
#pragma unroll
        for (int i = tid; i < 128 * 8; i += 256) {
            int r = i >> 3, u = i & 7;
            int sw = SW128(r * 128 + u * 16);
            CP_ASYNC16(smb + base + sw, a0 + (long long)r * K + u * 8);
        }
        const fp16* b0 = Bhi + (long long)bn * K + k0;
        const fp16* b1 = Blo + (long long)bn * K + k0;
#pragma unroll
        for (int i = tid; i < BN * 8; i += 256) {
            int r = i >> 3, u = i & 7;
            int sw = SW128(r * 128 + u * 16);
            CP_ASYNC16(smb + base + OFF_BH + sw, b0 + (long long)r * K + u * 8);
            CP_ASYNC16(smb + base + OFF_BL + sw, b1 + (long long)r * K + u * 8);
        }
        CP_COMMIT();
    };

    const int nch = K / BK;
    stage(0, 0);
    for (int c = 0; c < nch; c++) {
        const uint32_t cur = (c & 1) ? BUFB : 0;
        if (c + 1 < nch) {
            stage(c + 1, (c & 1) ? 0 : BUFB);
            CP_WAIT1();
        } else {
            CP_WAIT0();
        }
        __syncthreads();

#pragma unroll
        for (int ks = 0; ks < BK / 16; ks++) {
            const uint32_t ca = (uint32_t)(((2 * ks + aHalf) ^ swz) * 16);
            const uint32_t cb = (uint32_t)(((2 * ks + bHalf) ^ swz) * 16);
            uint32_t ah[MT][4], bhr[NG][4], blr[NG][4];
#pragma unroll
            for (int mt = 0; mt < MT; mt++)
                ldm_x4(ah[mt], smb + cur + aRowOff[mt] + ca);
#pragma unroll
            for (int ng = 0; ng < NG; ng++) {
                ldm_x4(bhr[ng], smb + cur + OFF_BH + bRowOff[ng] + cb);
                ldm_x4(blr[ng], smb + cur + OFF_BL + bRowOff[ng] + cb);
            }
#pragma unroll
            for (int mt = 0; mt < MT; mt++)
#pragma unroll
                for (int nt = 0; nt < NT; nt++)
                    mma_fp16(acc[mt][nt], ah[mt],
                             bhr[nt >> 1][(nt & 1) * 2], bhr[nt >> 1][(nt & 1) * 2 + 1]);
#pragma unroll
            for (int mt = 0; mt < MT; mt++)
#pragma unroll
                for (int nt = 0; nt < NT; nt++)
                    mma_fp16(acc[mt][nt], ah[mt],
                             blr[nt >> 1][(nt & 1) * 2], blr[nt >> 1][(nt & 1) * 2 + 1]);
        }
        __syncthreads();
    }

#pragma unroll
    for (int mt = 0; mt < MT; mt++) {
#pragma unroll
        for (int half = 0; half < 2; half++) {
            const long long row = bm + wm0 + mt * 16 + (lane >> 2) + half * 8;
#pragma unroll
            for (int nt = 0; nt < NT; nt++) {
                const int col = bn + wn0 + nt * 8 + (lane & 3) * 2;
                float v0 = acc[mt][nt][half * 2 + 0] * alpha;
                float v1 = acc[mt][nt][half * 2 + 1] * alpha;
                if (EPI == EPI_BIAS || EPI == EPI_BIAS_RES || EPI == EPI_GELU_H) {
                    v0 += bias[col]; v1 += bias[col + 1];
                }
                if (EPI == EPI_BIAS_RES) {
                    const float* rp = resid + coff + row * (long long)ldc + col;
                    v0 += rp[0]; v1 += rp[1];
                }
                if (EPI == EPI_GELU_H) {
                    v0 = gelu_exact(v0); v1 = gelu_exact(v1);
                }
                const long long o = coff + row * (long long)ldc + col;
                if (EPI == EPI_ALPHA || EPI == EPI_BIAS || EPI == EPI_BIAS_RES) {
                    float2 w; w.x = v0; w.y = v1;
                    *(float2*)(C + o) = w;
                } else {
                    __half2 hh; hh.x = __float2half(v0); hh.y = __float2half(v1);
                    *(__half2*)(Ch + o) = hh;
                }
            }
        }
    }
}

// ===================== Flash attention v2 (bf16 3-pass, proven) ========
// Grid (SEQ/128, BH), 256 threads. Q tile 128, KV tile 64 double-buffered.
__global__ __launch_bounds__(256, 1)
void flash_kernel(const bf16* __restrict__ Qh, const bf16* __restrict__ Ql,
                  const bf16* __restrict__ Kh, const bf16* __restrict__ Kl,
                  const bf16* __restrict__ Vh, const bf16* __restrict__ Vl,
                  fp16* __restrict__ O)
{
    constexpr int OFF_QL = 16384;
    constexpr int OFF_K  = 32768;
    constexpr int OFF_V  = 65536;
    constexpr int KBUF   = 16384;
    extern __shared__ char sm[];
    const uint32_t smb = smem_to_u32(sm);
    const int tid = threadIdx.x, wid = tid >> 5, lane = tid & 31;
    const int bh = blockIdx.y, q0 = blockIdx.x * 128;
    const long long qkbase = (long long)bh * SEQ * HDIM;
    const long long vbase  = (long long)bh * HDIM * SEQ;
    const int swz = lane & 7;

#pragma unroll
    for (int i = tid; i < 128 * 8; i += 256) {
        int r = i >> 3, u = i & 7;
        int sw = SW128(r * 128 + u * 16);
        CP_ASYNC16(smb + sw,          Qh + qkbase + (long long)(q0 + r) * HDIM + u * 8);
        CP_ASYNC16(smb + OFF_QL + sw, Ql + qkbase + (long long)(q0 + r) * HDIM + u * 8);
    }
    CP_COMMIT();

    auto stage = [&](int t, int buf) {
        const int kv0 = t * 64;
        const uint32_t kb = OFF_K + buf * KBUF, vb = OFF_V + buf * KBUF;
#pragma unroll
        for (int i = tid; i < 64 * 8; i += 256) {
            int r = i >> 3, u = i & 7;
            int sw = SW128(r * 128 + u * 16);
            CP_ASYNC16(smb + kb + sw,        Kh + qkbase + (long long)(kv0 + r) * HDIM + u * 8);
            CP_ASYNC16(smb + kb + 8192 + sw, Kl + qkbase + (long long)(kv0 + r) * HDIM + u * 8);
            CP_ASYNC16(smb + vb + sw,        Vh + vbase + (long long)r * SEQ + kv0 + u * 8);
            CP_ASYNC16(smb + vb + 8192 + sw, Vl + vbase + (long long)r * SEQ + kv0 + u * 8);
        }
        CP_COMMIT();
    };
    stage(0, 0);
    CP_WAIT0();
    __syncthreads();

    uint32_t qfh[4][4], qfl[4][4];
    {
        const int aRowOff = (wid * 16 + (lane & 15)) * 128;
        const int aHalf = lane >> 4;
#pragma unroll
        for (int ks = 0; ks < 4; ks++) {
            const uint32_t ca = (uint32_t)(((2 * ks + aHalf) ^ swz) * 16);
            ldm_x4(qfh[ks], smb + aRowOff + ca);
            ldm_x4(qfl[ks], smb + OFF_QL + aRowOff + ca);
        }
    }

    float Oacc[8][4];
#pragma unroll
    for (int i = 0; i < 8; i++)
#pragma unroll
        for (int t = 0; t < 4; t++) Oacc[i][t] = 0.0f;
    float mrow[2] = {-1e30f, -1e30f};
    float lrow[2] = {0.0f, 0.0f};

    const int kRowOff = (lane & 7) + ((lane >> 4) << 3);
    const int bHalf = (lane >> 3) & 1;

    for (int t = 0; t < SEQ / 64; t++) {
        const int buf = t & 1;
        if (t + 1 < SEQ / 64) { stage(t + 1, buf ^ 1); CP_WAIT1(); }
        else                  { CP_WAIT0(); }
        __syncthreads();
        const uint32_t kb = OFF_K + buf * KBUF, vb = OFF_V + buf * KBUF;

        float S[8][4];
#pragma unroll
        for (int j = 0; j < 8; j++)
#pragma unroll
            for (int c = 0; c < 4; c++) S[j][c] = 0.0f;
#pragma unroll
        for (int g = 0; g < 4; g++) {
            const int bRow = (g * 16 + kRowOff) * 128;
#pragma unroll
            for (int ks = 0; ks < 4; ks++) {
                const uint32_t cb = (uint32_t)(((2 * ks + bHalf) ^ swz) * 16);
                uint32_t kh4[4], kl4[4];
                ldm_x4(kh4, smb + kb + bRow + cb);
                ldm_x4(kl4, smb + kb + 8192 + bRow + cb);
                mma_bf16(S[2 * g],     qfh[ks], kh4[0], kh4[1]);
                mma_bf16(S[2 * g + 1], qfh[ks], kh4[2], kh4[3]);
                mma_bf16(S[2 * g],     qfh[ks], kl4[0], kl4[1]);
                mma_bf16(S[2 * g + 1], qfh[ks], kl4[2], kl4[3]);
                mma_bf16(S[2 * g],     qfl[ks], kh4[0], kh4[1]);
                mma_bf16(S[2 * g + 1], qfl[ks], kh4[2], kh4[3]);
            }
        }

        float mt0 = -1e30f, mt1 = -1e30f;
#pragma unroll
        for (int j = 0; j < 8; j++) {
            mt0 = fmaxf(mt0, fmaxf(S[j][0], S[j][1]));
            mt1 = fmaxf(mt1, fmaxf(S[j][2], S[j][3]));
        }
        mt0 = fmaxf(mt0, __shfl_xor_sync(0xffffffffu, mt0, 1));
        mt0 = fmaxf(mt0, __shfl_xor_sync(0xffffffffu, mt0, 2));
        mt1 = fmaxf(mt1, __shfl_xor_sync(0xffffffffu, mt1, 1));
        mt1 = fmaxf(mt1, __shfl_xor_sync(0xffffffffu, mt1, 2));
        const float mn0 = fmaxf(mrow[0], mt0), mn1 = fmaxf(mrow[1], mt1);
        const float sc0 = __expf(mrow[0] - mn0), sc1 = __expf(mrow[1] - mn1);
        float rs0 = 0.0f, rs1 = 0.0f;
#pragma unroll
        for (int j = 0; j < 8; j++) {
            S[j][0] = __expf(S[j][0] - mn0);
            S[j][1] = __expf(S[j][1] - mn0);
            S[j][2] = __expf(S[j][2] - mn1);
            S[j][3] = __expf(S[j][3] - mn1);
            rs0 += S[j][0] + S[j][1];
            rs1 += S[j][2] + S[j][3];
        }
        rs0 += __shfl_xor_sync(0xffffffffu, rs0, 1);
        rs0 += __shfl_xor_sync(0xffffffffu, rs0, 2);
        rs1 += __shfl_xor_sync(0xffffffffu, rs1, 1);
        rs1 += __shfl_xor_sync(0xffffffffu, rs1, 2);
        lrow[0] = lrow[0] * sc0 + rs0;
        lrow[1] = lrow[1] * sc1 + rs1;
        mrow[0] = mn0; mrow[1] = mn1;
#pragma unroll
        for (int i = 0; i < 8; i++) {
            Oacc[i][0] *= sc0; Oacc[i][1] *= sc0;
            Oacc[i][2] *= sc1; Oacc[i][3] *= sc1;
        }

#pragma unroll
        for (int j = 0; j < 4; j++) {
            float p00 = S[2*j][0],   p01 = S[2*j][1],   p02 = S[2*j][2],   p03 = S[2*j][3];
            float p10 = S[2*j+1][0], p11 = S[2*j+1][1], p12 = S[2*j+1][2], p13 = S[2*j+1][3];
            bf16 h, lo;
            uint32_t ah[4], al[4];
            float t0, t1, u0, u1;
            bf16split(p00, h, lo); t0 = __bfloat162float(h); u0 = __bfloat162float(lo);
            bf16split(p01, h, lo); t1 = __bfloat162float(h); u1 = __bfloat162float(lo);
            ah[0] = pack_bf16(t0, t1); al[0] = pack_bf16(u0, u1);
            bf16split(p02, h, lo); t0 = __bfloat162float(h); u0 = __bfloat162float(lo);
            bf16split(p03, h, lo); t1 = __bfloat162float(h); u1 = __bfloat162float(lo);
            ah[1] = pack_bf16(t0, t1); al[1] = pack_bf16(u0, u1);
            bf16split(p10, h, lo); t0 = __bfloat162float(h); u0 = __bfloat162float(lo);
            bf16split(p11, h, lo); t1 = __bfloat162float(h); u1 = __bfloat162float(lo);
            ah[2] = pack_bf16(t0, t1); al[2] = pack_bf16(u0, u1);
            bf16split(p12, h, lo); t0 = __bfloat162float(h); u0 = __bfloat162float(lo);
            bf16split(p13, h, lo); t1 = __bfloat162float(h); u1 = __bfloat162float(lo);
            ah[3] = pack_bf16(t0, t1); al[3] = pack_bf16(u0, u1);

            const uint32_t cv = (uint32_t)(((2 * j + bHalf) ^ swz) * 16);
#pragma unroll
            for (int vg = 0; vg < 4; vg++) {
                const int vRow = (vg * 16 + kRowOff) * 128;
                uint32_t vh4[4], vl4[4];
                ldm_x4(vh4, smb + vb + vRow + cv);
                ldm_x4(vl4, smb + vb + 8192 + vRow + cv);
                mma_bf16(Oacc[2 * vg],     ah, vh4[0], vh4[1]);
                mma_bf16(Oacc[2 * vg + 1], ah, vh4[2], vh4[3]);
                mma_bf16(Oacc[2 * vg],     ah, vl4[0], vl4[1]);
                mma_bf16(Oacc[2 * vg + 1], ah, vl4[2], vl4[3]);
                mma_bf16(Oacc[2 * vg],     al, vh4[0], vh4[1]);
                mma_bf16(Oacc[2 * vg + 1], al, vh4[2], vh4[3]);
            }
        }
        __syncthreads();
    }

    // epilogue: merged-head single fp16
    const float inv0 = 1.0f / lrow[0], inv1 = 1.0f / lrow[1];
    const int b = bh / NHEAD, hh = bh % NHEAD;
    const long long tok0 = (long long)b * SEQ + q0 + wid * 16 + (lane >> 2);
    const int col0 = hh * HDIM + (lane & 3) * 2;
#pragma unroll
    for (int vt = 0; vt < 8; vt++) {
        float v0 = Oacc[vt][0] * inv0, v1 = Oacc[vt][1] * inv0;
        float v2 = Oacc[vt][2] * inv1, v3 = Oacc[vt][3] * inv1;
        long long o = tok0 * EMB + col0 + vt * 8;
        { __half2 x; x.x = __float2half(v0); x.y = __float2half(v1); *(__half2*)(O + o) = x; }
        long long o2 = (tok0 + 8) * EMB + col0 + vt * 8;
        { __half2 x; x.x = __float2half(v2); x.y = __float2half(v3); *(__half2*)(O + o2) = x; }
    }
}

// ===================== LayerNorm -> fp16 ===============================
__global__ __launch_bounds__(256)
void layernorm_fp16_kernel(const float* __restrict__ x, const float* __restrict__ gamma,
                           const float* __restrict__ beta, fp16* __restrict__ o)
{
    long long row = blockIdx.x;
    const float4* xr = (const float4*)(x + row * EMB);
    float4 v = xr[threadIdx.x];
    float s  = v.x + v.y + v.z + v.w;
    float ss = v.x * v.x + v.y * v.y + v.z * v.z + v.w * v.w;
#pragma unroll
    for (int of = 16; of; of >>= 1) {
        s  += __shfl_xor_sync(0xffffffffu, s,  of);
        ss += __shfl_xor_sync(0xffffffffu, ss, of);
    }
    __shared__ float sh_s[8], sh_ss[8];
    int w = threadIdx.x >> 5, l = threadIdx.x & 31;
    if (l == 0) { sh_s[w] = s; sh_ss[w] = ss; }
    __syncthreads();
    s = 0.f; ss = 0.f;
#pragma unroll
    for (int i = 0; i < 8; i++) { s += sh_s[i]; ss += sh_ss[i]; }
    float mu   = s * (1.0f / EMB);
    float var  = ss * (1.0f / EMB) - mu * mu;
    float rstd = rsqrtf(var + 1e-6f);
    float4 gv = ((const float4*)gamma)[threadIdx.x];
    float4 bv = ((const float4*)beta)[threadIdx.x];
    float o0 = (v.x - mu) * rstd * gv.x + bv.x;
    float o1 = (v.y - mu) * rstd * gv.y + bv.y;
    float o2 = (v.z - mu) * rstd * gv.z + bv.z;
    float o3 = (v.w - mu) * rstd * gv.w + bv.w;
    long long base = row * EMB + threadIdx.x * 4;
    __half2 a; a.x = __float2half(o0); a.y = __float2half(o1);
    __half2 b; b.x = __float2half(o2); b.y = __float2half(o3);
    *(__half2*)(o + base)     = a;
    *(__half2*)(o + base + 2) = b;
}

// ============ transpose-convert: fp32 [R,C] -> [C,R] fp16 hi/lo ========
__global__ __launch_bounds__(256)
void wt_prep_kernel(const float* __restrict__ src, int R, int C,
                    fp16* __restrict__ dh, fp16* __restrict__ dl)
{
    __shared__ float t[32][33];
    int c0 = blockIdx.x * 32, r0 = blockIdx.y * 32;
    int tx = threadIdx.x & 31, ty = threadIdx.x >> 5;
#pragma unroll
    for (int i = ty; i < 32; i += 8)
        t[i][tx] = src[(long long)(r0 + i) * C + c0 + tx];
    __syncthreads();
#pragma unroll
    for (int i = ty; i < 32; i += 8) {
        float v = t[tx][i];
        fp16 h, l; fp16split(v, h, l);
        long long o = (long long)(c0 + i) * R + r0 + tx;
        dh[o] = h; dl[o] = l;
    }
}

// ============ V^T prep: qkv -> vt hi/lo bf16 [BH, 64, 2048] ============
__global__ __launch_bounds__(256)
void vt_prep_kernel(const float* __restrict__ qkv, bf16* __restrict__ dh, bf16* __restrict__ dl)
{
    __shared__ float t[32][33];
    int bh = blockIdx.z, b = bh / NHEAD, h = bh % NHEAD;
    int n0 = blockIdx.x * 32, d0 = blockIdx.y * 32;
    int tx = threadIdx.x & 31, ty = threadIdx.x >> 5;
#pragma unroll
    for (int i = ty; i < 32; i += 8)
        t[i][tx] = qkv[((long long)(b * SEQ + n0 + i)) * (3 * EMB) + 2 * EMB + h * HDIM + d0 + tx];
    __syncthreads();
#pragma unroll
    for (int i = ty; i < 32; i += 8) {
        float v = t[tx][i];
        bf16 hh, ll; bf16split(v, hh, ll);
        long long o = ((long long)bh * HDIM + d0 + i) * SEQ + n0 + tx;
        dh[o] = hh; dl[o] = ll;
    }
}

// ============ Q/K prep: qkv -> q (x0.125), k bf16 hi/lo ================
__global__ __launch_bounds__(256)
void qk_prep_kernel(const float* __restrict__ qkv,
                    bf16* __restrict__ qh, bf16* __restrict__ ql,
                    bf16* __restrict__ kh, bf16* __restrict__ kl)
{
    long long idx4 = (long long)blockIdx.x * 256 + threadIdx.x;
    long long e  = idx4 * 4;
    long long bn = e / EMB;
    int c  = (int)(e % EMB);
    long long b  = bn / SEQ, n = bn % SEQ;
    int h = c / HDIM, d = c % HDIM;
    long long src = bn * (3 * EMB) + (long long)h * HDIM + d;
    long long dst = ((b * NHEAD + h) * SEQ + n) * HDIM + d;
    float4 q4 = *(const float4*)(qkv + src);
    float4 k4 = *(const float4*)(qkv + src + EMB);
    q4.x *= 0.125f; q4.y *= 0.125f; q4.z *= 0.125f; q4.w *= 0.125f;
    bf16 h0,l0,h1,l1,h2,l2,h3,l3;
    bf16split(q4.x,h0,l0); bf16split(q4.y,h1,l1); bf16split(q4.z,h2,l2); bf16split(q4.w,h3,l3);
    { __nv_bfloat162 a; a.x=h0; a.y=h1; __nv_bfloat162 bb; bb.x=h2; bb.y=h3;
      __nv_bfloat162 cc; cc.x=l0; cc.y=l1; __nv_bfloat162 dd; dd.x=l2; dd.y=l3;
      *(__nv_bfloat162*)(qh+dst)=a; *(__nv_bfloat162*)(qh+dst+2)=bb;
      *(__nv_bfloat162*)(ql+dst)=cc; *(__nv_bfloat162*)(ql+dst+2)=dd; }
    bf16split(k4.x,h0,l0); bf16split(k4.y,h1,l1); bf16split(k4.z,h2,l2); bf16split(k4.w,h3,l3);
    { __nv_bfloat162 a; a.x=h0; a.y=h1; __nv_bfloat162 bb; bb.x=h2; bb.y=h3;
      __nv_bfloat162 cc; cc.x=l0; cc.y=l1; __nv_bfloat162 dd; dd.x=l2; dd.y=l3;
      *(__nv_bfloat162*)(kh+dst)=a; *(__nv_bfloat162*)(kh+dst+2)=bb;
      *(__nv_bfloat162*)(kl+dst)=cc; *(__nv_bfloat162*)(kl+dst+2)=dd; }
}

// ===================== host side =======================================
template<int BN, int WM, int WN, int EPI>
static void launch_gemm(const fp16* A, const fp16* Bhi, const fp16* Blo,
                        const float* bias, const float* resid,
                        float* C, fp16* Ch,
                        int M, int N, int K, int ldc,
                        long long sA, long long sB,
                        int batch, int hdiv, long long sCb, long long sCh,
                        float alpha)
{
    constexpr int SMEM_BYTES = 2 * (128 * 128 + 2 * BN * 128);
    cudaFuncSetAttribute(gemm_mma<BN, WM, WN, EPI>,
                         cudaFuncAttributeMaxDynamicSharedMemorySize, SMEM_BYTES);
    dim3 grid(N / BN, M / 128, batch);
    gemm_mma<BN, WM, WN, EPI><<<grid, 256, SMEM_BYTES>>>(
        A, Bhi, Blo, bias, resid, C, Ch,
        M, N, K, ldc, sA, sB, hdiv, sCb, sCh, alpha);
}

extern "C" void kernel_launch(void* const* d_in, const int* in_sizes, int n_in,
                              void* d_out, int out_size)
{
    const float* x      = (const float*)d_in[0];
    const float* ln1_g  = (const float*)d_in[1];
    const float* ln1_b  = (const float*)d_in[2];
    const float* w_qkv  = (const float*)d_in[3];
    const float* b_qkv  = (const float*)d_in[4];
    const float* w_proj = (const float*)d_in[5];
    const float* b_proj = (const float*)d_in[6];
    const float* ln2_g  = (const float*)d_in[7];
    const float* ln2_b  = (const float*)d_in[8];
    const float* w_fc1  = (const float*)d_in[9];
    const float* b_fc1  = (const float*)d_in[10];
    const float* w_fc2  = (const float*)d_in[11];
    const float* b_fc2  = (const float*)d_in[12];
    float* out = (float*)d_out;

    fp16 *wqkvTh, *wqkvTl, *wprojTh, *wprojTl, *wfc1Th, *wfc1Tl, *wfc2Th, *wfc2Tl;
    fp16 *ln1, *am, *ln2, *hb;
    bf16 *qh, *ql, *kh, *kl, *vth, *vtl;
    float *qkv, *x1;
    cudaGetSymbolAddress((void**)&wqkvTh, g_wqkvT_h);  cudaGetSymbolAddress((void**)&wqkvTl, g_wqkvT_l);
    cudaGetSymbolAddress((void**)&wprojTh, g_wprojT_h); cudaGetSymbolAddress((void**)&wprojTl, g_wprojT_l);
    cudaGetSymbolAddress((void**)&wfc1Th, g_wfc1T_h);  cudaGetSymbolAddress((void**)&wfc1Tl, g_wfc1T_l);
    cudaGetSymbolAddress((void**)&wfc2Th, g_wfc2T_h);  cudaGetSymbolAddress((void**)&wfc2Tl, g_wfc2T_l);
    cudaGetSymbolAddress((void**)&ln1, g_ln1);
    cudaGetSymbolAddress((void**)&qkv, g_qkv);
    cudaGetSymbolAddress((void**)&qh, g_q_h);          cudaGetSymbolAddress((void**)&ql, g_q_l);
    cudaGetSymbolAddress((void**)&kh, g_k_h);          cudaGetSymbolAddress((void**)&kl, g_k_l);
    cudaGetSymbolAddress((void**)&vth, g_vt_h);        cudaGetSymbolAddress((void**)&vtl, g_vt_l);
    cudaGetSymbolAddress((void**)&am, g_am);
    cudaGetSymbolAddress((void**)&x1, g_x1);
    cudaGetSymbolAddress((void**)&ln2, g_ln2);
    cudaGetSymbolAddress((void**)&hb, g_h);

    // 0) weight transpose-converts  W[K,N] -> Wt[N,K] fp16 hi/lo
    wt_prep_kernel<<<dim3(3 * EMB / 32, EMB / 32), 256>>>(w_qkv, EMB, 3 * EMB, wqkvTh, wqkvTl);
    wt_prep_kernel<<<dim3(EMB / 32, EMB / 32), 256>>>(w_proj, EMB, EMB, wprojTh, wprojTl);
    wt_prep_kernel<<<dim3(HIDDEN / 32, EMB / 32), 256>>>(w_fc1, EMB, HIDDEN, wfc1Th, wfc1Tl);
    wt_prep_kernel<<<dim3(EMB / 32, HIDDEN / 32), 256>>>(w_fc2, HIDDEN, EMB, wfc2Th, wfc2Tl);

    // 1) LN1 -> fp16
    layernorm_fp16_kernel<<<TOK, 256>>>(x, ln1_g, ln1_b, ln1);

    // 2) QKV: [4096,3072] = ln1 @ w_qkv + b  (fp32 out)
    launch_gemm<128, 64, 32, EPI_BIAS>(ln1, wqkvTh, wqkvTl, b_qkv, nullptr,
                                       qkv, nullptr,
                                       TOK, 3 * EMB, EMB, 3 * EMB, 0, 0, 1, 1, 0, 0, 1.0f);

    // 3) Q/K gather (+0.125 on Q) + V transpose, split to bf16
    qk_prep_kernel<<<(TOK * EMB / 4) / 256, 256>>>(qkv, qh, ql, kh, kl);
    vt_prep_kernel<<<dim3(SEQ / 32, HDIM / 32, BH), 256>>>(qkv, vth, vtl);

    // 4) fused flash attention -> merged heads fp16
    {
        constexpr int FSMEM = 96 * 1024;
        cudaFuncSetAttribute(flash_kernel,
                             cudaFuncAttributeMaxDynamicSharedMemorySize, FSMEM);
        dim3 grid(SEQ / 128, BH);
        flash_kernel<<<grid, 256, FSMEM>>>(qh, ql, kh, kl, vth, vtl, am);
    }

    // 5) proj + residual: x1 = am @ w_proj + b + x
    launch_gemm<128, 64, 32, EPI_BIAS_RES>(am, wprojTh, wprojTl, b_proj, x,
                                           x1, nullptr,
                                           TOK, EMB, EMB, EMB, 0, 0, 1, 1, 0, 0, 1.0f);

    // 6) LN2 -> fp16
    layernorm_fp16_kernel<<<TOK, 256>>>(x1, ln2_g, ln2_b, ln2);

    // 7) FC1 + GELU -> h fp16
    launch_gemm<128, 64, 32, EPI_GELU_H>(ln2, wfc1Th, wfc1Tl, b_fc1, nullptr,
                                         nullptr, hb,
                                         TOK, HIDDEN, EMB, HIDDEN, 0, 0, 1, 1, 0, 0, 1.0f);

    // 8) FC2 + bias + residual -> out
    launch_gemm<128, 64, 32, EPI_BIAS_RES>(hb, wfc2Th, wfc2Tl, b_fc2, x1,
                                           out, nullptr,
                                           TOK, EMB, HIDDEN, EMB, 0, 0, 1, 1, 0, 0, 1.0f);
}

// round 12
// speedup vs baseline: 2.6039x; 1.1002x over previous
#include <cuda_runtime.h>
#include <cuda_fp16.h>
#include <math.h>
#include <stdint.h>

// Problem constants
#define Bz     2
#define SEQ    2048
#define EMB    1024
#define NHEAD  16
#define HDIM   64
#define HIDDEN 4096
#define TOK    (Bz * SEQ)          // 4096 rows
#define BH     (Bz * NHEAD)        // 32 batched heads

typedef __half fp16;

// ===================== MMA / async primitives (non-'a' PTX) ============
__device__ __forceinline__ void ldm_x4(uint32_t* r, uint32_t addr) {
    asm volatile("ldmatrix.sync.aligned.m8n8.x4.shared.b16 {%0,%1,%2,%3}, [%4];"
        : "=r"(r[0]), "=r"(r[1]), "=r"(r[2]), "=r"(r[3]) : "r"(addr));
}
__device__ __forceinline__ void mma_fp16(float* c, const uint32_t* a,
                                         uint32_t b0, uint32_t b1) {
    asm volatile(
        "mma.sync.aligned.m16n8k16.row.col.f32.f16.f16.f32 "
        "{%0,%1,%2,%3}, {%4,%5,%6,%7}, {%8,%9}, {%0,%1,%2,%3};"
        : "+f"(c[0]), "+f"(c[1]), "+f"(c[2]), "+f"(c[3])
        : "r"(a[0]), "r"(a[1]), "r"(a[2]), "r"(a[3]), "r"(b0), "r"(b1));
}
__device__ __forceinline__ uint32_t smem_to_u32(const void* p) {
    uint32_t a;
    asm("{ .reg .u64 t; cvta.to.shared.u64 t, %1; cvt.u32.u64 %0, t; }" : "=r"(a) : "l"(p));
    return a;
}
#define SW128(off) ((off) ^ (((off) >> 3) & 0x70))

#define CP_ASYNC16(saddr, gptr) \
    asm volatile("cp.async.cg.shared.global [%0], [%1], 16;" \
        :: "r"((uint32_t)(saddr)), "l"(gptr))
#define CP_COMMIT() asm volatile("cp.async.commit_group;" ::: "memory")
#define CP_WAIT1()  asm volatile("cp.async.wait_group 1;" ::: "memory")
#define CP_WAIT0()  asm volatile("cp.async.wait_group 0;" ::: "memory")

__device__ __forceinline__ uint32_t pack_fp16(float a, float b) {
    __half2 h;
    h.x = __float2half(a);
    h.y = __float2half(b);
    return *(uint32_t*)&h;
}

// ===================== scratch =========================================
__device__ fp16  g_wqkvT_h[3 * EMB * EMB],  g_wqkvT_l[3 * EMB * EMB];
__device__ fp16  g_wprojT_h[EMB * EMB],     g_wprojT_l[EMB * EMB];
__device__ fp16  g_wfc1T_h[HIDDEN * EMB],   g_wfc1T_l[HIDDEN * EMB];
__device__ fp16  g_wfc2T_h[EMB * HIDDEN],   g_wfc2T_l[EMB * HIDDEN];
__device__ fp16  g_ln1[TOK * EMB];
__device__ fp16  g_q[BH * SEQ * HDIM];                 // scaled, single
__device__ fp16  g_k_h[BH * SEQ * HDIM],    g_k_l[BH * SEQ * HDIM];
__device__ float g_v[TOK * EMB];                       // (b,n,h*64+d) fp32
__device__ fp16  g_vt_h[BH * HDIM * SEQ],   g_vt_l[BH * HDIM * SEQ];
__device__ fp16  g_am[TOK * EMB];
__device__ float g_x1[TOK * EMB];
__device__ fp16  g_ln2[TOK * EMB];
__device__ fp16  g_h[TOK * HIDDEN];

__device__ __forceinline__ void fp16split(float v, fp16& hi, fp16& lo) {
    hi = __float2half(v);
    lo = __float2half(v - __half2float(hi));
}
__device__ __forceinline__ float gelu_exact(float x) {
    return 0.5f * x * (1.0f + erff(x * 0.70710678118654752440f));
}

// ===================== fp16 2-pass GEMM (cp.async pipelined) ===========
// D[M,N] = alpha*(A @ B^T). A[M,K] fp16 single; B[N,K] fp16 hi/lo.
#define EPI_ALPHA    0
#define EPI_BIAS     1
#define EPI_BIAS_RES 2
#define EPI_H        3
#define EPI_GELU_H   4
#define EPI_QKV      5   // fused q/k/v extraction (bias included)

template<int BN, int WM, int WN, int EPI>
__global__ __launch_bounds__(256, 1)
void gemm_mma(const fp16* __restrict__ A,
              const fp16* __restrict__ Bhi, const fp16* __restrict__ Blo,
              const float* __restrict__ bias, const float* __restrict__ resid,
              float* __restrict__ C, fp16* __restrict__ Ch,
              fp16* __restrict__ Qo, fp16* __restrict__ Kho,
              fp16* __restrict__ Klo, float* __restrict__ Vo,
              int M, int N, int K, int ldc,
              long long sA, long long sB,
              int hdiv, long long sCb, long long sCh,
              float alpha)
{
    constexpr int BK = 64;
    constexpr int OFF_BH = 128 * 128;
    constexpr int OFF_BL = OFF_BH + BN * 128;
    constexpr int BUFB   = OFF_BL + BN * 128;
    constexpr int WGC = BN / WN;
    constexpr int MT  = WM / 16;
    constexpr int NT  = WN / 8;
    constexpr int NG  = WN / 16;

    extern __shared__ char sm[];
    const uint32_t smb = smem_to_u32(sm);
    const int tid = threadIdx.x, wid = tid >> 5, lane = tid & 31;
    const int bm = blockIdx.y * 128, bn = blockIdx.x * BN, z = blockIdx.z;
    const int wm0 = (wid / WGC) * WM, wn0 = (wid % WGC) * WN;

    A   += (long long)z * sA;
    Bhi += (long long)z * sB;  Blo += (long long)z * sB;
    const long long coff = (long long)(z / hdiv) * sCb + (long long)(z % hdiv) * sCh;

    float acc[MT][NT][4];
#pragma unroll
    for (int i = 0; i < MT; i++)
#pragma unroll
        for (int j = 0; j < NT; j++)
#pragma unroll
            for (int t = 0; t < 4; t++) acc[i][j][t] = 0.0f;

    const int swz   = lane & 7;
    const int aHalf = lane >> 4;
    const int bHalf = (lane >> 3) & 1;
    int aRowOff[MT], bRowOff[NG];
#pragma unroll
    for (int mt = 0; mt < MT; mt++)
        aRowOff[mt] = (wm0 + mt * 16 + (lane & 15)) * 128;
#pragma unroll
    for (int ng = 0; ng < NG; ng++)
        bRowOff[ng] = (wn0 + ng * 16 + (lane & 7) + ((lane >> 4) << 3)) * 128;

    auto stage = [&](int c, uint32_t base) {
        const long long k0 = (long long)c * BK;
        const fp16* a0 = A + (long long)bm * K + k0;
#pragma unroll
        for (int i = tid; i < 128 * 8; i += 256) {
            int r = i >> 3, u = i & 7;
            int sw = SW128(r * 128 + u * 16);
            CP_ASYNC16(smb + base + sw, a0 + (long long)r * K + u * 8);
        }
        const fp16* b0 = Bhi + (long long)bn * K + k0;
        const fp16* b1 = Blo + (long long)bn * K + k0;
#pragma unroll
        for (int i = tid; i < BN * 8; i += 256) {
            int r = i >> 3, u = i & 7;
            int sw = SW128(r * 128 + u * 16);
            CP_ASYNC16(smb + base + OFF_BH + sw, b0 + (long long)r * K + u * 8);
            CP_ASYNC16(smb + base + OFF_BL + sw, b1 + (long long)r * K + u * 8);
        }
        CP_COMMIT();
    };

    const int nch = K / BK;
    stage(0, 0);
    for (int c = 0; c < nch; c++) {
        const uint32_t cur = (c & 1) ? BUFB : 0;
        if (c + 1 < nch) {
            stage(c + 1, (c & 1) ? 0 : BUFB);
            CP_WAIT1();
        } else {
            CP_WAIT0();
        }
        __syncthreads();

#pragma unroll
        for (int ks = 0; ks < BK / 16; ks++) {
            const uint32_t ca = (uint32_t)(((2 * ks + aHalf) ^ swz) * 16);
            const uint32_t cb = (uint32_t)(((2 * ks + bHalf) ^ swz) * 16);
            uint32_t ah[MT][4], bhr[NG][4], blr[NG][4];
#pragma unroll
            for (int mt = 0; mt < MT; mt++)
                ldm_x4(ah[mt], smb + cur + aRowOff[mt] + ca);
#pragma unroll
            for (int ng = 0; ng < NG; ng++) {
                ldm_x4(bhr[ng], smb + cur + OFF_BH + bRowOff[ng] + cb);
                ldm_x4(blr[ng], smb + cur + OFF_BL + bRowOff[ng] + cb);
            }
#pragma unroll
            for (int mt = 0; mt < MT; mt++)
#pragma unroll
                for (int nt = 0; nt < NT; nt++)
                    mma_fp16(acc[mt][nt], ah[mt],
                             bhr[nt >> 1][(nt & 1) * 2], bhr[nt >> 1][(nt & 1) * 2 + 1]);
#pragma unroll
            for (int mt = 0; mt < MT; mt++)
#pragma unroll
                for (int nt = 0; nt < NT; nt++)
                    mma_fp16(acc[mt][nt], ah[mt],
                             blr[nt >> 1][(nt & 1) * 2], blr[nt >> 1][(nt & 1) * 2 + 1]);
        }
        __syncthreads();
    }

#pragma unroll
    for (int mt = 0; mt < MT; mt++) {
#pragma unroll
        for (int half = 0; half < 2; half++) {
            const long long row = bm + wm0 + mt * 16 + (lane >> 2) + half * 8;
#pragma unroll
            for (int nt = 0; nt < NT; nt++) {
                const int col = bn + wn0 + nt * 8 + (lane & 3) * 2;
                float v0 = acc[mt][nt][half * 2 + 0] * alpha;
                float v1 = acc[mt][nt][half * 2 + 1] * alpha;
                if (EPI == EPI_BIAS || EPI == EPI_BIAS_RES || EPI == EPI_GELU_H || EPI == EPI_QKV) {
                    v0 += bias[col]; v1 += bias[col + 1];
                }
                if (EPI == EPI_BIAS_RES) {
                    const float* rp = resid + coff + row * (long long)ldc + col;
                    v0 += rp[0]; v1 += rp[1];
                }
                if (EPI == EPI_GELU_H) {
                    v0 = gelu_exact(v0); v1 = gelu_exact(v1);
                }
                if (EPI == EPI_QKV) {
                    const int region = col >> 10;       // 0=Q 1=K 2=V (warp-uniform)
                    const int cc = col & 1023;
                    const int h = cc >> 6, d = cc & 63;
                    const long long b = row >> 11, n = row & 2047;
                    if (region == 2) {
                        float2 w; w.x = v0; w.y = v1;
                        *(float2*)(Vo + row * EMB + cc) = w;
                    } else {
                        const long long dst = ((b * NHEAD + h) * SEQ + n) * HDIM + d;
                        if (region == 0) {
                            __half2 x; x.x = __float2half(v0 * 0.125f);
                            x.y = __float2half(v1 * 0.125f);
                            *(__half2*)(Qo + dst) = x;
                        } else {
                            fp16 h0, l0, h1, l1;
                            fp16split(v0, h0, l0); fp16split(v1, h1, l1);
                            __half2 xh; xh.x = h0; xh.y = h1;
                            __half2 xl; xl.x = l0; xl.y = l1;
                            *(__half2*)(Kho + dst) = xh;
                            *(__half2*)(Klo + dst) = xl;
                        }
                    }
                } else {
                    const long long o = coff + row * (long long)ldc + col;
                    if (EPI == EPI_ALPHA || EPI == EPI_BIAS || EPI == EPI_BIAS_RES) {
                        float2 w; w.x = v0; w.y = v1;
                        *(float2*)(C + o) = w;
                    } else {
                        __half2 hh; hh.x = __float2half(v0); hh.y = __float2half(v1);
                        *(__half2*)(Ch + o) = hh;
                    }
                }
            }
        }
    }
}

// ===================== Flash attention v3 (fp16 2-pass) ================
// Grid (SEQ/128, BH), 256 threads. Q tile 128 (single fp16), KV tile 64
// double-buffered. S = Qf*Kh + Qf*Kl; O += Ph*Vh + Ph*Vl.
__global__ __launch_bounds__(256, 1)
void flash_kernel(const fp16* __restrict__ Qf,
                  const fp16* __restrict__ Kh, const fp16* __restrict__ Kl,
                  const fp16* __restrict__ Vh, const fp16* __restrict__ Vl,
                  fp16* __restrict__ O)
{
    constexpr int OFF_K = 16384;       // Q tile 16 KB
    constexpr int OFF_V = 49152;       // after 2 K bufs
    constexpr int KBUF  = 16384;       // hi 8K + lo 8K
    extern __shared__ char sm[];
    const uint32_t smb = smem_to_u32(sm);
    const int tid = threadIdx.x, wid = tid >> 5, lane = tid & 31;
    const int bh = blockIdx.y, q0 = blockIdx.x * 128;
    const long long qkbase = (long long)bh * SEQ * HDIM;
    const long long vbase  = (long long)bh * HDIM * SEQ;
    const int swz = lane & 7;

#pragma unroll
    for (int i = tid; i < 128 * 8; i += 256) {
        int r = i >> 3, u = i & 7;
        int sw = SW128(r * 128 + u * 16);
        CP_ASYNC16(smb + sw, Qf + qkbase + (long long)(q0 + r) * HDIM + u * 8);
    }
    CP_COMMIT();

    auto stage = [&](int t, int buf) {
        const int kv0 = t * 64;
        const uint32_t kb = OFF_K + buf * KBUF, vb = OFF_V + buf * KBUF;
#pragma unroll
        for (int i = tid; i < 64 * 8; i += 256) {
            int r = i >> 3, u = i & 7;
            int sw = SW128(r * 128 + u * 16);
            CP_ASYNC16(smb + kb + sw,        Kh + qkbase + (long long)(kv0 + r) * HDIM + u * 8);
            CP_ASYNC16(smb + kb + 8192 + sw, Kl + qkbase + (long long)(kv0 + r) * HDIM + u * 8);
            CP_ASYNC16(smb + vb + sw,        Vh + vbase + (long long)r * SEQ + kv0 + u * 8);
            CP_ASYNC16(smb + vb + 8192 + sw, Vl + vbase + (long long)r * SEQ + kv0 + u * 8);
        }
        CP_COMMIT();
    };
    stage(0, 0);
    CP_WAIT0();
    __syncthreads();

    uint32_t qf[4][4];
    {
        const int aRowOff = (wid * 16 + (lane & 15)) * 128;
        const int aHalf = lane >> 4;
#pragma unroll
        for (int ks = 0; ks < 4; ks++) {
            const uint32_t ca = (uint32_t)(((2 * ks + aHalf) ^ swz) * 16);
            ldm_x4(qf[ks], smb + aRowOff + ca);
        }
    }

    float Oacc[8][4];
#pragma unroll
    for (int i = 0; i < 8; i++)
#pragma unroll
        for (int t = 0; t < 4; t++) Oacc[i][t] = 0.0f;
    float mrow[2] = {-1e30f, -1e30f};
    float lrow[2] = {0.0f, 0.0f};

    const int kRowOff = (lane & 7) + ((lane >> 4) << 3);
    const int bHalf = (lane >> 3) & 1;

    for (int t = 0; t < SEQ / 64; t++) {
        const int buf = t & 1;
        if (t + 1 < SEQ / 64) { stage(t + 1, buf ^ 1); CP_WAIT1(); }
        else                  { CP_WAIT0(); }
        __syncthreads();
        const uint32_t kb = OFF_K + buf * KBUF, vb = OFF_V + buf * KBUF;

        // ---- S = Qf K^T (2-pass) ----
        float S[8][4];
#pragma unroll
        for (int j = 0; j < 8; j++)
#pragma unroll
            for (int c = 0; c < 4; c++) S[j][c] = 0.0f;
#pragma unroll
        for (int g = 0; g < 4; g++) {
            const int bRow = (g * 16 + kRowOff) * 128;
#pragma unroll
            for (int ks = 0; ks < 4; ks++) {
                const uint32_t cb = (uint32_t)(((2 * ks + bHalf) ^ swz) * 16);
                uint32_t kh4[4], kl4[4];
                ldm_x4(kh4, smb + kb + bRow + cb);
                ldm_x4(kl4, smb + kb + 8192 + bRow + cb);
                mma_fp16(S[2 * g],     qf[ks], kh4[0], kh4[1]);
                mma_fp16(S[2 * g + 1], qf[ks], kh4[2], kh4[3]);
                mma_fp16(S[2 * g],     qf[ks], kl4[0], kl4[1]);
                mma_fp16(S[2 * g + 1], qf[ks], kl4[2], kl4[3]);
            }
        }

        // ---- online softmax ----
        float mt0 = -1e30f, mt1 = -1e30f;
#pragma unroll
        for (int j = 0; j < 8; j++) {
            mt0 = fmaxf(mt0, fmaxf(S[j][0], S[j][1]));
            mt1 = fmaxf(mt1, fmaxf(S[j][2], S[j][3]));
        }
        mt0 = fmaxf(mt0, __shfl_xor_sync(0xffffffffu, mt0, 1));
        mt0 = fmaxf(mt0, __shfl_xor_sync(0xffffffffu, mt0, 2));
        mt1 = fmaxf(mt1, __shfl_xor_sync(0xffffffffu, mt1, 1));
        mt1 = fmaxf(mt1, __shfl_xor_sync(0xffffffffu, mt1, 2));
        const float mn0 = fmaxf(mrow[0], mt0), mn1 = fmaxf(mrow[1], mt1);
        const float sc0 = __expf(mrow[0] - mn0), sc1 = __expf(mrow[1] - mn1);
        float rs0 = 0.0f, rs1 = 0.0f;
#pragma unroll
        for (int j = 0; j < 8; j++) {
            S[j][0] = __expf(S[j][0] - mn0);
            S[j][1] = __expf(S[j][1] - mn0);
            S[j][2] = __expf(S[j][2] - mn1);
            S[j][3] = __expf(S[j][3] - mn1);
            rs0 += S[j][0] + S[j][1];
            rs1 += S[j][2] + S[j][3];
        }
        rs0 += __shfl_xor_sync(0xffffffffu, rs0, 1);
        rs0 += __shfl_xor_sync(0xffffffffu, rs0, 2);
        rs1 += __shfl_xor_sync(0xffffffffu, rs1, 1);
        rs1 += __shfl_xor_sync(0xffffffffu, rs1, 2);
        lrow[0] = lrow[0] * sc0 + rs0;
        lrow[1] = lrow[1] * sc1 + rs1;
        mrow[0] = mn0; mrow[1] = mn1;
#pragma unroll
        for (int i = 0; i < 8; i++) {
            Oacc[i][0] *= sc0; Oacc[i][1] *= sc0;
            Oacc[i][2] *= sc1; Oacc[i][3] *= sc1;
        }

        // ---- O += P V (2-pass, P single fp16) ----
#pragma unroll
        for (int j = 0; j < 4; j++) {
            uint32_t ah[4];
            ah[0] = pack_fp16(S[2*j][0],   S[2*j][1]);
            ah[1] = pack_fp16(S[2*j][2],   S[2*j][3]);
            ah[2] = pack_fp16(S[2*j+1][0], S[2*j+1][1]);
            ah[3] = pack_fp16(S[2*j+1][2], S[2*j+1][3]);

            const uint32_t cv = (uint32_t)(((2 * j + bHalf) ^ swz) * 16);
#pragma unroll
            for (int vg = 0; vg < 4; vg++) {
                const int vRow = (vg * 16 + kRowOff) * 128;
                uint32_t vh4[4], vl4[4];
                ldm_x4(vh4, smb + vb + vRow + cv);
                ldm_x4(vl4, smb + vb + 8192 + vRow + cv);
                mma_fp16(Oacc[2 * vg],     ah, vh4[0], vh4[1]);
                mma_fp16(Oacc[2 * vg + 1], ah, vh4[2], vh4[3]);
                mma_fp16(Oacc[2 * vg],     ah, vl4[0], vl4[1]);
                mma_fp16(Oacc[2 * vg + 1], ah, vl4[2], vl4[3]);
            }
        }
        __syncthreads();
    }

    // epilogue: merged-head single fp16
    const float inv0 = 1.0f / lrow[0], inv1 = 1.0f / lrow[1];
    const int b = bh / NHEAD, hh = bh % NHEAD;
    const long long tok0 = (long long)b * SEQ + q0 + wid * 16 + (lane >> 2);
    const int col0 = hh * HDIM + (lane & 3) * 2;
#pragma unroll
    for (int vt = 0; vt < 8; vt++) {
        float v0 = Oacc[vt][0] * inv0, v1 = Oacc[vt][1] * inv0;
        float v2 = Oacc[vt][2] * inv1, v3 = Oacc[vt][3] * inv1;
        long long o = tok0 * EMB + col0 + vt * 8;
        { __half2 x; x.x = __float2half(v0); x.y = __float2half(v1); *(__half2*)(O + o) = x; }
        long long o2 = (tok0 + 8) * EMB + col0 + vt * 8;
        { __half2 x; x.x = __float2half(v2); x.y = __float2half(v3); *(__half2*)(O + o2) = x; }
    }
}

// ===================== LayerNorm -> fp16 ===============================
__global__ __launch_bounds__(256)
void layernorm_fp16_kernel(const float* __restrict__ x, const float* __restrict__ gamma,
                           const float* __restrict__ beta, fp16* __restrict__ o)
{
    long long row = blockIdx.x;
    const float4* xr = (const float4*)(x + row * EMB);
    float4 v = xr[threadIdx.x];
    float s  = v.x + v.y + v.z + v.w;
    float ss = v.x * v.x + v.y * v.y + v.z * v.z + v.w * v.w;
#pragma unroll
    for (int of = 16; of; of >>= 1) {
        s  += __shfl_xor_sync(0xffffffffu, s,  of);
        ss += __shfl_xor_sync(0xffffffffu, ss, of);
    }
    __shared__ float sh_s[8], sh_ss[8];
    int w = threadIdx.x >> 5, l = threadIdx.x & 31;
    if (l == 0) { sh_s[w] = s; sh_ss[w] = ss; }
    __syncthreads();
    s = 0.f; ss = 0.f;
#pragma unroll
    for (int i = 0; i < 8; i++) { s += sh_s[i]; ss += sh_ss[i]; }
    float mu   = s * (1.0f / EMB);
    float var  = ss * (1.0f / EMB) - mu * mu;
    float rstd = rsqrtf(var + 1e-6f);
    float4 gv = ((const float4*)gamma)[threadIdx.x];
    float4 bv = ((const float4*)beta)[threadIdx.x];
    float o0 = (v.x - mu) * rstd * gv.x + bv.x;
    float o1 = (v.y - mu) * rstd * gv.y + bv.y;
    float o2 = (v.z - mu) * rstd * gv.z + bv.z;
    float o3 = (v.w - mu) * rstd * gv.w + bv.w;
    long long base = row * EMB + threadIdx.x * 4;
    __half2 a; a.x = __float2half(o0); a.y = __float2half(o1);
    __half2 b; b.x = __float2half(o2); b.y = __float2half(o3);
    *(__half2*)(o + base)     = a;
    *(__half2*)(o + base + 2) = b;
}

// ============ transpose-convert: fp32 [R,C] -> [C,R] fp16 hi/lo ========
__global__ __launch_bounds__(256)
void wt_prep_kernel(const float* __restrict__ src, int R, int C,
                    fp16* __restrict__ dh, fp16* __restrict__ dl)
{
    __shared__ float t[32][33];
    int c0 = blockIdx.x * 32, r0 = blockIdx.y * 32;
    int tx = threadIdx.x & 31, ty = threadIdx.x >> 5;
#pragma unroll
    for (int i = ty; i < 32; i += 8)
        t[i][tx] = src[(long long)(r0 + i) * C + c0 + tx];
    __syncthreads();
#pragma unroll
    for (int i = ty; i < 32; i += 8) {
        float v = t[tx][i];
        fp16 h, l; fp16split(v, h, l);
        long long o = (long long)(c0 + i) * R + r0 + tx;
        dh[o] = h; dl[o] = l;
    }
}

// ============ V^T prep: v fp32 (b,n,h*64+d) -> vt fp16 hi/lo [BH,64,SEQ]
__global__ __launch_bounds__(256)
void vt_prep_kernel(const float* __restrict__ v, fp16* __restrict__ dh, fp16* __restrict__ dl)
{
    __shared__ float t[32][33];
    int bh = blockIdx.z, b = bh / NHEAD, h = bh % NHEAD;
    int n0 = blockIdx.x * 32, d0 = blockIdx.y * 32;
    int tx = threadIdx.x & 31, ty = threadIdx.x >> 5;
#pragma unroll
    for (int i = ty; i < 32; i += 8)
        t[i][tx] = v[((long long)(b * SEQ + n0 + i)) * EMB + h * HDIM + d0 + tx];
    __syncthreads();
#pragma unroll
    for (int i = ty; i < 32; i += 8) {
        float val = t[tx][i];
        fp16 hh, ll; fp16split(val, hh, ll);
        long long o = ((long long)bh * HDIM + d0 + i) * SEQ + n0 + tx;
        dh[o] = hh; dl[o] = ll;
    }
}

// ===================== host side =======================================
template<int BN, int WM, int WN, int EPI>
static void launch_gemm(const fp16* A, const fp16* Bhi, const fp16* Blo,
                        const float* bias, const float* resid,
                        float* C, fp16* Ch,
                        fp16* Qo, fp16* Kho, fp16* Klo, float* Vo,
                        int M, int N, int K, int ldc,
                        long long sA, long long sB,
                        int batch, int hdiv, long long sCb, long long sCh,
                        float alpha)
{
    constexpr int SMEM_BYTES = 2 * (128 * 128 + 2 * BN * 128);
    cudaFuncSetAttribute(gemm_mma<BN, WM, WN, EPI>,
                         cudaFuncAttributeMaxDynamicSharedMemorySize, SMEM_BYTES);
    dim3 grid(N / BN, M / 128, batch);
    gemm_mma<BN, WM, WN, EPI><<<grid, 256, SMEM_BYTES>>>(
        A, Bhi, Blo, bias, resid, C, Ch, Qo, Kho, Klo, Vo,
        M, N, K, ldc, sA, sB, hdiv, sCb, sCh, alpha);
}

extern "C" void kernel_launch(void* const* d_in, const int* in_sizes, int n_in,
                              void* d_out, int out_size)
{
    const float* x      = (const float*)d_in[0];
    const float* ln1_g  = (const float*)d_in[1];
    const float* ln1_b  = (const float*)d_in[2];
    const float* w_qkv  = (const float*)d_in[3];
    const float* b_qkv  = (const float*)d_in[4];
    const float* w_proj = (const float*)d_in[5];
    const float* b_proj = (const float*)d_in[6];
    const float* ln2_g  = (const float*)d_in[7];
    const float* ln2_b  = (const float*)d_in[8];
    const float* w_fc1  = (const float*)d_in[9];
    const float* b_fc1  = (const float*)d_in[10];
    const float* w_fc2  = (const float*)d_in[11];
    const float* b_fc2  = (const float*)d_in[12];
    float* out = (float*)d_out;

    fp16 *wqkvTh, *wqkvTl, *wprojTh, *wprojTl, *wfc1Th, *wfc1Tl, *wfc2Th, *wfc2Tl;
    fp16 *ln1, *qf, *kh, *kl, *vth, *vtl, *am, *ln2, *hb;
    float *vbuf, *x1;
    cudaGetSymbolAddress((void**)&wqkvTh, g_wqkvT_h);  cudaGetSymbolAddress((void**)&wqkvTl, g_wqkvT_l);
    cudaGetSymbolAddress((void**)&wprojTh, g_wprojT_h); cudaGetSymbolAddress((void**)&wprojTl, g_wprojT_l);
    cudaGetSymbolAddress((void**)&wfc1Th, g_wfc1T_h);  cudaGetSymbolAddress((void**)&wfc1Tl, g_wfc1T_l);
    cudaGetSymbolAddress((void**)&wfc2Th, g_wfc2T_h);  cudaGetSymbolAddress((void**)&wfc2Tl, g_wfc2T_l);
    cudaGetSymbolAddress((void**)&ln1, g_ln1);
    cudaGetSymbolAddress((void**)&qf, g_q);
    cudaGetSymbolAddress((void**)&kh, g_k_h);          cudaGetSymbolAddress((void**)&kl, g_k_l);
    cudaGetSymbolAddress((void**)&vbuf, g_v);
    cudaGetSymbolAddress((void**)&vth, g_vt_h);        cudaGetSymbolAddress((void**)&vtl, g_vt_l);
    cudaGetSymbolAddress((void**)&am, g_am);
    cudaGetSymbolAddress((void**)&x1, g_x1);
    cudaGetSymbolAddress((void**)&ln2, g_ln2);
    cudaGetSymbolAddress((void**)&hb, g_h);

    // 0) weight transpose-converts  W[K,N] -> Wt[N,K] fp16 hi/lo
    wt_prep_kernel<<<dim3(3 * EMB / 32, EMB / 32), 256>>>(w_qkv, EMB, 3 * EMB, wqkvTh, wqkvTl);
    wt_prep_kernel<<<dim3(EMB / 32, EMB / 32), 256>>>(w_proj, EMB, EMB, wprojTh, wprojTl);
    wt_prep_kernel<<<dim3(HIDDEN / 32, EMB / 32), 256>>>(w_fc1, EMB, HIDDEN, wfc1Th, wfc1Tl);
    wt_prep_kernel<<<dim3(EMB / 32, HIDDEN / 32), 256>>>(w_fc2, HIDDEN, EMB, wfc2Th, wfc2Tl);

    // 1) LN1 -> fp16
    layernorm_fp16_kernel<<<TOK, 256>>>(x, ln1_g, ln1_b, ln1);

    // 2) QKV GEMM with fused q/k/v extraction
    launch_gemm<128, 64, 32, EPI_QKV>(ln1, wqkvTh, wqkvTl, b_qkv, nullptr,
                                      nullptr, nullptr, qf, kh, kl, vbuf,
                                      TOK, 3 * EMB, EMB, 3 * EMB, 0, 0, 1, 1, 0, 0, 1.0f);

    // 3) V transpose -> fp16 hi/lo
    vt_prep_kernel<<<dim3(SEQ / 32, HDIM / 32, BH), 256>>>(vbuf, vth, vtl);

    // 4) fused flash attention -> merged heads fp16
    {
        constexpr int FSMEM = 80 * 1024;
        cudaFuncSetAttribute(flash_kernel,
                             cudaFuncAttributeMaxDynamicSharedMemorySize, FSMEM);
        dim3 grid(SEQ / 128, BH);
        flash_kernel<<<grid, 256, FSMEM>>>(qf, kh, kl, vth, vtl, am);
    }

    // 5) proj + residual: x1 = am @ w_proj + b + x
    launch_gemm<128, 64, 32, EPI_BIAS_RES>(am, wprojTh, wprojTl, b_proj, x,
                                           x1, nullptr, nullptr, nullptr, nullptr, nullptr,
                                           TOK, EMB, EMB, EMB, 0, 0, 1, 1, 0, 0, 1.0f);

    // 6) LN2 -> fp16
    layernorm_fp16_kernel<<<TOK, 256>>>(x1, ln2_g, ln2_b, ln2);

    // 7) FC1 + GELU -> h fp16
    launch_gemm<128, 64, 32, EPI_GELU_H>(ln2, wfc1Th, wfc1Tl, b_fc1, nullptr,
                                         nullptr, hb, nullptr, nullptr, nullptr, nullptr,
                                         TOK, HIDDEN, EMB, HIDDEN, 0, 0, 1, 1, 0, 0, 1.0f);

    // 8) FC2 + bias + residual -> out
    launch_gemm<128, 64, 32, EPI_BIAS_RES>(hb, wfc2Th, wfc2Tl, b_fc2, x1,
                                           out, nullptr, nullptr, nullptr, nullptr, nullptr,
                                           TOK, EMB, HIDDEN, EMB, 0, 0, 1, 1, 0, 0, 1.0f);
}

// round 13
// speedup vs baseline: 3.5515x; 1.3639x over previous
#include <cuda_runtime.h>
#include <cuda_fp16.h>
#include <math.h>
#include <stdint.h>

// Problem constants
#define Bz     2
#define SEQ    2048
#define EMB    1024
#define NHEAD  16
#define HDIM   64
#define HIDDEN 4096
#define TOK    (Bz * SEQ)          // 4096 rows
#define BH     (Bz * NHEAD)        // 32 batched heads

typedef __half fp16;

// ===================== MMA / async primitives (non-'a' PTX) ============
__device__ __forceinline__ void ldm_x4(uint32_t* r, uint32_t addr) {
    asm volatile("ldmatrix.sync.aligned.m8n8.x4.shared.b16 {%0,%1,%2,%3}, [%4];"
        : "=r"(r[0]), "=r"(r[1]), "=r"(r[2]), "=r"(r[3]) : "r"(addr));
}
__device__ __forceinline__ void mma_fp16(float* c, const uint32_t* a,
                                         uint32_t b0, uint32_t b1) {
    asm volatile(
        "mma.sync.aligned.m16n8k16.row.col.f32.f16.f16.f32 "
        "{%0,%1,%2,%3}, {%4,%5,%6,%7}, {%8,%9}, {%0,%1,%2,%3};"
        : "+f"(c[0]), "+f"(c[1]), "+f"(c[2]), "+f"(c[3])
        : "r"(a[0]), "r"(a[1]), "r"(a[2]), "r"(a[3]), "r"(b0), "r"(b1));
}
__device__ __forceinline__ uint32_t smem_to_u32(const void* p) {
    uint32_t a;
    asm("{ .reg .u64 t; cvta.to.shared.u64 t, %1; cvt.u32.u64 %0, t; }" : "=r"(a) : "l"(p));
    return a;
}
#define SW128(off) ((off) ^ (((off) >> 3) & 0x70))

#define CP_ASYNC16(saddr, gptr) \
    asm volatile("cp.async.cg.shared.global [%0], [%1], 16;" \
        :: "r"((uint32_t)(saddr)), "l"(gptr))
#define CP_COMMIT() asm volatile("cp.async.commit_group;" ::: "memory")
#define CP_WAIT1()  asm volatile("cp.async.wait_group 1;" ::: "memory")
#define CP_WAIT0()  asm volatile("cp.async.wait_group 0;" ::: "memory")

__device__ __forceinline__ uint32_t pack_fp16(float a, float b) {
    __half2 h;
    h.x = __float2half(a);
    h.y = __float2half(b);
    return *(uint32_t*)&h;
}

// ===================== scratch =========================================
__device__ fp16  g_wqkvT[3 * EMB * EMB];
__device__ fp16  g_wprojT[EMB * EMB];
__device__ fp16  g_wfc1T[HIDDEN * EMB];
__device__ fp16  g_wfc2T[EMB * HIDDEN];
__device__ fp16  g_ln1[TOK * EMB];
__device__ fp16  g_q[BH * SEQ * HDIM];                 // scaled, single
__device__ fp16  g_k_h[BH * SEQ * HDIM],    g_k_l[BH * SEQ * HDIM];
__device__ float g_v[TOK * EMB];                       // (b,n,h*64+d) fp32
__device__ fp16  g_vt_h[BH * HDIM * SEQ],   g_vt_l[BH * HDIM * SEQ];
__device__ fp16  g_am[TOK * EMB];
__device__ float g_x1[TOK * EMB];
__device__ fp16  g_ln2[TOK * EMB];
__device__ fp16  g_h[TOK * HIDDEN];

__device__ __forceinline__ void fp16split(float v, fp16& hi, fp16& lo) {
    hi = __float2half(v);
    lo = __float2half(v - __half2float(hi));
}
__device__ __forceinline__ float gelu_exact(float x) {
    return 0.5f * x * (1.0f + erff(x * 0.70710678118654752440f));
}

// ===================== fp16 1-pass GEMM (cp.async pipelined) ===========
// D[M,N] = alpha*(A @ B^T). A[M,K], B[N,K] single fp16.
#define EPI_ALPHA    0
#define EPI_BIAS     1
#define EPI_BIAS_RES 2
#define EPI_H        3
#define EPI_GELU_H   4
#define EPI_QKV      5   // fused q/k/v extraction (bias included)

template<int BN, int WM, int WN, int EPI>
__global__ __launch_bounds__(256, 1)
void gemm_mma(const fp16* __restrict__ A, const fp16* __restrict__ B,
              const float* __restrict__ bias, const float* __restrict__ resid,
              float* __restrict__ C, fp16* __restrict__ Ch,
              fp16* __restrict__ Qo, fp16* __restrict__ Kho,
              fp16* __restrict__ Klo, float* __restrict__ Vo,
              int M, int N, int K, int ldc,
              long long sA, long long sB,
              int hdiv, long long sCb, long long sCh,
              float alpha)
{
    constexpr int BK = 64;
    constexpr int OFF_B = 128 * 128;             // A tile = 16 KB
    constexpr int BUFB  = OFF_B + BN * 128;      // bytes per buffer
    constexpr int WGC = BN / WN;
    constexpr int MT  = WM / 16;
    constexpr int NT  = WN / 8;
    constexpr int NG  = WN / 16;

    extern __shared__ char sm[];
    const uint32_t smb = smem_to_u32(sm);
    const int tid = threadIdx.x, wid = tid >> 5, lane = tid & 31;
    const int bm = blockIdx.y * 128, bn = blockIdx.x * BN, z = blockIdx.z;
    const int wm0 = (wid / WGC) * WM, wn0 = (wid % WGC) * WN;

    A += (long long)z * sA;
    B += (long long)z * sB;
    const long long coff = (long long)(z / hdiv) * sCb + (long long)(z % hdiv) * sCh;

    float acc[MT][NT][4];
#pragma unroll
    for (int i = 0; i < MT; i++)
#pragma unroll
        for (int j = 0; j < NT; j++)
#pragma unroll
            for (int t = 0; t < 4; t++) acc[i][j][t] = 0.0f;

    const int swz   = lane & 7;
    const int aHalf = lane >> 4;
    const int bHalf = (lane >> 3) & 1;
    int aRowOff[MT], bRowOff[NG];
#pragma unroll
    for (int mt = 0; mt < MT; mt++)
        aRowOff[mt] = (wm0 + mt * 16 + (lane & 15)) * 128;
#pragma unroll
    for (int ng = 0; ng < NG; ng++)
        bRowOff[ng] = (wn0 + ng * 16 + (lane & 7) + ((lane >> 4) << 3)) * 128;

    auto stage = [&](int c, uint32_t base) {
        const long long k0 = (long long)c * BK;
        const fp16* a0 = A + (long long)bm * K + k0;
#pragma unroll
        for (int i = tid; i < 128 * 8; i += 256) {
            int r = i >> 3, u = i & 7;
            int sw = SW128(r * 128 + u * 16);
            CP_ASYNC16(smb + base + sw, a0 + (long long)r * K + u * 8);
        }
        const fp16* b0 = B + (long long)bn * K + k0;
#pragma unroll
        for (int i = tid; i < BN * 8; i += 256) {
            int r = i >> 3, u = i & 7;
            int sw = SW128(r * 128 + u * 16);
            CP_ASYNC16(smb + base + OFF_B + sw, b0 + (long long)r * K + u * 8);
        }
        CP_COMMIT();
    };

    const int nch = K / BK;
    stage(0, 0);
    for (int c = 0; c < nch; c++) {
        const uint32_t cur = (c & 1) ? BUFB : 0;
        if (c + 1 < nch) {
            stage(c + 1, (c & 1) ? 0 : BUFB);
            CP_WAIT1();
        } else {
            CP_WAIT0();
        }
        __syncthreads();

#pragma unroll
        for (int ks = 0; ks < BK / 16; ks++) {
            const uint32_t ca = (uint32_t)(((2 * ks + aHalf) ^ swz) * 16);
            const uint32_t cb = (uint32_t)(((2 * ks + bHalf) ^ swz) * 16);
            uint32_t ah[MT][4], br[NG][4];
#pragma unroll
            for (int mt = 0; mt < MT; mt++)
                ldm_x4(ah[mt], smb + cur + aRowOff[mt] + ca);
#pragma unroll
            for (int ng = 0; ng < NG; ng++)
                ldm_x4(br[ng], smb + cur + OFF_B + bRowOff[ng] + cb);
#pragma unroll
            for (int mt = 0; mt < MT; mt++)
#pragma unroll
                for (int nt = 0; nt < NT; nt++)
                    mma_fp16(acc[mt][nt], ah[mt],
                             br[nt >> 1][(nt & 1) * 2], br[nt >> 1][(nt & 1) * 2 + 1]);
        }
        __syncthreads();
    }

#pragma unroll
    for (int mt = 0; mt < MT; mt++) {
#pragma unroll
        for (int half = 0; half < 2; half++) {
            const long long row = bm + wm0 + mt * 16 + (lane >> 2) + half * 8;
#pragma unroll
            for (int nt = 0; nt < NT; nt++) {
                const int col = bn + wn0 + nt * 8 + (lane & 3) * 2;
                float v0 = acc[mt][nt][half * 2 + 0] * alpha;
                float v1 = acc[mt][nt][half * 2 + 1] * alpha;
                if (EPI == EPI_BIAS || EPI == EPI_BIAS_RES || EPI == EPI_GELU_H || EPI == EPI_QKV) {
                    v0 += bias[col]; v1 += bias[col + 1];
                }
                if (EPI == EPI_BIAS_RES) {
                    const float* rp = resid + coff + row * (long long)ldc + col;
                    v0 += rp[0]; v1 += rp[1];
                }
                if (EPI == EPI_GELU_H) {
                    v0 = gelu_exact(v0); v1 = gelu_exact(v1);
                }
                if (EPI == EPI_QKV) {
                    const int region = col >> 10;       // 0=Q 1=K 2=V (warp-uniform)
                    const int cc = col & 1023;
                    const int h = cc >> 6, d = cc & 63;
                    const long long b = row >> 11, n = row & 2047;
                    if (region == 2) {
                        float2 w; w.x = v0; w.y = v1;
                        *(float2*)(Vo + row * EMB + cc) = w;
                    } else {
                        const long long dst = ((b * NHEAD + h) * SEQ + n) * HDIM + d;
                        if (region == 0) {
                            __half2 x; x.x = __float2half(v0 * 0.125f);
                            x.y = __float2half(v1 * 0.125f);
                            *(__half2*)(Qo + dst) = x;
                        } else {
                            fp16 h0, l0, h1, l1;
                            fp16split(v0, h0, l0); fp16split(v1, h1, l1);
                            __half2 xh; xh.x = h0; xh.y = h1;
                            __half2 xl; xl.x = l0; xl.y = l1;
                            *(__half2*)(Kho + dst) = xh;
                            *(__half2*)(Klo + dst) = xl;
                        }
                    }
                } else {
                    const long long o = coff + row * (long long)ldc + col;
                    if (EPI == EPI_ALPHA || EPI == EPI_BIAS || EPI == EPI_BIAS_RES) {
                        float2 w; w.x = v0; w.y = v1;
                        *(float2*)(C + o) = w;
                    } else {
                        __half2 hh; hh.x = __float2half(v0); hh.y = __float2half(v1);
                        *(__half2*)(Ch + o) = hh;
                    }
                }
            }
        }
    }
}

// ===================== Flash attention v3 (fp16 2-pass) ================
// Grid (SEQ/128, BH), 256 threads. Q tile 128 (single fp16), KV tile 64
// double-buffered. S = Qf*Kh + Qf*Kl; O += Ph*Vh + Ph*Vl.
__global__ __launch_bounds__(256, 1)
void flash_kernel(const fp16* __restrict__ Qf,
                  const fp16* __restrict__ Kh, const fp16* __restrict__ Kl,
                  const fp16* __restrict__ Vh, const fp16* __restrict__ Vl,
                  fp16* __restrict__ O)
{
    constexpr int OFF_K = 16384;       // Q tile 16 KB
    constexpr int OFF_V = 49152;       // after 2 K bufs
    constexpr int KBUF  = 16384;       // hi 8K + lo 8K
    extern __shared__ char sm[];
    const uint32_t smb = smem_to_u32(sm);
    const int tid = threadIdx.x, wid = tid >> 5, lane = tid & 31;
    const int bh = blockIdx.y, q0 = blockIdx.x * 128;
    const long long qkbase = (long long)bh * SEQ * HDIM;
    const long long vbase  = (long long)bh * HDIM * SEQ;
    const int swz = lane & 7;

#pragma unroll
    for (int i = tid; i < 128 * 8; i += 256) {
        int r = i >> 3, u = i & 7;
        int sw = SW128(r * 128 + u * 16);
        CP_ASYNC16(smb + sw, Qf + qkbase + (long long)(q0 + r) * HDIM + u * 8);
    }
    CP_COMMIT();

    auto stage = [&](int t, int buf) {
        const int kv0 = t * 64;
        const uint32_t kb = OFF_K + buf * KBUF, vb = OFF_V + buf * KBUF;
#pragma unroll
        for (int i = tid; i < 64 * 8; i += 256) {
            int r = i >> 3, u = i & 7;
            int sw = SW128(r * 128 + u * 16);
            CP_ASYNC16(smb + kb + sw,        Kh + qkbase + (long long)(kv0 + r) * HDIM + u * 8);
            CP_ASYNC16(smb + kb + 8192 + sw, Kl + qkbase + (long long)(kv0 + r) * HDIM + u * 8);
            CP_ASYNC16(smb + vb + sw,        Vh + vbase + (long long)r * SEQ + kv0 + u * 8);
            CP_ASYNC16(smb + vb + 8192 + sw, Vl + vbase + (long long)r * SEQ + kv0 + u * 8);
        }
        CP_COMMIT();
    };
    stage(0, 0);
    CP_WAIT0();
    __syncthreads();

    uint32_t qf[4][4];
    {
        const int aRowOff = (wid * 16 + (lane & 15)) * 128;
        const int aHalf = lane >> 4;
#pragma unroll
        for (int ks = 0; ks < 4; ks++) {
            const uint32_t ca = (uint32_t)(((2 * ks + aHalf) ^ swz) * 16);
            ldm_x4(qf[ks], smb + aRowOff + ca);
        }
    }

    float Oacc[8][4];
#pragma unroll
    for (int i = 0; i < 8; i++)
#pragma unroll
        for (int t = 0; t < 4; t++) Oacc[i][t] = 0.0f;
    float mrow[2] = {-1e30f, -1e30f};
    float lrow[2] = {0.0f, 0.0f};

    const int kRowOff = (lane & 7) + ((lane >> 4) << 3);
    const int bHalf = (lane >> 3) & 1;

    for (int t = 0; t < SEQ / 64; t++) {
        const int buf = t & 1;
        if (t + 1 < SEQ / 64) { stage(t + 1, buf ^ 1); CP_WAIT1(); }
        else                  { CP_WAIT0(); }
        __syncthreads();
        const uint32_t kb = OFF_K + buf * KBUF, vb = OFF_V + buf * KBUF;

        // ---- S = Qf K^T (2-pass) ----
        float S[8][4];
#pragma unroll
        for (int j = 0; j < 8; j++)
#pragma unroll
            for (int c = 0; c < 4; c++) S[j][c] = 0.0f;
#pragma unroll
        for (int g = 0; g < 4; g++) {
            const int bRow = (g * 16 + kRowOff) * 128;
#pragma unroll
            for (int ks = 0; ks < 4; ks++) {
                const uint32_t cb = (uint32_t)(((2 * ks + bHalf) ^ swz) * 16);
                uint32_t kh4[4], kl4[4];
                ldm_x4(kh4, smb + kb + bRow + cb);
                ldm_x4(kl4, smb + kb + 8192 + bRow + cb);
                mma_fp16(S[2 * g],     qf[ks], kh4[0], kh4[1]);
                mma_fp16(S[2 * g + 1], qf[ks], kh4[2], kh4[3]);
                mma_fp16(S[2 * g],     qf[ks], kl4[0], kl4[1]);
                mma_fp16(S[2 * g + 1], qf[ks], kl4[2], kl4[3]);
            }
        }

        // ---- online softmax ----
        float mt0 = -1e30f, mt1 = -1e30f;
#pragma unroll
        for (int j = 0; j < 8; j++) {
            mt0 = fmaxf(mt0, fmaxf(S[j][0], S[j][1]));
            mt1 = fmaxf(mt1, fmaxf(S[j][2], S[j][3]));
        }
        mt0 = fmaxf(mt0, __shfl_xor_sync(0xffffffffu, mt0, 1));
        mt0 = fmaxf(mt0, __shfl_xor_sync(0xffffffffu, mt0, 2));
        mt1 = fmaxf(mt1, __shfl_xor_sync(0xffffffffu, mt1, 1));
        mt1 = fmaxf(mt1, __shfl_xor_sync(0xffffffffu, mt1, 2));
        const float mn0 = fmaxf(mrow[0], mt0), mn1 = fmaxf(mrow[1], mt1);
        const float sc0 = __expf(mrow[0] - mn0), sc1 = __expf(mrow[1] - mn1);
        float rs0 = 0.0f, rs1 = 0.0f;
#pragma unroll
        for (int j = 0; j < 8; j++) {
            S[j][0] = __expf(S[j][0] - mn0);
            S[j][1] = __expf(S[j][1] - mn0);
            S[j][2] = __expf(S[j][2] - mn1);
            S[j][3] = __expf(S[j][3] - mn1);
            rs0 += S[j][0] + S[j][1];
            rs1 += S[j][2] + S[j][3];
        }
        rs0 += __shfl_xor_sync(0xffffffffu, rs0, 1);
        rs0 += __shfl_xor_sync(0xffffffffu, rs0, 2);
        rs1 += __shfl_xor_sync(0xffffffffu, rs1, 1);
        rs1 += __shfl_xor_sync(0xffffffffu, rs1, 2);
        lrow[0] = lrow[0] * sc0 + rs0;
        lrow[1] = lrow[1] * sc1 + rs1;
        mrow[0] = mn0; mrow[1] = mn1;
#pragma unroll
        for (int i = 0; i < 8; i++) {
            Oacc[i][0] *= sc0; Oacc[i][1] *= sc0;
            Oacc[i][2] *= sc1; Oacc[i][3] *= sc1;
        }

        // ---- O += P V (2-pass, P single fp16) ----
#pragma unroll
        for (int j = 0; j < 4; j++) {
            uint32_t ah[4];
            ah[0] = pack_fp16(S[2*j][0],   S[2*j][1]);
            ah[1] = pack_fp16(S[2*j][2],   S[2*j][3]);
            ah[2] = pack_fp16(S[2*j+1][0], S[2*j+1][1]);
            ah[3] = pack_fp16(S[2*j+1][2], S[2*j+1][3]);

            const uint32_t cv = (uint32_t)(((2 * j + bHalf) ^ swz) * 16);
#pragma unroll
            for (int vg = 0; vg < 4; vg++) {
                const int vRow = (vg * 16 + kRowOff) * 128;
                uint32_t vh4[4], vl4[4];
                ldm_x4(vh4, smb + vb + vRow + cv);
                ldm_x4(vl4, smb + vb + 8192 + vRow + cv);
                mma_fp16(Oacc[2 * vg],     ah, vh4[0], vh4[1]);
                mma_fp16(Oacc[2 * vg + 1], ah, vh4[2], vh4[3]);
                mma_fp16(Oacc[2 * vg],     ah, vl4[0], vl4[1]);
                mma_fp16(Oacc[2 * vg + 1], ah, vl4[2], vl4[3]);
            }
        }
        __syncthreads();
    }

    // epilogue: merged-head single fp16
    const float inv0 = 1.0f / lrow[0], inv1 = 1.0f / lrow[1];
    const int b = bh / NHEAD, hh = bh % NHEAD;
    const long long tok0 = (long long)b * SEQ + q0 + wid * 16 + (lane >> 2);
    const int col0 = hh * HDIM + (lane & 3) * 2;
#pragma unroll
    for (int vt = 0; vt < 8; vt++) {
        float v0 = Oacc[vt][0] * inv0, v1 = Oacc[vt][1] * inv0;
        float v2 = Oacc[vt][2] * inv1, v3 = Oacc[vt][3] * inv1;
        long long o = tok0 * EMB + col0 + vt * 8;
        { __half2 x; x.x = __float2half(v0); x.y = __float2half(v1); *(__half2*)(O + o) = x; }
        long long o2 = (tok0 + 8) * EMB + col0 + vt * 8;
        { __half2 x; x.x = __float2half(v2); x.y = __float2half(v3); *(__half2*)(O + o2) = x; }
    }
}

// ===================== LayerNorm -> fp16 ===============================
__global__ __launch_bounds__(256)
void layernorm_fp16_kernel(const float* __restrict__ x, const float* __restrict__ gamma,
                           const float* __restrict__ beta, fp16* __restrict__ o)
{
    long long row = blockIdx.x;
    const float4* xr = (const float4*)(x + row * EMB);
    float4 v = xr[threadIdx.x];
    float s  = v.x + v.y + v.z + v.w;
    float ss = v.x * v.x + v.y * v.y + v.z * v.z + v.w * v.w;
#pragma unroll
    for (int of = 16; of; of >>= 1) {
        s  += __shfl_xor_sync(0xffffffffu, s,  of);
        ss += __shfl_xor_sync(0xffffffffu, ss, of);
    }
    __shared__ float sh_s[8], sh_ss[8];
    int w = threadIdx.x >> 5, l = threadIdx.x & 31;
    if (l == 0) { sh_s[w] = s; sh_ss[w] = ss; }
    __syncthreads();
    s = 0.f; ss = 0.f;
#pragma unroll
    for (int i = 0; i < 8; i++) { s += sh_s[i]; ss += sh_ss[i]; }
    float mu   = s * (1.0f / EMB);
    float var  = ss * (1.0f / EMB) - mu * mu;
    float rstd = rsqrtf(var + 1e-6f);
    float4 gv = ((const float4*)gamma)[threadIdx.x];
    float4 bv = ((const float4*)beta)[threadIdx.x];
    float o0 = (v.x - mu) * rstd * gv.x + bv.x;
    float o1 = (v.y - mu) * rstd * gv.y + bv.y;
    float o2 = (v.z - mu) * rstd * gv.z + bv.z;
    float o3 = (v.w - mu) * rstd * gv.w + bv.w;
    long long base = row * EMB + threadIdx.x * 4;
    __half2 a; a.x = __float2half(o0); a.y = __float2half(o1);
    __half2 b; b.x = __float2half(o2); b.y = __float2half(o3);
    *(__half2*)(o + base)     = a;
    *(__half2*)(o + base + 2) = b;
}

// ============ transpose-convert: fp32 [R,C] -> [C,R] fp16 ==============
__global__ __launch_bounds__(256)
void wt_prep_kernel(const float* __restrict__ src, int R, int C,
                    fp16* __restrict__ dh)
{
    __shared__ float t[32][33];
    int c0 = blockIdx.x * 32, r0 = blockIdx.y * 32;
    int tx = threadIdx.x & 31, ty = threadIdx.x >> 5;
#pragma unroll
    for (int i = ty; i < 32; i += 8)
        t[i][tx] = src[(long long)(r0 + i) * C + c0 + tx];
    __syncthreads();
#pragma unroll
    for (int i = ty; i < 32; i += 8) {
        long long o = (long long)(c0 + i) * R + r0 + tx;
        dh[o] = __float2half(t[tx][i]);
    }
}

// ============ V^T prep: v fp32 (b,n,h*64+d) -> vt fp16 hi/lo [BH,64,SEQ]
__global__ __launch_bounds__(256)
void vt_prep_kernel(const float* __restrict__ v, fp16* __restrict__ dh, fp16* __restrict__ dl)
{
    __shared__ float t[32][33];
    int bh = blockIdx.z, b = bh / NHEAD, h = bh % NHEAD;
    int n0 = blockIdx.x * 32, d0 = blockIdx.y * 32;
    int tx = threadIdx.x & 31, ty = threadIdx.x >> 5;
#pragma unroll
    for (int i = ty; i < 32; i += 8)
        t[i][tx] = v[((long long)(b * SEQ + n0 + i)) * EMB + h * HDIM + d0 + tx];
    __syncthreads();
#pragma unroll
    for (int i = ty; i < 32; i += 8) {
        float val = t[tx][i];
        fp16 hh, ll; fp16split(val, hh, ll);
        long long o = ((long long)bh * HDIM + d0 + i) * SEQ + n0 + tx;
        dh[o] = hh; dl[o] = ll;
    }
}

// ===================== host side =======================================
template<int BN, int WM, int WN, int EPI>
static void launch_gemm(const fp16* A, const fp16* B,
                        const float* bias, const float* resid,
                        float* C, fp16* Ch,
                        fp16* Qo, fp16* Kho, fp16* Klo, float* Vo,
                        int M, int N, int K, int ldc,
                        long long sA, long long sB,
                        int batch, int hdiv, long long sCb, long long sCh,
                        float alpha)
{
    constexpr int SMEM_BYTES = 2 * (128 * 128 + BN * 128);
    cudaFuncSetAttribute(gemm_mma<BN, WM, WN, EPI>,
                         cudaFuncAttributeMaxDynamicSharedMemorySize, SMEM_BYTES);
    dim3 grid(N / BN, M / 128, batch);
    gemm_mma<BN, WM, WN, EPI><<<grid, 256, SMEM_BYTES>>>(
        A, B, bias, resid, C, Ch, Qo, Kho, Klo, Vo,
        M, N, K, ldc, sA, sB, hdiv, sCb, sCh, alpha);
}

extern "C" void kernel_launch(void* const* d_in, const int* in_sizes, int n_in,
                              void* d_out, int out_size)
{
    const float* x      = (const float*)d_in[0];
    const float* ln1_g  = (const float*)d_in[1];
    const float* ln1_b  = (const float*)d_in[2];
    const float* w_qkv  = (const float*)d_in[3];
    const float* b_qkv  = (const float*)d_in[4];
    const float* w_proj = (const float*)d_in[5];
    const float* b_proj = (const float*)d_in[6];
    const float* ln2_g  = (const float*)d_in[7];
    const float* ln2_b  = (const float*)d_in[8];
    const float* w_fc1  = (const float*)d_in[9];
    const float* b_fc1  = (const float*)d_in[10];
    const float* w_fc2  = (const float*)d_in[11];
    const float* b_fc2  = (const float*)d_in[12];
    float* out = (float*)d_out;

    fp16 *wqkvT, *wprojT, *wfc1T, *wfc2T;
    fp16 *ln1, *qf, *kh, *kl, *vth, *vtl, *am, *ln2, *hb;
    float *vbuf, *x1;
    cudaGetSymbolAddress((void**)&wqkvT, g_wqkvT);
    cudaGetSymbolAddress((void**)&wprojT, g_wprojT);
    cudaGetSymbolAddress((void**)&wfc1T, g_wfc1T);
    cudaGetSymbolAddress((void**)&wfc2T, g_wfc2T);
    cudaGetSymbolAddress((void**)&ln1, g_ln1);
    cudaGetSymbolAddress((void**)&qf, g_q);
    cudaGetSymbolAddress((void**)&kh, g_k_h);          cudaGetSymbolAddress((void**)&kl, g_k_l);
    cudaGetSymbolAddress((void**)&vbuf, g_v);
    cudaGetSymbolAddress((void**)&vth, g_vt_h);        cudaGetSymbolAddress((void**)&vtl, g_vt_l);
    cudaGetSymbolAddress((void**)&am, g_am);
    cudaGetSymbolAddress((void**)&x1, g_x1);
    cudaGetSymbolAddress((void**)&ln2, g_ln2);
    cudaGetSymbolAddress((void**)&hb, g_h);

    // 0) weight transpose-converts  W[K,N] -> Wt[N,K] fp16
    wt_prep_kernel<<<dim3(3 * EMB / 32, EMB / 32), 256>>>(w_qkv, EMB, 3 * EMB, wqkvT);
    wt_prep_kernel<<<dim3(EMB / 32, EMB / 32), 256>>>(w_proj, EMB, EMB, wprojT);
    wt_prep_kernel<<<dim3(HIDDEN / 32, EMB / 32), 256>>>(w_fc1, EMB, HIDDEN, wfc1T);
    wt_prep_kernel<<<dim3(EMB / 32, HIDDEN / 32), 256>>>(w_fc2, HIDDEN, EMB, wfc2T);

    // 1) LN1 -> fp16
    layernorm_fp16_kernel<<<TOK, 256>>>(x, ln1_g, ln1_b, ln1);

    // 2) QKV GEMM with fused q/k/v extraction
    launch_gemm<128, 64, 32, EPI_QKV>(ln1, wqkvT, b_qkv, nullptr,
                                      nullptr, nullptr, qf, kh, kl, vbuf,
                                      TOK, 3 * EMB, EMB, 3 * EMB, 0, 0, 1, 1, 0, 0, 1.0f);

    // 3) V transpose -> fp16 hi/lo
    vt_prep_kernel<<<dim3(SEQ / 32, HDIM / 32, BH), 256>>>(vbuf, vth, vtl);

    // 4) fused flash attention -> merged heads fp16
    {
        constexpr int FSMEM = 80 * 1024;
        cudaFuncSetAttribute(flash_kernel,
                             cudaFuncAttributeMaxDynamicSharedMemorySize, FSMEM);
        dim3 grid(SEQ / 128, BH);
        flash_kernel<<<grid, 256, FSMEM>>>(qf, kh, kl, vth, vtl, am);
    }

    // 5) proj + residual: x1 = am @ w_proj + b + x
    launch_gemm<128, 64, 32, EPI_BIAS_RES>(am, wprojT, b_proj, x,
                                           x1, nullptr, nullptr, nullptr, nullptr, nullptr,
                                           TOK, EMB, EMB, EMB, 0, 0, 1, 1, 0, 0, 1.0f);

    // 6) LN2 -> fp16
    layernorm_fp16_kernel<<<TOK, 256>>>(x1, ln2_g, ln2_b, ln2);

    // 7) FC1 + GELU -> h fp16
    launch_gemm<128, 64, 32, EPI_GELU_H>(ln2, wfc1T, b_fc1, nullptr,
                                         nullptr, hb, nullptr, nullptr, nullptr, nullptr,
                                         TOK, HIDDEN, EMB, HIDDEN, 0, 0, 1, 1, 0, 0, 1.0f);

    // 8) FC2 + bias + residual -> out
    launch_gemm<128, 64, 32, EPI_BIAS_RES>(hb, wfc2T, b_fc2, x1,
                                           out, nullptr, nullptr, nullptr, nullptr, nullptr,
                                           TOK, EMB, HIDDEN, EMB, 0, 0, 1, 1, 0, 0, 1.0f);
}

// round 14
// speedup vs baseline: 4.1865x; 1.1788x over previous
#include <cuda_runtime.h>
#include <cuda_fp16.h>
#include <math.h>
#include <stdint.h>

// Problem constants
#define Bz     2
#define SEQ    2048
#define EMB    1024
#define NHEAD  16
#define HDIM   64
#define HIDDEN 4096
#define TOK    (Bz * SEQ)          // 4096 rows
#define BH     (Bz * NHEAD)        // 32 batched heads

typedef __half fp16;

// ===================== MMA / async primitives (non-'a' PTX) ============
__device__ __forceinline__ void ldm_x4(uint32_t* r, uint32_t addr) {
    asm volatile("ldmatrix.sync.aligned.m8n8.x4.shared.b16 {%0,%1,%2,%3}, [%4];"
        : "=r"(r[0]), "=r"(r[1]), "=r"(r[2]), "=r"(r[3]) : "r"(addr));
}
__device__ __forceinline__ void mma_fp16(float* c, const uint32_t* a,
                                         uint32_t b0, uint32_t b1) {
    asm volatile(
        "mma.sync.aligned.m16n8k16.row.col.f32.f16.f16.f32 "
        "{%0,%1,%2,%3}, {%4,%5,%6,%7}, {%8,%9}, {%0,%1,%2,%3};"
        : "+f"(c[0]), "+f"(c[1]), "+f"(c[2]), "+f"(c[3])
        : "r"(a[0]), "r"(a[1]), "r"(a[2]), "r"(a[3]), "r"(b0), "r"(b1));
}
__device__ __forceinline__ uint32_t smem_to_u32(const void* p) {
    uint32_t a;
    asm("{ .reg .u64 t; cvta.to.shared.u64 t, %1; cvt.u32.u64 %0, t; }" : "=r"(a) : "l"(p));
    return a;
}
#define SW128(off) ((off) ^ (((off) >> 3) & 0x70))

#define CP_ASYNC16(saddr, gptr) \
    asm volatile("cp.async.cg.shared.global [%0], [%1], 16;" \
        :: "r"((uint32_t)(saddr)), "l"(gptr))
#define CP_COMMIT() asm volatile("cp.async.commit_group;" ::: "memory")
#define CP_WAIT1()  asm volatile("cp.async.wait_group 1;" ::: "memory")
#define CP_WAIT0()  asm volatile("cp.async.wait_group 0;" ::: "memory")

__device__ __forceinline__ uint32_t pack_fp16(float a, float b) {
    __half2 h;
    h.x = __float2half(a);
    h.y = __float2half(b);
    return *(uint32_t*)&h;
}

// ===================== scratch =========================================
__device__ fp16  g_wqkvT[3 * EMB * EMB];
__device__ fp16  g_wprojT[EMB * EMB];
__device__ fp16  g_wfc1T[HIDDEN * EMB];
__device__ fp16  g_wfc2T[EMB * HIDDEN];
__device__ fp16  g_ln1[TOK * EMB];
__device__ fp16  g_q[BH * SEQ * HDIM];                 // scaled, single
__device__ fp16  g_k[BH * SEQ * HDIM];                 // single
__device__ float g_v[TOK * EMB];                       // (b,n,h*64+d) fp32
__device__ fp16  g_vt[BH * HDIM * SEQ];                // single
__device__ fp16  g_am[TOK * EMB];
__device__ float g_x1[TOK * EMB];
__device__ fp16  g_ln2[TOK * EMB];
__device__ fp16  g_h[TOK * HIDDEN];

__device__ __forceinline__ float gelu_exact(float x) {
    return 0.5f * x * (1.0f + erff(x * 0.70710678118654752440f));
}

// ===================== fp16 1-pass GEMM (cp.async pipelined) ===========
// D[M,N] = alpha*(A @ B^T). A[M,K], B[N,K] single fp16.
#define EPI_ALPHA    0
#define EPI_BIAS     1
#define EPI_BIAS_RES 2
#define EPI_H        3
#define EPI_GELU_H   4
#define EPI_QKV      5   // fused q/k/v extraction (bias included)

template<int BN, int WM, int WN, int EPI>
__global__ __launch_bounds__(256, 1)
void gemm_mma(const fp16* __restrict__ A, const fp16* __restrict__ B,
              const float* __restrict__ bias, const float* __restrict__ resid,
              float* __restrict__ C, fp16* __restrict__ Ch,
              fp16* __restrict__ Qo, fp16* __restrict__ Ko,
              float* __restrict__ Vo,
              int M, int N, int K, int ldc,
              long long sA, long long sB,
              int hdiv, long long sCb, long long sCh,
              float alpha)
{
    constexpr int BK = 64;
    constexpr int OFF_B = 128 * 128;             // A tile = 16 KB
    constexpr int BUFB  = OFF_B + BN * 128;      // bytes per buffer
    constexpr int WGC = BN / WN;
    constexpr int MT  = WM / 16;
    constexpr int NT  = WN / 8;
    constexpr int NG  = WN / 16;

    extern __shared__ char sm[];
    const uint32_t smb = smem_to_u32(sm);
    const int tid = threadIdx.x, wid = tid >> 5, lane = tid & 31;
    const int bm = blockIdx.y * 128, bn = blockIdx.x * BN, z = blockIdx.z;
    const int wm0 = (wid / WGC) * WM, wn0 = (wid % WGC) * WN;

    A += (long long)z * sA;
    B += (long long)z * sB;
    const long long coff = (long long)(z / hdiv) * sCb + (long long)(z % hdiv) * sCh;

    float acc[MT][NT][4];
#pragma unroll
    for (int i = 0; i < MT; i++)
#pragma unroll
        for (int j = 0; j < NT; j++)
#pragma unroll
            for (int t = 0; t < 4; t++) acc[i][j][t] = 0.0f;

    const int swz   = lane & 7;
    const int aHalf = lane >> 4;
    const int bHalf = (lane >> 3) & 1;
    int aRowOff[MT], bRowOff[NG];
#pragma unroll
    for (int mt = 0; mt < MT; mt++)
        aRowOff[mt] = (wm0 + mt * 16 + (lane & 15)) * 128;
#pragma unroll
    for (int ng = 0; ng < NG; ng++)
        bRowOff[ng] = (wn0 + ng * 16 + (lane & 7) + ((lane >> 4) << 3)) * 128;

    auto stage = [&](int c, uint32_t base) {
        const long long k0 = (long long)c * BK;
        const fp16* a0 = A + (long long)bm * K + k0;
#pragma unroll
        for (int i = tid; i < 128 * 8; i += 256) {
            int r = i >> 3, u = i & 7;
            int sw = SW128(r * 128 + u * 16);
            CP_ASYNC16(smb + base + sw, a0 + (long long)r * K + u * 8);
        }
        const fp16* b0 = B + (long long)bn * K + k0;
#pragma unroll
        for (int i = tid; i < BN * 8; i += 256) {
            int r = i >> 3, u = i & 7;
            int sw = SW128(r * 128 + u * 16);
            CP_ASYNC16(smb + base + OFF_B + sw, b0 + (long long)r * K + u * 8);
        }
        CP_COMMIT();
    };

    const int nch = K / BK;
    stage(0, 0);
    for (int c = 0; c < nch; c++) {
        const uint32_t cur = (c & 1) ? BUFB : 0;
        if (c + 1 < nch) {
            stage(c + 1, (c & 1) ? 0 : BUFB);
            CP_WAIT1();
        } else {
            CP_WAIT0();
        }
        __syncthreads();

#pragma unroll
        for (int ks = 0; ks < BK / 16; ks++) {
            const uint32_t ca = (uint32_t)(((2 * ks + aHalf) ^ swz) * 16);
            const uint32_t cb = (uint32_t)(((2 * ks + bHalf) ^ swz) * 16);
            uint32_t ah[MT][4], br[NG][4];
#pragma unroll
            for (int mt = 0; mt < MT; mt++)
                ldm_x4(ah[mt], smb + cur + aRowOff[mt] + ca);
#pragma unroll
            for (int ng = 0; ng < NG; ng++)
                ldm_x4(br[ng], smb + cur + OFF_B + bRowOff[ng] + cb);
#pragma unroll
            for (int mt = 0; mt < MT; mt++)
#pragma unroll
                for (int nt = 0; nt < NT; nt++)
                    mma_fp16(acc[mt][nt], ah[mt],
                             br[nt >> 1][(nt & 1) * 2], br[nt >> 1][(nt & 1) * 2 + 1]);
        }
        __syncthreads();
    }

#pragma unroll
    for (int mt = 0; mt < MT; mt++) {
#pragma unroll
        for (int half = 0; half < 2; half++) {
            const long long row = bm + wm0 + mt * 16 + (lane >> 2) + half * 8;
#pragma unroll
            for (int nt = 0; nt < NT; nt++) {
                const int col = bn + wn0 + nt * 8 + (lane & 3) * 2;
                float v0 = acc[mt][nt][half * 2 + 0] * alpha;
                float v1 = acc[mt][nt][half * 2 + 1] * alpha;
                if (EPI == EPI_BIAS || EPI == EPI_BIAS_RES || EPI == EPI_GELU_H || EPI == EPI_QKV) {
                    v0 += bias[col]; v1 += bias[col + 1];
                }
                if (EPI == EPI_BIAS_RES) {
                    const float* rp = resid + coff + row * (long long)ldc + col;
                    v0 += rp[0]; v1 += rp[1];
                }
                if (EPI == EPI_GELU_H) {
                    v0 = gelu_exact(v0); v1 = gelu_exact(v1);
                }
                if (EPI == EPI_QKV) {
                    const int region = col >> 10;       // 0=Q 1=K 2=V (warp-uniform)
                    const int cc = col & 1023;
                    const int h = cc >> 6, d = cc & 63;
                    const long long b = row >> 11, n = row & 2047;
                    if (region == 2) {
                        float2 w; w.x = v0; w.y = v1;
                        *(float2*)(Vo + row * EMB + cc) = w;
                    } else {
                        const long long dst = ((b * NHEAD + h) * SEQ + n) * HDIM + d;
                        if (region == 0) {
                            __half2 x; x.x = __float2half(v0 * 0.125f);
                            x.y = __float2half(v1 * 0.125f);
                            *(__half2*)(Qo + dst) = x;
                        } else {
                            __half2 x; x.x = __float2half(v0);
                            x.y = __float2half(v1);
                            *(__half2*)(Ko + dst) = x;
                        }
                    }
                } else {
                    const long long o = coff + row * (long long)ldc + col;
                    if (EPI == EPI_ALPHA || EPI == EPI_BIAS || EPI == EPI_BIAS_RES) {
                        float2 w; w.x = v0; w.y = v1;
                        *(float2*)(C + o) = w;
                    } else {
                        __half2 hh; hh.x = __float2half(v0); hh.y = __float2half(v1);
                        *(__half2*)(Ch + o) = hh;
                    }
                }
            }
        }
    }
}

// ===================== Flash attention v4 (single-pass fp16) ===========
// Grid (SEQ/128, BH), 256 threads. Q tile 128, KV tile 64 double-buffered.
// S = Qf*Kf; O += Pf*Vf.  smem: Q 16K | K 2x8K | V 2x8K = 48 KB.
__global__ __launch_bounds__(256)
void flash_kernel(const fp16* __restrict__ Qf, const fp16* __restrict__ Kf,
                  const fp16* __restrict__ Vf, fp16* __restrict__ O)
{
    constexpr int OFF_K = 16384;
    constexpr int OFF_V = 32768;
    constexpr int KBUF  = 8192;
    extern __shared__ char sm[];
    const uint32_t smb = smem_to_u32(sm);
    const int tid = threadIdx.x, wid = tid >> 5, lane = tid & 31;
    const int bh = blockIdx.y, q0 = blockIdx.x * 128;
    const long long qkbase = (long long)bh * SEQ * HDIM;
    const long long vbase  = (long long)bh * HDIM * SEQ;
    const int swz = lane & 7;

#pragma unroll
    for (int i = tid; i < 128 * 8; i += 256) {
        int r = i >> 3, u = i & 7;
        int sw = SW128(r * 128 + u * 16);
        CP_ASYNC16(smb + sw, Qf + qkbase + (long long)(q0 + r) * HDIM + u * 8);
    }
    CP_COMMIT();

    auto stage = [&](int t, int buf) {
        const int kv0 = t * 64;
        const uint32_t kb = OFF_K + buf * KBUF, vb = OFF_V + buf * KBUF;
#pragma unroll
        for (int i = tid; i < 64 * 8; i += 256) {
            int r = i >> 3, u = i & 7;
            int sw = SW128(r * 128 + u * 16);
            CP_ASYNC16(smb + kb + sw, Kf + qkbase + (long long)(kv0 + r) * HDIM + u * 8);
            CP_ASYNC16(smb + vb + sw, Vf + vbase + (long long)r * SEQ + kv0 + u * 8);
        }
        CP_COMMIT();
    };
    stage(0, 0);
    CP_WAIT0();
    __syncthreads();

    uint32_t qf[4][4];
    {
        const int aRowOff = (wid * 16 + (lane & 15)) * 128;
        const int aHalf = lane >> 4;
#pragma unroll
        for (int ks = 0; ks < 4; ks++) {
            const uint32_t ca = (uint32_t)(((2 * ks + aHalf) ^ swz) * 16);
            ldm_x4(qf[ks], smb + aRowOff + ca);
        }
    }

    float Oacc[8][4];
#pragma unroll
    for (int i = 0; i < 8; i++)
#pragma unroll
        for (int t = 0; t < 4; t++) Oacc[i][t] = 0.0f;
    float mrow[2] = {-1e30f, -1e30f};
    float lrow[2] = {0.0f, 0.0f};

    const int kRowOff = (lane & 7) + ((lane >> 4) << 3);
    const int bHalf = (lane >> 3) & 1;

    for (int t = 0; t < SEQ / 64; t++) {
        const int buf = t & 1;
        if (t + 1 < SEQ / 64) { stage(t + 1, buf ^ 1); CP_WAIT1(); }
        else                  { CP_WAIT0(); }
        __syncthreads();
        const uint32_t kb = OFF_K + buf * KBUF, vb = OFF_V + buf * KBUF;

        // ---- S = Qf Kf^T ----
        float S[8][4];
#pragma unroll
        for (int j = 0; j < 8; j++)
#pragma unroll
            for (int c = 0; c < 4; c++) S[j][c] = 0.0f;
#pragma unroll
        for (int g = 0; g < 4; g++) {
            const int bRow = (g * 16 + kRowOff) * 128;
#pragma unroll
            for (int ks = 0; ks < 4; ks++) {
                const uint32_t cb = (uint32_t)(((2 * ks + bHalf) ^ swz) * 16);
                uint32_t k4[4];
                ldm_x4(k4, smb + kb + bRow + cb);
                mma_fp16(S[2 * g],     qf[ks], k4[0], k4[1]);
                mma_fp16(S[2 * g + 1], qf[ks], k4[2], k4[3]);
            }
        }

        // ---- online softmax ----
        float mt0 = -1e30f, mt1 = -1e30f;
#pragma unroll
        for (int j = 0; j < 8; j++) {
            mt0 = fmaxf(mt0, fmaxf(S[j][0], S[j][1]));
            mt1 = fmaxf(mt1, fmaxf(S[j][2], S[j][3]));
        }
        mt0 = fmaxf(mt0, __shfl_xor_sync(0xffffffffu, mt0, 1));
        mt0 = fmaxf(mt0, __shfl_xor_sync(0xffffffffu, mt0, 2));
        mt1 = fmaxf(mt1, __shfl_xor_sync(0xffffffffu, mt1, 1));
        mt1 = fmaxf(mt1, __shfl_xor_sync(0xffffffffu, mt1, 2));
        const float mn0 = fmaxf(mrow[0], mt0), mn1 = fmaxf(mrow[1], mt1);
        const float sc0 = __expf(mrow[0] - mn0), sc1 = __expf(mrow[1] - mn1);
        float rs0 = 0.0f, rs1 = 0.0f;
#pragma unroll
        for (int j = 0; j < 8; j++) {
            S[j][0] = __expf(S[j][0] - mn0);
            S[j][1] = __expf(S[j][1] - mn0);
            S[j][2] = __expf(S[j][2] - mn1);
            S[j][3] = __expf(S[j][3] - mn1);
            rs0 += S[j][0] + S[j][1];
            rs1 += S[j][2] + S[j][3];
        }
        rs0 += __shfl_xor_sync(0xffffffffu, rs0, 1);
        rs0 += __shfl_xor_sync(0xffffffffu, rs0, 2);
        rs1 += __shfl_xor_sync(0xffffffffu, rs1, 1);
        rs1 += __shfl_xor_sync(0xffffffffu, rs1, 2);
        lrow[0] = lrow[0] * sc0 + rs0;
        lrow[1] = lrow[1] * sc1 + rs1;
        mrow[0] = mn0; mrow[1] = mn1;
#pragma unroll
        for (int i = 0; i < 8; i++) {
            Oacc[i][0] *= sc0; Oacc[i][1] *= sc0;
            Oacc[i][2] *= sc1; Oacc[i][3] *= sc1;
        }

        // ---- O += P Vf ----
#pragma unroll
        for (int j = 0; j < 4; j++) {
            uint32_t ah[4];
            ah[0] = pack_fp16(S[2*j][0],   S[2*j][1]);
            ah[1] = pack_fp16(S[2*j][2],   S[2*j][3]);
            ah[2] = pack_fp16(S[2*j+1][0], S[2*j+1][1]);
            ah[3] = pack_fp16(S[2*j+1][2], S[2*j+1][3]);

            const uint32_t cv = (uint32_t)(((2 * j + bHalf) ^ swz) * 16);
#pragma unroll
            for (int vg = 0; vg < 4; vg++) {
                const int vRow = (vg * 16 + kRowOff) * 128;
                uint32_t v4[4];
                ldm_x4(v4, smb + vb + vRow + cv);
                mma_fp16(Oacc[2 * vg],     ah, v4[0], v4[1]);
                mma_fp16(Oacc[2 * vg + 1], ah, v4[2], v4[3]);
            }
        }
        __syncthreads();
    }

    // epilogue: merged-head single fp16
    const float inv0 = 1.0f / lrow[0], inv1 = 1.0f / lrow[1];
    const int b = bh / NHEAD, hh = bh % NHEAD;
    const long long tok0 = (long long)b * SEQ + q0 + wid * 16 + (lane >> 2);
    const int col0 = hh * HDIM + (lane & 3) * 2;
#pragma unroll
    for (int vt = 0; vt < 8; vt++) {
        float v0 = Oacc[vt][0] * inv0, v1 = Oacc[vt][1] * inv0;
        float v2 = Oacc[vt][2] * inv1, v3 = Oacc[vt][3] * inv1;
        long long o = tok0 * EMB + col0 + vt * 8;
        { __half2 x; x.x = __float2half(v0); x.y = __float2half(v1); *(__half2*)(O + o) = x; }
        long long o2 = (tok0 + 8) * EMB + col0 + vt * 8;
        { __half2 x; x.x = __float2half(v2); x.y = __float2half(v3); *(__half2*)(O + o2) = x; }
    }
}

// ===================== LayerNorm -> fp16 ===============================
__global__ __launch_bounds__(256)
void layernorm_fp16_kernel(const float* __restrict__ x, const float* __restrict__ gamma,
                           const float* __restrict__ beta, fp16* __restrict__ o)
{
    long long row = blockIdx.x;
    const float4* xr = (const float4*)(x + row * EMB);
    float4 v = xr[threadIdx.x];
    float s  = v.x + v.y + v.z + v.w;
    float ss = v.x * v.x + v.y * v.y + v.z * v.z + v.w * v.w;
#pragma unroll
    for (int of = 16; of; of >>= 1) {
        s  += __shfl_xor_sync(0xffffffffu, s,  of);
        ss += __shfl_xor_sync(0xffffffffu, ss, of);
    }
    __shared__ float sh_s[8], sh_ss[8];
    int w = threadIdx.x >> 5, l = threadIdx.x & 31;
    if (l == 0) { sh_s[w] = s; sh_ss[w] = ss; }
    __syncthreads();
    s = 0.f; ss = 0.f;
#pragma unroll
    for (int i = 0; i < 8; i++) { s += sh_s[i]; ss += sh_ss[i]; }
    float mu   = s * (1.0f / EMB);
    float var  = ss * (1.0f / EMB) - mu * mu;
    float rstd = rsqrtf(var + 1e-6f);
    float4 gv = ((const float4*)gamma)[threadIdx.x];
    float4 bv = ((const float4*)beta)[threadIdx.x];
    float o0 = (v.x - mu) * rstd * gv.x + bv.x;
    float o1 = (v.y - mu) * rstd * gv.y + bv.y;
    float o2 = (v.z - mu) * rstd * gv.z + bv.z;
    float o3 = (v.w - mu) * rstd * gv.w + bv.w;
    long long base = row * EMB + threadIdx.x * 4;
    __half2 a; a.x = __float2half(o0); a.y = __float2half(o1);
    __half2 b; b.x = __float2half(o2); b.y = __float2half(o3);
    *(__half2*)(o + base)     = a;
    *(__half2*)(o + base + 2) = b;
}

// ============ transpose-convert: fp32 [R,C] -> [C,R] fp16 ==============
__global__ __launch_bounds__(256)
void wt_prep_kernel(const float* __restrict__ src, int R, int C,
                    fp16* __restrict__ dh)
{
    __shared__ float t[32][33];
    int c0 = blockIdx.x * 32, r0 = blockIdx.y * 32;
    int tx = threadIdx.x & 31, ty = threadIdx.x >> 5;
#pragma unroll
    for (int i = ty; i < 32; i += 8)
        t[i][tx] = src[(long long)(r0 + i) * C + c0 + tx];
    __syncthreads();
#pragma unroll
    for (int i = ty; i < 32; i += 8) {
        long long o = (long long)(c0 + i) * R + r0 + tx;
        dh[o] = __float2half(t[tx][i]);
    }
}

// ============ V^T prep: v fp32 (b,n,h*64+d) -> vt fp16 [BH,64,SEQ] =====
__global__ __launch_bounds__(256)
void vt_prep_kernel(const float* __restrict__ v, fp16* __restrict__ dh)
{
    __shared__ float t[32][33];
    int bh = blockIdx.z, b = bh / NHEAD, h = bh % NHEAD;
    int n0 = blockIdx.x * 32, d0 = blockIdx.y * 32;
    int tx = threadIdx.x & 31, ty = threadIdx.x >> 5;
#pragma unroll
    for (int i = ty; i < 32; i += 8)
        t[i][tx] = v[((long long)(b * SEQ + n0 + i)) * EMB + h * HDIM + d0 + tx];
    __syncthreads();
#pragma unroll
    for (int i = ty; i < 32; i += 8) {
        long long o = ((long long)bh * HDIM + d0 + i) * SEQ + n0 + tx;
        dh[o] = __float2half(t[tx][i]);
    }
}

// ===================== host side =======================================
template<int BN, int WM, int WN, int EPI>
static void launch_gemm(const fp16* A, const fp16* B,
                        const float* bias, const float* resid,
                        float* C, fp16* Ch,
                        fp16* Qo, fp16* Ko, float* Vo,
                        int M, int N, int K, int ldc,
                        long long sA, long long sB,
                        int batch, int hdiv, long long sCb, long long sCh,
                        float alpha)
{
    constexpr int SMEM_BYTES = 2 * (128 * 128 + BN * 128);
    cudaFuncSetAttribute(gemm_mma<BN, WM, WN, EPI>,
                         cudaFuncAttributeMaxDynamicSharedMemorySize, SMEM_BYTES);
    dim3 grid(N / BN, M / 128, batch);
    gemm_mma<BN, WM, WN, EPI><<<grid, 256, SMEM_BYTES>>>(
        A, B, bias, resid, C, Ch, Qo, Ko, Vo,
        M, N, K, ldc, sA, sB, hdiv, sCb, sCh, alpha);
}

extern "C" void kernel_launch(void* const* d_in, const int* in_sizes, int n_in,
                              void* d_out, int out_size)
{
    const float* x      = (const float*)d_in[0];
    const float* ln1_g  = (const float*)d_in[1];
    const float* ln1_b  = (const float*)d_in[2];
    const float* w_qkv  = (const float*)d_in[3];
    const float* b_qkv  = (const float*)d_in[4];
    const float* w_proj = (const float*)d_in[5];
    const float* b_proj = (const float*)d_in[6];
    const float* ln2_g  = (const float*)d_in[7];
    const float* ln2_b  = (const float*)d_in[8];
    const float* w_fc1  = (const float*)d_in[9];
    const float* b_fc1  = (const float*)d_in[10];
    const float* w_fc2  = (const float*)d_in[11];
    const float* b_fc2  = (const float*)d_in[12];
    float* out = (float*)d_out;

    fp16 *wqkvT, *wprojT, *wfc1T, *wfc2T;
    fp16 *ln1, *qf, *kf, *vt, *am, *ln2, *hb;
    float *vbuf, *x1;
    cudaGetSymbolAddress((void**)&wqkvT, g_wqkvT);
    cudaGetSymbolAddress((void**)&wprojT, g_wprojT);
    cudaGetSymbolAddress((void**)&wfc1T, g_wfc1T);
    cudaGetSymbolAddress((void**)&wfc2T, g_wfc2T);
    cudaGetSymbolAddress((void**)&ln1, g_ln1);
    cudaGetSymbolAddress((void**)&qf, g_q);
    cudaGetSymbolAddress((void**)&kf, g_k);
    cudaGetSymbolAddress((void**)&vbuf, g_v);
    cudaGetSymbolAddress((void**)&vt, g_vt);
    cudaGetSymbolAddress((void**)&am, g_am);
    cudaGetSymbolAddress((void**)&x1, g_x1);
    cudaGetSymbolAddress((void**)&ln2, g_ln2);
    cudaGetSymbolAddress((void**)&hb, g_h);

    // 0) weight transpose-converts  W[K,N] -> Wt[N,K] fp16
    wt_prep_kernel<<<dim3(3 * EMB / 32, EMB / 32), 256>>>(w_qkv, EMB, 3 * EMB, wqkvT);
    wt_prep_kernel<<<dim3(EMB / 32, EMB / 32), 256>>>(w_proj, EMB, EMB, wprojT);
    wt_prep_kernel<<<dim3(HIDDEN / 32, EMB / 32), 256>>>(w_fc1, EMB, HIDDEN, wfc1T);
    wt_prep_kernel<<<dim3(EMB / 32, HIDDEN / 32), 256>>>(w_fc2, HIDDEN, EMB, wfc2T);

    // 1) LN1 -> fp16
    layernorm_fp16_kernel<<<TOK, 256>>>(x, ln1_g, ln1_b, ln1);

    // 2) QKV GEMM with fused q/k/v extraction
    launch_gemm<128, 64, 32, EPI_QKV>(ln1, wqkvT, b_qkv, nullptr,
                                      nullptr, nullptr, qf, kf, vbuf,
                                      TOK, 3 * EMB, EMB, 3 * EMB, 0, 0, 1, 1, 0, 0, 1.0f);

    // 3) V transpose -> fp16
    vt_prep_kernel<<<dim3(SEQ / 32, HDIM / 32, BH), 256>>>(vbuf, vt);

    // 4) fused flash attention -> merged heads fp16
    {
        constexpr int FSMEM = 48 * 1024;
        cudaFuncSetAttribute(flash_kernel,
                             cudaFuncAttributeMaxDynamicSharedMemorySize, FSMEM);
        dim3 grid(SEQ / 128, BH);
        flash_kernel<<<grid, 256, FSMEM>>>(qf, kf, vt, am);
    }

    // 5) proj + residual: x1 = am @ w_proj + b + x
    launch_gemm<128, 64, 32, EPI_BIAS_RES>(am, wprojT, b_proj, x,
                                           x1, nullptr, nullptr, nullptr, nullptr,
                                           TOK, EMB, EMB, EMB, 0, 0, 1, 1, 0, 0, 1.0f);

    // 6) LN2 -> fp16
    layernorm_fp16_kernel<<<TOK, 256>>>(x1, ln2_g, ln2_b, ln2);

    // 7) FC1 + GELU -> h fp16
    launch_gemm<128, 64, 32, EPI_GELU_H>(ln2, wfc1T, b_fc1, nullptr,
                                         nullptr, hb, nullptr, nullptr, nullptr,
                                         TOK, HIDDEN, EMB, HIDDEN, 0, 0, 1, 1, 0, 0, 1.0f);

    // 8) FC2 + bias + residual -> out
    launch_gemm<128, 64, 32, EPI_BIAS_RES>(hb, wfc2T, b_fc2, x1,
                                           out, nullptr, nullptr, nullptr, nullptr,
                                           TOK, EMB, HIDDEN, EMB, 0, 0, 1, 1, 0, 0, 1.0f);
}

// round 16
// speedup vs baseline: 4.2132x; 1.0064x over previous
#include <cuda_runtime.h>
#include <cuda_fp16.h>
#include <math.h>
#include <stdint.h>

// Problem constants
#define Bz     2
#define SEQ    2048
#define EMB    1024
#define NHEAD  16
#define HDIM   64
#define HIDDEN 4096
#define TOK    (Bz * SEQ)          // 4096 rows
#define BH     (Bz * NHEAD)        // 32 batched heads

typedef __half fp16;

// ===================== MMA / async primitives (non-'a' PTX) ============
__device__ __forceinline__ void ldm_x4(uint32_t* r, uint32_t addr) {
    asm volatile("ldmatrix.sync.aligned.m8n8.x4.shared.b16 {%0,%1,%2,%3}, [%4];"
        : "=r"(r[0]), "=r"(r[1]), "=r"(r[2]), "=r"(r[3]) : "r"(addr));
}
__device__ __forceinline__ void mma_fp16(float* c, const uint32_t* a,
                                         uint32_t b0, uint32_t b1) {
    asm volatile(
        "mma.sync.aligned.m16n8k16.row.col.f32.f16.f16.f32 "
        "{%0,%1,%2,%3}, {%4,%5,%6,%7}, {%8,%9}, {%0,%1,%2,%3};"
        : "+f"(c[0]), "+f"(c[1]), "+f"(c[2]), "+f"(c[3])
        : "r"(a[0]), "r"(a[1]), "r"(a[2]), "r"(a[3]), "r"(b0), "r"(b1));
}
__device__ __forceinline__ uint32_t smem_to_u32(const void* p) {
    uint32_t a;
    asm("{ .reg .u64 t; cvta.to.shared.u64 t, %1; cvt.u32.u64 %0, t; }" : "=r"(a) : "l"(p));
    return a;
}
#define SW128(off) ((off) ^ (((off) >> 3) & 0x70))

#define CP_ASYNC16(saddr, gptr) \
    asm volatile("cp.async.cg.shared.global [%0], [%1], 16;" \
        :: "r"((uint32_t)(saddr)), "l"(gptr))
#define CP_COMMIT() asm volatile("cp.async.commit_group;" ::: "memory")
#define CP_WAIT1()  asm volatile("cp.async.wait_group 1;" ::: "memory")
#define CP_WAIT0()  asm volatile("cp.async.wait_group 0;" ::: "memory")

__device__ __forceinline__ uint32_t pack_fp16(float a, float b) {
    __half2 h;
    h.x = __float2half(a);
    h.y = __float2half(b);
    return *(uint32_t*)&h;
}

// ===================== scratch =========================================
__device__ fp16  g_wqkvT[3 * EMB * EMB];
__device__ fp16  g_wprojT[EMB * EMB];
__device__ fp16  g_wfc1T[HIDDEN * EMB];
__device__ fp16  g_wfc2T[EMB * HIDDEN];
__device__ fp16  g_ln1[TOK * EMB];
__device__ fp16  g_q[BH * SEQ * HDIM];                 // scaled, single
__device__ fp16  g_k[BH * SEQ * HDIM];                 // single
__device__ float g_v[TOK * EMB];                       // (b,n,h*64+d) fp32
__device__ fp16  g_vt[BH * HDIM * SEQ];                // single
__device__ fp16  g_am[TOK * EMB];
__device__ float g_x1[TOK * EMB];
__device__ fp16  g_ln2[TOK * EMB];
__device__ fp16  g_h[TOK * HIDDEN];

__device__ __forceinline__ float gelu_exact(float x) {
    return 0.5f * x * (1.0f + erff(x * 0.70710678118654752440f));
}

// ===================== fp16 1-pass GEMM (cp.async pipelined) ===========
// D[M,N] = alpha*(A @ B^T). A[M,K], B[N,K] single fp16.
#define EPI_ALPHA    0
#define EPI_BIAS     1
#define EPI_BIAS_RES 2
#define EPI_H        3
#define EPI_GELU_H   4
#define EPI_QKV      5   // fused q/k/v extraction (bias included)

template<int BN, int WM, int WN, int EPI>
__global__ __launch_bounds__(256, 1)
void gemm_mma(const fp16* __restrict__ A, const fp16* __restrict__ B,
              const float* __restrict__ bias, const float* __restrict__ resid,
              float* __restrict__ C, fp16* __restrict__ Ch,
              fp16* __restrict__ Qo, fp16* __restrict__ Ko,
              float* __restrict__ Vo,
              int M, int N, int K, int ldc,
              long long sA, long long sB,
              int hdiv, long long sCb, long long sCh,
              float alpha)
{
    constexpr int BK = 64;
    constexpr int OFF_B = 128 * 128;             // A tile = 16 KB
    constexpr int BUFB  = OFF_B + BN * 128;      // bytes per buffer
    constexpr int WGC = BN / WN;
    constexpr int MT  = WM / 16;
    constexpr int NT  = WN / 8;
    constexpr int NG  = WN / 16;

    extern __shared__ char sm[];
    const uint32_t smb = smem_to_u32(sm);
    const int tid = threadIdx.x, wid = tid >> 5, lane = tid & 31;
    const int bm = blockIdx.y * 128, bn = blockIdx.x * BN, z = blockIdx.z;
    const int wm0 = (wid / WGC) * WM, wn0 = (wid % WGC) * WN;

    A += (long long)z * sA;
    B += (long long)z * sB;
    const long long coff = (long long)(z / hdiv) * sCb + (long long)(z % hdiv) * sCh;

    float acc[MT][NT][4];
#pragma unroll
    for (int i = 0; i < MT; i++)
#pragma unroll
        for (int j = 0; j < NT; j++)
#pragma unroll
            for (int t = 0; t < 4; t++) acc[i][j][t] = 0.0f;

    const int swz   = lane & 7;
    const int aHalf = lane >> 4;
    const int bHalf = (lane >> 3) & 1;
    int aRowOff[MT], bRowOff[NG];
#pragma unroll
    for (int mt = 0; mt < MT; mt++)
        aRowOff[mt] = (wm0 + mt * 16 + (lane & 15)) * 128;
#pragma unroll
    for (int ng = 0; ng < NG; ng++)
        bRowOff[ng] = (wn0 + ng * 16 + (lane & 7) + ((lane >> 4) << 3)) * 128;

    auto stage = [&](int c, uint32_t base) {
        const long long k0 = (long long)c * BK;
        const fp16* a0 = A + (long long)bm * K + k0;
#pragma unroll
        for (int i = tid; i < 128 * 8; i += 256) {
            int r = i >> 3, u = i & 7;
            int sw = SW128(r * 128 + u * 16);
            CP_ASYNC16(smb + base + sw, a0 + (long long)r * K + u * 8);
        }
        const fp16* b0 = B + (long long)bn * K + k0;
#pragma unroll
        for (int i = tid; i < BN * 8; i += 256) {
            int r = i >> 3, u = i & 7;
            int sw = SW128(r * 128 + u * 16);
            CP_ASYNC16(smb + base + OFF_B + sw, b0 + (long long)r * K + u * 8);
        }
        CP_COMMIT();
    };

    const int nch = K / BK;
    stage(0, 0);
    for (int c = 0; c < nch; c++) {
        const uint32_t cur = (c & 1) ? BUFB : 0;
        if (c + 1 < nch) {
            stage(c + 1, (c & 1) ? 0 : BUFB);
            CP_WAIT1();
        } else {
            CP_WAIT0();
        }
        __syncthreads();

#pragma unroll
        for (int ks = 0; ks < BK / 16; ks++) {
            const uint32_t ca = (uint32_t)(((2 * ks + aHalf) ^ swz) * 16);
            const uint32_t cb = (uint32_t)(((2 * ks + bHalf) ^ swz) * 16);
            uint32_t ah[MT][4], br[NG][4];
#pragma unroll
            for (int mt = 0; mt < MT; mt++)
                ldm_x4(ah[mt], smb + cur + aRowOff[mt] + ca);
#pragma unroll
            for (int ng = 0; ng < NG; ng++)
                ldm_x4(br[ng], smb + cur + OFF_B + bRowOff[ng] + cb);
#pragma unroll
            for (int mt = 0; mt < MT; mt++)
#pragma unroll
                for (int nt = 0; nt < NT; nt++)
                    mma_fp16(acc[mt][nt], ah[mt],
                             br[nt >> 1][(nt & 1) * 2], br[nt >> 1][(nt & 1) * 2 + 1]);
        }
        __syncthreads();
    }

#pragma unroll
    for (int mt = 0; mt < MT; mt++) {
#pragma unroll
        for (int half = 0; half < 2; half++) {
            const long long row = bm + wm0 + mt * 16 + (lane >> 2) + half * 8;
#pragma unroll
            for (int nt = 0; nt < NT; nt++) {
                const int col = bn + wn0 + nt * 8 + (lane & 3) * 2;
                float v0 = acc[mt][nt][half * 2 + 0] * alpha;
                float v1 = acc[mt][nt][half * 2 + 1] * alpha;
                if (EPI == EPI_BIAS || EPI == EPI_BIAS_RES || EPI == EPI_GELU_H || EPI == EPI_QKV) {
                    v0 += bias[col]; v1 += bias[col + 1];
                }
                if (EPI == EPI_BIAS_RES) {
                    const float* rp = resid + coff + row * (long long)ldc + col;
                    v0 += rp[0]; v1 += rp[1];
                }
                if (EPI == EPI_GELU_H) {
                    v0 = gelu_exact(v0); v1 = gelu_exact(v1);
                }
                if (EPI == EPI_QKV) {
                    const int region = col >> 10;       // 0=Q 1=K 2=V (warp-uniform)
                    const int cc = col & 1023;
                    const int h = cc >> 6, d = cc & 63;
                    const long long b = row >> 11, n = row & 2047;
                    if (region == 2) {
                        float2 w; w.x = v0; w.y = v1;
                        *(float2*)(Vo + row * EMB + cc) = w;
                    } else {
                        const long long dst = ((b * NHEAD + h) * SEQ + n) * HDIM + d;
                        if (region == 0) {
                            __half2 x; x.x = __float2half(v0 * 0.125f);
                            x.y = __float2half(v1 * 0.125f);
                            *(__half2*)(Qo + dst) = x;
                        } else {
                            __half2 x; x.x = __float2half(v0);
                            x.y = __float2half(v1);
                            *(__half2*)(Ko + dst) = x;
                        }
                    }
                } else {
                    const long long o = coff + row * (long long)ldc + col;
                    if (EPI == EPI_ALPHA || EPI == EPI_BIAS || EPI == EPI_BIAS_RES) {
                        float2 w; w.x = v0; w.y = v1;
                        *(float2*)(C + o) = w;
                    } else {
                        __half2 hh; hh.x = __float2half(v0); hh.y = __float2half(v1);
                        *(__half2*)(Ch + o) = hh;
                    }
                }
            }
        }
    }
}

// ===================== Flash attention v4 (single-pass fp16) ===========
// Grid (SEQ/128, BH), 256 threads. Q tile 128, KV tile 64 double-buffered.
// S = Qf*Kf; O += Pf*Vf.  smem: Q 16K | K 2x8K | V 2x8K = 48 KB.
__global__ __launch_bounds__(256)
void flash_kernel(const fp16* __restrict__ Qf, const fp16* __restrict__ Kf,
                  const fp16* __restrict__ Vf, fp16* __restrict__ O)
{
    constexpr int OFF_K = 16384;
    constexpr int OFF_V = 32768;
    constexpr int KBUF  = 8192;
    extern __shared__ char sm[];
    const uint32_t smb = smem_to_u32(sm);
    const int tid = threadIdx.x, wid = tid >> 5, lane = tid & 31;
    const int bh = blockIdx.y, q0 = blockIdx.x * 128;
    const long long qkbase = (long long)bh * SEQ * HDIM;
    const long long vbase  = (long long)bh * HDIM * SEQ;
    const int swz = lane & 7;

#pragma unroll
    for (int i = tid; i < 128 * 8; i += 256) {
        int r = i >> 3, u = i & 7;
        int sw = SW128(r * 128 + u * 16);
        CP_ASYNC16(smb + sw, Qf + qkbase + (long long)(q0 + r) * HDIM + u * 8);
    }
    CP_COMMIT();

    auto stage = [&](int t, int buf) {
        const int kv0 = t * 64;
        const uint32_t kb = OFF_K + buf * KBUF, vb = OFF_V + buf * KBUF;
#pragma unroll
        for (int i = tid; i < 64 * 8; i += 256) {
            int r = i >> 3, u = i & 7;
            int sw = SW128(r * 128 + u * 16);
            CP_ASYNC16(smb + kb + sw, Kf + qkbase + (long long)(kv0 + r) * HDIM + u * 8);
            CP_ASYNC16(smb + vb + sw, Vf + vbase + (long long)r * SEQ + kv0 + u * 8);
        }
        CP_COMMIT();
    };
    stage(0, 0);
    CP_WAIT0();
    __syncthreads();

    uint32_t qf[4][4];
    {
        const int aRowOff = (wid * 16 + (lane & 15)) * 128;
        const int aHalf = lane >> 4;
#pragma unroll
        for (int ks = 0; ks < 4; ks++) {
            const uint32_t ca = (uint32_t)(((2 * ks + aHalf) ^ swz) * 16);
            ldm_x4(qf[ks], smb + aRowOff + ca);
        }
    }

    float Oacc[8][4];
#pragma unroll
    for (int i = 0; i < 8; i++)
#pragma unroll
        for (int t = 0; t < 4; t++) Oacc[i][t] = 0.0f;
    float mrow[2] = {-1e30f, -1e30f};
    float lrow[2] = {0.0f, 0.0f};

    const int kRowOff = (lane & 7) + ((lane >> 4) << 3);
    const int bHalf = (lane >> 3) & 1;

    for (int t = 0; t < SEQ / 64; t++) {
        const int buf = t & 1;
        if (t + 1 < SEQ / 64) { stage(t + 1, buf ^ 1); CP_WAIT1(); }
        else                  { CP_WAIT0(); }
        __syncthreads();
        const uint32_t kb = OFF_K + buf * KBUF, vb = OFF_V + buf * KBUF;

        // ---- S = Qf Kf^T ----
        float S[8][4];
#pragma unroll
        for (int j = 0; j < 8; j++)
#pragma unroll
            for (int c = 0; c < 4; c++) S[j][c] = 0.0f;
#pragma unroll
        for (int g = 0; g < 4; g++) {
            const int bRow = (g * 16 + kRowOff) * 128;
#pragma unroll
            for (int ks = 0; ks < 4; ks++) {
                const uint32_t cb = (uint32_t)(((2 * ks + bHalf) ^ swz) * 16);
                uint32_t k4[4];
                ldm_x4(k4, smb + kb + bRow + cb);
                mma_fp16(S[2 * g],     qf[ks], k4[0], k4[1]);
                mma_fp16(S[2 * g + 1], qf[ks], k4[2], k4[3]);
            }
        }

        // ---- online softmax ----
        float mt0 = -1e30f, mt1 = -1e30f;
#pragma unroll
        for (int j = 0; j < 8; j++) {
            mt0 = fmaxf(mt0, fmaxf(S[j][0], S[j][1]));
            mt1 = fmaxf(mt1, fmaxf(S[j][2], S[j][3]));
        }
        mt0 = fmaxf(mt0, __shfl_xor_sync(0xffffffffu, mt0, 1));
        mt0 = fmaxf(mt0, __shfl_xor_sync(0xffffffffu, mt0, 2));
        mt1 = fmaxf(mt1, __shfl_xor_sync(0xffffffffu, mt1, 1));
        mt1 = fmaxf(mt1, __shfl_xor_sync(0xffffffffu, mt1, 2));
        const float mn0 = fmaxf(mrow[0], mt0), mn1 = fmaxf(mrow[1], mt1);
        const float sc0 = __expf(mrow[0] - mn0), sc1 = __expf(mrow[1] - mn1);
        float rs0 = 0.0f, rs1 = 0.0f;
#pragma unroll
        for (int j = 0; j < 8; j++) {
            S[j][0] = __expf(S[j][0] - mn0);
            S[j][1] = __expf(S[j][1] - mn0);
            S[j][2] = __expf(S[j][2] - mn1);
            S[j][3] = __expf(S[j][3] - mn1);
            rs0 += S[j][0] + S[j][1];
            rs1 += S[j][2] + S[j][3];
        }
        rs0 += __shfl_xor_sync(0xffffffffu, rs0, 1);
        rs0 += __shfl_xor_sync(0xffffffffu, rs0, 2);
        rs1 += __shfl_xor_sync(0xffffffffu, rs1, 1);
        rs1 += __shfl_xor_sync(0xffffffffu, rs1, 2);
        lrow[0] = lrow[0] * sc0 + rs0;
        lrow[1] = lrow[1] * sc1 + rs1;
        mrow[0] = mn0; mrow[1] = mn1;
#pragma unroll
        for (int i = 0; i < 8; i++) {
            Oacc[i][0] *= sc0; Oacc[i][1] *= sc0;
            Oacc[i][2] *= sc1; Oacc[i][3] *= sc1;
        }

        // ---- O += P Vf ----
#pragma unroll
        for (int j = 0; j < 4; j++) {
            uint32_t ah[4];
            ah[0] = pack_fp16(S[2*j][0],   S[2*j][1]);
            ah[1] = pack_fp16(S[2*j][2],   S[2*j][3]);
            ah[2] = pack_fp16(S[2*j+1][0], S[2*j+1][1]);
            ah[3] = pack_fp16(S[2*j+1][2], S[2*j+1][3]);

            const uint32_t cv = (uint32_t)(((2 * j + bHalf) ^ swz) * 16);
#pragma unroll
            for (int vg = 0; vg < 4; vg++) {
                const int vRow = (vg * 16 + kRowOff) * 128;
                uint32_t v4[4];
                ldm_x4(v4, smb + vb + vRow + cv);
                mma_fp16(Oacc[2 * vg],     ah, v4[0], v4[1]);
                mma_fp16(Oacc[2 * vg + 1], ah, v4[2], v4[3]);
            }
        }
        __syncthreads();
    }

    // epilogue: merged-head single fp16
    const float inv0 = 1.0f / lrow[0], inv1 = 1.0f / lrow[1];
    const int b = bh / NHEAD, hh = bh % NHEAD;
    const long long tok0 = (long long)b * SEQ + q0 + wid * 16 + (lane >> 2);
    const int col0 = hh * HDIM + (lane & 3) * 2;
#pragma unroll
    for (int vt = 0; vt < 8; vt++) {
        float v0 = Oacc[vt][0] * inv0, v1 = Oacc[vt][1] * inv0;
        float v2 = Oacc[vt][2] * inv1, v3 = Oacc[vt][3] * inv1;
        long long o = tok0 * EMB + col0 + vt * 8;
        { __half2 x; x.x = __float2half(v0); x.y = __float2half(v1); *(__half2*)(O + o) = x; }
        long long o2 = (tok0 + 8) * EMB + col0 + vt * 8;
        { __half2 x; x.x = __float2half(v2); x.y = __float2half(v3); *(__half2*)(O + o2) = x; }
    }
}

// ===================== LayerNorm -> fp16 ===============================
__global__ __launch_bounds__(256)
void layernorm_fp16_kernel(const float* __restrict__ x, const float* __restrict__ gamma,
                           const float* __restrict__ beta, fp16* __restrict__ o)
{
    long long row = blockIdx.x;
    const float4* xr = (const float4*)(x + row * EMB);
    float4 v = xr[threadIdx.x];
    float s  = v.x + v.y + v.z + v.w;
    float ss = v.x * v.x + v.y * v.y + v.z * v.z + v.w * v.w;
#pragma unroll
    for (int of = 16; of; of >>= 1) {
        s  += __shfl_xor_sync(0xffffffffu, s,  of);
        ss += __shfl_xor_sync(0xffffffffu, ss, of);
    }
    __shared__ float sh_s[8], sh_ss[8];
    int w = threadIdx.x >> 5, l = threadIdx.x & 31;
    if (l == 0) { sh_s[w] = s; sh_ss[w] = ss; }
    __syncthreads();
    s = 0.f; ss = 0.f;
#pragma unroll
    for (int i = 0; i < 8; i++) { s += sh_s[i]; ss += sh_ss[i]; }
    float mu   = s * (1.0f / EMB);
    float var  = ss * (1.0f / EMB) - mu * mu;
    float rstd = rsqrtf(var + 1e-6f);
    float4 gv = ((const float4*)gamma)[threadIdx.x];
    float4 bv = ((const float4*)beta)[threadIdx.x];
    float o0 = (v.x - mu) * rstd * gv.x + bv.x;
    float o1 = (v.y - mu) * rstd * gv.y + bv.y;
    float o2 = (v.z - mu) * rstd * gv.z + bv.z;
    float o3 = (v.w - mu) * rstd * gv.w + bv.w;
    long long base = row * EMB + threadIdx.x * 4;
    __half2 a; a.x = __float2half(o0); a.y = __float2half(o1);
    __half2 b; b.x = __float2half(o2); b.y = __float2half(o3);
    *(__half2*)(o + base)     = a;
    *(__half2*)(o + base + 2) = b;
}

// ============ transpose-convert: fp32 [R,C] -> [C,R] fp16 ==============
__global__ __launch_bounds__(256)
void wt_prep_kernel(const float* __restrict__ src, int R, int C,
                    fp16* __restrict__ dh)
{
    __shared__ float t[32][33];
    int c0 = blockIdx.x * 32, r0 = blockIdx.y * 32;
    int tx = threadIdx.x & 31, ty = threadIdx.x >> 5;
#pragma unroll
    for (int i = ty; i < 32; i += 8)
        t[i][tx] = src[(long long)(r0 + i) * C + c0 + tx];
    __syncthreads();
#pragma unroll
    for (int i = ty; i < 32; i += 8) {
        long long o = (long long)(c0 + i) * R + r0 + tx;
        dh[o] = __float2half(t[tx][i]);
    }
}

// ============ V^T prep: v fp32 (b,n,h*64+d) -> vt fp16 [BH,64,SEQ] =====
__global__ __launch_bounds__(256)
void vt_prep_kernel(const float* __restrict__ v, fp16* __restrict__ dh)
{
    __shared__ float t[32][33];
    int bh = blockIdx.z, b = bh / NHEAD, h = bh % NHEAD;
    int n0 = blockIdx.x * 32, d0 = blockIdx.y * 32;
    int tx = threadIdx.x & 31, ty = threadIdx.x >> 5;
#pragma unroll
    for (int i = ty; i < 32; i += 8)
        t[i][tx] = v[((long long)(b * SEQ + n0 + i)) * EMB + h * HDIM + d0 + tx];
    __syncthreads();
#pragma unroll
    for (int i = ty; i < 32; i += 8) {
        long long o = ((long long)bh * HDIM + d0 + i) * SEQ + n0 + tx;
        dh[o] = __float2half(t[tx][i]);
    }
}

// ===================== host side =======================================
template<int BN, int WM, int WN, int EPI>
static void launch_gemm(const fp16* A, const fp16* B,
                        const float* bias, const float* resid,
                        float* C, fp16* Ch,
                        fp16* Qo, fp16* Ko, float* Vo,
                        int M, int N, int K, int ldc,
                        long long sA, long long sB,
                        int batch, int hdiv, long long sCb, long long sCh,
                        float alpha)
{
    constexpr int SMEM_BYTES = 2 * (128 * 128 + BN * 128);
    cudaFuncSetAttribute(gemm_mma<BN, WM, WN, EPI>,
                         cudaFuncAttributeMaxDynamicSharedMemorySize, SMEM_BYTES);
    dim3 grid(N / BN, M / 128, batch);
    gemm_mma<BN, WM, WN, EPI><<<grid, 256, SMEM_BYTES>>>(
        A, B, bias, resid, C, Ch, Qo, Ko, Vo,
        M, N, K, ldc, sA, sB, hdiv, sCb, sCh, alpha);
}

extern "C" void kernel_launch(void* const* d_in, const int* in_sizes, int n_in,
                              void* d_out, int out_size)
{
    const float* x      = (const float*)d_in[0];
    const float* ln1_g  = (const float*)d_in[1];
    const float* ln1_b  = (const float*)d_in[2];
    const float* w_qkv  = (const float*)d_in[3];
    const float* b_qkv  = (const float*)d_in[4];
    const float* w_proj = (const float*)d_in[5];
    const float* b_proj = (const float*)d_in[6];
    const float* ln2_g  = (const float*)d_in[7];
    const float* ln2_b  = (const float*)d_in[8];
    const float* w_fc1  = (const float*)d_in[9];
    const float* b_fc1  = (const float*)d_in[10];
    const float* w_fc2  = (const float*)d_in[11];
    const float* b_fc2  = (const float*)d_in[12];
    float* out = (float*)d_out;

    fp16 *wqkvT, *wprojT, *wfc1T, *wfc2T;
    fp16 *ln1, *qf, *kf, *vt, *am, *ln2, *hb;
    float *vbuf, *x1;
    cudaGetSymbolAddress((void**)&wqkvT, g_wqkvT);
    cudaGetSymbolAddress((void**)&wprojT, g_wprojT);
    cudaGetSymbolAddress((void**)&wfc1T, g_wfc1T);
    cudaGetSymbolAddress((void**)&wfc2T, g_wfc2T);
    cudaGetSymbolAddress((void**)&ln1, g_ln1);
    cudaGetSymbolAddress((void**)&qf, g_q);
    cudaGetSymbolAddress((void**)&kf, g_k);
    cudaGetSymbolAddress((void**)&vbuf, g_v);
    cudaGetSymbolAddress((void**)&vt, g_vt);
    cudaGetSymbolAddress((void**)&am, g_am);
    cudaGetSymbolAddress((void**)&x1, g_x1);
    cudaGetSymbolAddress((void**)&ln2, g_ln2);
    cudaGetSymbolAddress((void**)&hb, g_h);

    // 0) weight transpose-converts  W[K,N] -> Wt[N,K] fp16
    wt_prep_kernel<<<dim3(3 * EMB / 32, EMB / 32), 256>>>(w_qkv, EMB, 3 * EMB, wqkvT);
    wt_prep_kernel<<<dim3(EMB / 32, EMB / 32), 256>>>(w_proj, EMB, EMB, wprojT);
    wt_prep_kernel<<<dim3(HIDDEN / 32, EMB / 32), 256>>>(w_fc1, EMB, HIDDEN, wfc1T);
    wt_prep_kernel<<<dim3(EMB / 32, HIDDEN / 32), 256>>>(w_fc2, HIDDEN, EMB, wfc2T);

    // 1) LN1 -> fp16
    layernorm_fp16_kernel<<<TOK, 256>>>(x, ln1_g, ln1_b, ln1);

    // 2) QKV GEMM with fused q/k/v extraction (128x256 tile)
    launch_gemm<256, 64, 64, EPI_QKV>(ln1, wqkvT, b_qkv, nullptr,
                                      nullptr, nullptr, qf, kf, vbuf,
                                      TOK, 3 * EMB, EMB, 3 * EMB, 0, 0, 1, 1, 0, 0, 1.0f);

    // 3) V transpose -> fp16
    vt_prep_kernel<<<dim3(SEQ / 32, HDIM / 32, BH), 256>>>(vbuf, vt);

    // 4) fused flash attention -> merged heads fp16
    {
        constexpr int FSMEM = 48 * 1024;
        cudaFuncSetAttribute(flash_kernel,
                             cudaFuncAttributeMaxDynamicSharedMemorySize, FSMEM);
        dim3 grid(SEQ / 128, BH);
        flash_kernel<<<grid, 256, FSMEM>>>(qf, kf, vt, am);
    }

    // 5) proj + residual: x1 = am @ w_proj + b + x
    launch_gemm<256, 64, 64, EPI_BIAS_RES>(am, wprojT, b_proj, x,
                                           x1, nullptr, nullptr, nullptr, nullptr,
                                           TOK, EMB, EMB, EMB, 0, 0, 1, 1, 0, 0, 1.0f);

    // 6) LN2 -> fp16
    layernorm_fp16_kernel<<<TOK, 256>>>(x1, ln2_g, ln2_b, ln2);

    // 7) FC1 + GELU -> h fp16
    launch_gemm<256, 64, 64, EPI_GELU_H>(ln2, wfc1T, b_fc1, nullptr,
                                         nullptr, hb, nullptr, nullptr, nullptr,
                                         TOK, HIDDEN, EMB, HIDDEN, 0, 0, 1, 1, 0, 0, 1.0f);

    // 8) FC2 + bias + residual -> out
    launch_gemm<256, 64, 64, EPI_BIAS_RES>(hb, wfc2T, b_fc2, x1,
                                           out, nullptr, nullptr, nullptr, nullptr,
                                           TOK, EMB, HIDDEN, EMB, 0, 0, 1, 1, 0, 0, 1.0f);
}